// round 6
// baseline (speedup 1.0000x reference)
#include <cuda_runtime.h>
#include <cstdint>

#define D_MODEL 1024
#define N_HEADS 16
#define D_HEAD  64
#define B_SIZE  2
#define T_SEQ   2048
#define M_ROWS  (B_SIZE * T_SEQ)   // 4096

// Scratch (allocation-free rule: __device__ globals)
__device__ float g_Q[M_ROWS * D_MODEL];     // [B,H,T,64], pre-scaled, tf32-rounded
__device__ float g_K[M_ROWS * D_MODEL];
__device__ float g_V[M_ROWS * D_MODEL];
__device__ float g_attn[M_ROWS * D_MODEL];  // [B,T,1024], tf32-rounded
__device__ float g_xr[M_ROWS * D_MODEL];    // x rounded to tf32
__device__ float g_Wr[4][D_MODEL * D_MODEL]; // Wq,Wk,Wv,Wo rounded

// ===========================================================================
// Common PTX helpers
// ===========================================================================
__device__ __forceinline__ uint32_t f2tf32(float x) {
    uint32_t r;
    asm("cvt.rna.tf32.f32 %0, %1;" : "=r"(r) : "f"(x));
    return r;
}

__device__ __forceinline__ void mma_tf32(float c[4], const uint32_t a[4],
                                         const uint32_t b[2]) {
    asm volatile(
        "mma.sync.aligned.m16n8k8.row.col.f32.tf32.tf32.f32 "
        "{%0,%1,%2,%3}, {%4,%5,%6,%7}, {%8,%9}, {%0,%1,%2,%3};"
        : "+f"(c[0]), "+f"(c[1]), "+f"(c[2]), "+f"(c[3])
        : "r"(a[0]), "r"(a[1]), "r"(a[2]), "r"(a[3]), "r"(b[0]), "r"(b[1]));
}

__device__ __forceinline__ void cp_async16(void* dst_smem, const void* src) {
    uint32_t d = (uint32_t)__cvta_generic_to_shared(dst_smem);
    asm volatile("cp.async.cg.shared.global [%0], [%1], 16;" ::
                 "r"(d), "l"(src));
}
__device__ __forceinline__ void cp_commit() {
    asm volatile("cp.async.commit_group;");
}
template <int N>
__device__ __forceinline__ void cp_wait() {
    asm volatile("cp.async.wait_group %0;" :: "n"(N));
}

// ===========================================================================
// Elementwise tf32 rounding pre-pass (float4, grid-stride)
// ===========================================================================
__global__ void round_tf32_kernel(const float* __restrict__ src,
                                  float* __restrict__ dst, int n4)
{
    int i = blockIdx.x * blockDim.x + threadIdx.x;
    const int stride = gridDim.x * blockDim.x;
    for (; i < n4; i += stride) {
        float4 v = reinterpret_cast<const float4*>(src)[i];
        uint4 r;
        r.x = f2tf32(v.x); r.y = f2tf32(v.y);
        r.z = f2tf32(v.z); r.w = f2tf32(v.w);
        reinterpret_cast<uint4*>(dst)[i] = r;
    }
}

// ===========================================================================
// TF32 GEMM core (operands pre-rounded -> raw-bit fragments, zero cvt).
// BM=128, BN=128, BK=32. 256 threads = 8 warps (2 M x 4 N), warp tile 64x32.
// ===========================================================================
#define GEMM_SA 36
#define GEMM_SB 136
#define GEMM_AS_FLOATS (128 * GEMM_SA)
#define GEMM_BS_FLOATS (32 * GEMM_SB)
#define GEMM_SMEM_BYTES ((2 * GEMM_AS_FLOATS + 2 * GEMM_BS_FLOATS) * 4)

// Shared mainloop: accumulates A(brow:+128, :) @ W(:, bcol:+128) into acc.
__device__ __forceinline__ void gemm_mainloop(
    const float* __restrict__ A, const float* __restrict__ W,
    float* As, float* Bs, int brow, int bcol, int K, int N,
    float acc[4][4][4])
{
    const int tid  = threadIdx.x;
    const int lane = tid & 31;
    const int g    = lane >> 2;
    const int t4   = lane & 3;
    const int wid  = tid >> 5;
    const int warp_m = (wid & 1) * 64;
    const int warp_n = (wid >> 1) * 32;

    const int am  = tid & 127;
    const int akq = tid >> 7;
    const int bn4 = tid & 31;
    const int bk  = tid >> 5;

    auto load_stage = [&](int k0, int buf) {
        float* as = As + buf * GEMM_AS_FLOATS;
        float* bs = Bs + buf * GEMM_BS_FLOATS;
        const float* ag = A + (size_t)(brow + am) * K + k0;
        #pragma unroll
        for (int it = 0; it < 4; it++) {
            const int k4 = akq + 2 * it;
            cp_async16(&as[am * GEMM_SA + k4 * 4], &ag[k4 * 4]);
        }
        #pragma unroll
        for (int it = 0; it < 4; it++) {
            const int k = bk + 8 * it;
            cp_async16(&bs[k * GEMM_SB + bn4 * 4],
                       &W[(size_t)(k0 + k) * N + bcol + bn4 * 4]);
        }
        cp_commit();
    };

    const int nk = K / 32;
    load_stage(0, 0);

    for (int it = 0; it < nk; it++) {
        if (it + 1 < nk) {
            load_stage((it + 1) * 32, (it + 1) & 1);
            cp_wait<1>();
        } else {
            cp_wait<0>();
        }
        __syncthreads();

        const float* as = As + (it & 1) * GEMM_AS_FLOATS;
        const float* bs = Bs + (it & 1) * GEMM_BS_FLOATS;

        #pragma unroll
        for (int ks = 0; ks < 4; ks++) {
            const int kk = ks * 8;
            uint32_t af[4][4], bf[4][2];
            #pragma unroll
            for (int mf = 0; mf < 4; mf++) {
                const int m = warp_m + mf * 16 + g;
                af[mf][0] = __float_as_uint(as[(m    ) * GEMM_SA + kk + t4    ]);
                af[mf][1] = __float_as_uint(as[(m + 8) * GEMM_SA + kk + t4    ]);
                af[mf][2] = __float_as_uint(as[(m    ) * GEMM_SA + kk + t4 + 4]);
                af[mf][3] = __float_as_uint(as[(m + 8) * GEMM_SA + kk + t4 + 4]);
            }
            #pragma unroll
            for (int nf = 0; nf < 4; nf++) {
                const int n = warp_n + nf * 8 + g;
                bf[nf][0] = __float_as_uint(bs[(kk + t4    ) * GEMM_SB + n]);
                bf[nf][1] = __float_as_uint(bs[(kk + t4 + 4) * GEMM_SB + n]);
            }
            #pragma unroll
            for (int mf = 0; mf < 4; mf++)
                #pragma unroll
                for (int nf = 0; nf < 4; nf++)
                    mma_tf32(acc[mf][nf], af[mf], bf[nf]);
        }
        __syncthreads();
    }
}

// ---- Fused QKV projection: grid (24, 32). blockIdx.x/8 selects Q/K/V. ----
__global__ __launch_bounds__(256)
void qkv_gemm_kernel(const float* __restrict__ A,
                     const float* __restrict__ Wq, const float* __restrict__ Wk,
                     const float* __restrict__ Wv,
                     const float* __restrict__ bq, const float* __restrict__ bk,
                     const float* __restrict__ bv,
                     float* __restrict__ Qo, float* __restrict__ Ko,
                     float* __restrict__ Vo)
{
    extern __shared__ float sm[];
    float* As = sm;
    float* Bs = sm + 2 * GEMM_AS_FLOATS;

    const int wsel = blockIdx.x >> 3;           // 0=Q, 1=K, 2=V
    const int bcol = (blockIdx.x & 7) * 128;
    const int brow = blockIdx.y * 128;
    const float* W    = (wsel == 0) ? Wq : (wsel == 1) ? Wk : Wv;
    const float* bias = (wsel == 0) ? bq : (wsel == 1) ? bk : bv;
    float* C          = (wsel == 0) ? Qo : (wsel == 1) ? Ko : Vo;
    const float scale = (wsel == 0) ? 0.125f : 1.0f;

    float acc[4][4][4];
    #pragma unroll
    for (int mf = 0; mf < 4; mf++)
        #pragma unroll
        for (int nf = 0; nf < 4; nf++)
            #pragma unroll
            for (int c = 0; c < 4; c++) acc[mf][nf][c] = 0.0f;

    gemm_mainloop(A, W, As, Bs, brow, bcol, D_MODEL, D_MODEL, acc);

    const int lane = threadIdx.x & 31;
    const int g  = lane >> 2, t4 = lane & 3;
    const int wid = threadIdx.x >> 5;
    const int warp_m = (wid & 1) * 64, warp_n = (wid >> 1) * 32;

    // head-layout scatter, tf32-rounded output
    #pragma unroll
    for (int mf = 0; mf < 4; mf++) {
        #pragma unroll
        for (int nf = 0; nf < 4; nf++) {
            const int col = bcol + warp_n + nf * 8 + 2 * t4;
            const float b0 = bias[col], b1 = bias[col + 1];
            #pragma unroll
            for (int rr = 0; rr < 2; rr++) {
                const int row = brow + warp_m + mf * 16 + g + rr * 8;
                const float v0 = (acc[mf][nf][rr * 2 + 0] + b0) * scale;
                const float v1 = (acc[mf][nf][rr * 2 + 1] + b1) * scale;
                const int bb = row >> 11, tt = row & (T_SEQ - 1);
                const int hh = col >> 6,  dd = col & 63;
                float* p = &C[(((size_t)(bb * N_HEADS + hh) * T_SEQ) + tt)
                              * D_HEAD + dd];
                p[0] = __uint_as_float(f2tf32(v0));
                p[1] = __uint_as_float(f2tf32(v1));
            }
        }
    }
}

// ---- Output projection: full-fp32 epilogue ----
__global__ __launch_bounds__(256)
void out_gemm_kernel(const float* __restrict__ A, const float* __restrict__ W,
                     const float* __restrict__ bias, float* __restrict__ C)
{
    extern __shared__ float sm[];
    float* As = sm;
    float* Bs = sm + 2 * GEMM_AS_FLOATS;

    const int bcol = blockIdx.x * 128;
    const int brow = blockIdx.y * 128;

    float acc[4][4][4];
    #pragma unroll
    for (int mf = 0; mf < 4; mf++)
        #pragma unroll
        for (int nf = 0; nf < 4; nf++)
            #pragma unroll
            for (int c = 0; c < 4; c++) acc[mf][nf][c] = 0.0f;

    gemm_mainloop(A, W, As, Bs, brow, bcol, D_MODEL, D_MODEL, acc);

    const int lane = threadIdx.x & 31;
    const int g  = lane >> 2, t4 = lane & 3;
    const int wid = threadIdx.x >> 5;
    const int warp_m = (wid & 1) * 64, warp_n = (wid >> 1) * 32;

    #pragma unroll
    for (int mf = 0; mf < 4; mf++) {
        #pragma unroll
        for (int nf = 0; nf < 4; nf++) {
            const int col = bcol + warp_n + nf * 8 + 2 * t4;
            const float b0 = bias[col], b1 = bias[col + 1];
            #pragma unroll
            for (int rr = 0; rr < 2; rr++) {
                const int row = brow + warp_m + mf * 16 + g + rr * 8;
                float* p = &C[(size_t)row * D_MODEL + col];
                p[0] = acc[mf][nf][rr * 2 + 0] + b0;
                p[1] = acc[mf][nf][rr * 2 + 1] + b1;
            }
        }
    }
}

// ===========================================================================
// Tensor-core flash attention (causal). BQ = BKV = 128, 512 threads.
// Inputs pre-rounded tf32 -> all fragments raw-bit. Output tf32-rounded.
// ===========================================================================
#define SQ 68
#define SK 68
#define SV 72
#define SP 132
#define OFF_Q  0
#define OFF_K  (128 * SQ)
#define OFF_V  (OFF_K + 128 * SK)
#define OFF_S  (OFF_V + 128 * SV)
#define OFF_RM (OFF_S + 128 * SP)
#define OFF_RL (OFF_RM + 128)
#define OFF_RS (OFF_RL + 128)
#define OFF_PM (OFF_RS + 128)
#define OFF_PS (OFF_PM + 256)
#define ATTN_SMEM_FLOATS (OFF_PS + 256)
#define ATTN_SMEM_BYTES  (ATTN_SMEM_FLOATS * 4)

__global__ __launch_bounds__(512, 1)
void attn_mma_kernel(const float* __restrict__ Qh,
                     const float* __restrict__ Kh,
                     const float* __restrict__ Vh,
                     float* __restrict__ out)
{
    extern __shared__ float sm[];
    float* Qs    = sm + OFF_Q;
    float* Ks    = sm + OFF_K;
    float* Vs    = sm + OFF_V;
    float* Ss    = sm + OFF_S;
    float* row_m = sm + OFF_RM;
    float* row_l = sm + OFF_RL;
    float* row_s = sm + OFF_RS;
    float* pmax  = sm + OFF_PM;
    float* psum  = sm + OFF_PS;

    const int tid  = threadIdx.x;
    const int lane = tid & 31;
    const int wid  = tid >> 5;
    const int g    = lane >> 2;
    const int t4   = lane & 3;
    const int wr   = wid >> 1;
    const int wc   = wid & 1;

    const int bx = gridDim.x - 1 - blockIdx.x;
    const int bh = blockIdx.y;
    const int b  = bh >> 4;
    const int h  = bh & 15;
    const int q0 = bx * 128;

    const float* Qb = Qh + (size_t)bh * T_SEQ * D_HEAD;
    const float* Kb = Kh + (size_t)bh * T_SEQ * D_HEAD;
    const float* Vb = Vh + (size_t)bh * T_SEQ * D_HEAD;

    auto load_q = [&]() {
        #pragma unroll
        for (int it = 0; it < 4; it++) {
            const int id = tid + it * 512;
            const int r = id >> 4, c4 = id & 15;
            cp_async16(&Qs[r * SQ + c4 * 4], &Qb[(size_t)(q0 + r) * 64 + c4 * 4]);
        }
    };
    auto load_k = [&](int k0) {
        #pragma unroll
        for (int it = 0; it < 4; it++) {
            const int id = tid + it * 512;
            const int r = id >> 4, c4 = id & 15;
            cp_async16(&Ks[r * SK + c4 * 4], &Kb[(size_t)(k0 + r) * 64 + c4 * 4]);
        }
    };
    auto load_v = [&](int k0) {
        #pragma unroll
        for (int it = 0; it < 4; it++) {
            const int id = tid + it * 512;
            const int r = id >> 4, c4 = id & 15;
            cp_async16(&Vs[r * SV + c4 * 4], &Vb[(size_t)(k0 + r) * 64 + c4 * 4]);
        }
    };

    load_q();
    load_k(0);
    cp_commit();
    load_v(0);
    cp_commit();

    if (tid < 128) { row_m[tid] = -1e30f; row_l[tid] = 0.0f; }

    float o_acc[4][4];
    #pragma unroll
    for (int nf = 0; nf < 4; nf++)
        #pragma unroll
        for (int c = 0; c < 4; c++) o_acc[nf][c] = 0.0f;

    const int r0 = wr * 16 + g;
    const int r1 = r0 + 8;
    const int nkt = bx + 1;

    for (int kt = 0; kt < nkt; kt++) {
        const bool have_next = (kt + 1 < nkt);

        cp_wait<1>();
        __syncthreads();

        // ---- S = Q K^T ----
        float s_acc[8][4];
        #pragma unroll
        for (int nf = 0; nf < 8; nf++)
            #pragma unroll
            for (int c = 0; c < 4; c++) s_acc[nf][c] = 0.0f;

        #pragma unroll
        for (int kb = 0; kb < 8; kb++) {
            uint32_t a[4];
            a[0] = __float_as_uint(Qs[r0 * SQ + kb * 8 + t4]);
            a[1] = __float_as_uint(Qs[r1 * SQ + kb * 8 + t4]);
            a[2] = __float_as_uint(Qs[r0 * SQ + kb * 8 + t4 + 4]);
            a[3] = __float_as_uint(Qs[r1 * SQ + kb * 8 + t4 + 4]);
            #pragma unroll
            for (int nf = 0; nf < 8; nf++) {
                const int n = wc * 64 + nf * 8 + g;
                uint32_t bfr[2];
                bfr[0] = __float_as_uint(Ks[n * SK + kb * 8 + t4]);
                bfr[1] = __float_as_uint(Ks[n * SK + kb * 8 + t4 + 4]);
                mma_tf32(s_acc[nf], a, bfr);
            }
        }

        if (kt == bx) {
            #pragma unroll
            for (int nf = 0; nf < 8; nf++) {
                const int c0 = wc * 64 + nf * 8 + t4 * 2;
                if (c0     > r0) s_acc[nf][0] = -1e30f;
                if (c0 + 1 > r0) s_acc[nf][1] = -1e30f;
                if (c0     > r1) s_acc[nf][2] = -1e30f;
                if (c0 + 1 > r1) s_acc[nf][3] = -1e30f;
            }
        }

        {
            float pm0 = -1e30f, pm1 = -1e30f;
            #pragma unroll
            for (int nf = 0; nf < 8; nf++) {
                pm0 = fmaxf(pm0, fmaxf(s_acc[nf][0], s_acc[nf][1]));
                pm1 = fmaxf(pm1, fmaxf(s_acc[nf][2], s_acc[nf][3]));
            }
            pm0 = fmaxf(pm0, __shfl_xor_sync(0xffffffffu, pm0, 1));
            pm0 = fmaxf(pm0, __shfl_xor_sync(0xffffffffu, pm0, 2));
            pm1 = fmaxf(pm1, __shfl_xor_sync(0xffffffffu, pm1, 1));
            pm1 = fmaxf(pm1, __shfl_xor_sync(0xffffffffu, pm1, 2));
            if (t4 == 0) {
                pmax[r0 * 2 + wc] = pm0;
                pmax[r1 * 2 + wc] = pm1;
            }
        }
        __syncthreads();

        if (have_next) { load_k((kt + 1) * 128); cp_commit(); }

        if (tid < 128) {
            const float m_old = row_m[tid];
            const float mn = fmaxf(m_old, fmaxf(pmax[tid * 2], pmax[tid * 2 + 1]));
            row_m[tid] = mn;
            row_s[tid] = __expf(m_old - mn);
        }
        __syncthreads();

        {
            const float mn0 = row_m[r0], mn1 = row_m[r1];
            float sum0 = 0.0f, sum1 = 0.0f;
            #pragma unroll
            for (int nf = 0; nf < 8; nf++) {
                const int c0 = wc * 64 + nf * 8 + t4 * 2;
                const float p00 = __expf(s_acc[nf][0] - mn0);
                const float p01 = __expf(s_acc[nf][1] - mn0);
                const float p10 = __expf(s_acc[nf][2] - mn1);
                const float p11 = __expf(s_acc[nf][3] - mn1);
                sum0 += p00 + p01;
                sum1 += p10 + p11;
                *reinterpret_cast<uint2*>(&Ss[r0 * SP + c0]) =
                    make_uint2(f2tf32(p00), f2tf32(p01));
                *reinterpret_cast<uint2*>(&Ss[r1 * SP + c0]) =
                    make_uint2(f2tf32(p10), f2tf32(p11));
            }
            sum0 += __shfl_xor_sync(0xffffffffu, sum0, 1);
            sum0 += __shfl_xor_sync(0xffffffffu, sum0, 2);
            sum1 += __shfl_xor_sync(0xffffffffu, sum1, 1);
            sum1 += __shfl_xor_sync(0xffffffffu, sum1, 2);
            if (t4 == 0) {
                psum[r0 * 2 + wc] = sum0;
                psum[r1 * 2 + wc] = sum1;
            }
            const float sc0 = row_s[r0], sc1 = row_s[r1];
            #pragma unroll
            for (int nf = 0; nf < 4; nf++) {
                o_acc[nf][0] *= sc0; o_acc[nf][1] *= sc0;
                o_acc[nf][2] *= sc1; o_acc[nf][3] *= sc1;
            }
        }

        if (have_next) cp_wait<1>(); else cp_wait<0>();
        __syncthreads();

        if (tid < 128)
            row_l[tid] = row_l[tid] * row_s[tid] + psum[tid * 2] + psum[tid * 2 + 1];

        // ---- O += P V (V pre-rounded -> raw bits) ----
        #pragma unroll
        for (int kb = 0; kb < 16; kb++) {
            uint32_t a[4];
            a[0] = __float_as_uint(Ss[r0 * SP + kb * 8 + t4]);
            a[1] = __float_as_uint(Ss[r1 * SP + kb * 8 + t4]);
            a[2] = __float_as_uint(Ss[r0 * SP + kb * 8 + t4 + 4]);
            a[3] = __float_as_uint(Ss[r1 * SP + kb * 8 + t4 + 4]);
            #pragma unroll
            for (int nf = 0; nf < 4; nf++) {
                const int n = wc * 32 + nf * 8 + g;
                uint32_t bfr[2];
                bfr[0] = __float_as_uint(Vs[(kb * 8 + t4) * SV + n]);
                bfr[1] = __float_as_uint(Vs[(kb * 8 + t4 + 4) * SV + n]);
                mma_tf32(o_acc[nf], a, bfr);
            }
        }
        __syncthreads();

        if (have_next) { load_v((kt + 1) * 128); cp_commit(); }
    }

    // ---- normalize + store (tf32-rounded for the O-projection GEMM) ----
    const float il0 = 1.0f / row_l[r0];
    const float il1 = 1.0f / row_l[r1];
    #pragma unroll
    for (int nf = 0; nf < 4; nf++) {
        const int d = wc * 32 + nf * 8 + t4 * 2;
        float* p0 = &out[((size_t)(b * T_SEQ + q0 + r0)) * D_MODEL + h * 64 + d];
        float* p1 = &out[((size_t)(b * T_SEQ + q0 + r1)) * D_MODEL + h * 64 + d];
        *reinterpret_cast<uint2*>(p0) =
            make_uint2(f2tf32(o_acc[nf][0] * il0), f2tf32(o_acc[nf][1] * il0));
        *reinterpret_cast<uint2*>(p1) =
            make_uint2(f2tf32(o_acc[nf][2] * il1), f2tf32(o_acc[nf][3] * il1));
    }
}

// ---------------------------------------------------------------------------
extern "C" void kernel_launch(void* const* d_in, const int* in_sizes, int n_in,
                              void* d_out, int out_size)
{
    const float* x  = (const float*)d_in[0];
    const float* Wq = (const float*)d_in[1];
    const float* bq = (const float*)d_in[2];
    const float* Wk = (const float*)d_in[3];
    const float* bk = (const float*)d_in[4];
    const float* Wv = (const float*)d_in[5];
    const float* bv = (const float*)d_in[6];
    const float* Wo = (const float*)d_in[7];
    const float* bo = (const float*)d_in[8];
    float* out = (float*)d_out;

    float *Q, *K, *V, *attn, *xr, *Wr;
    cudaGetSymbolAddress((void**)&Q, g_Q);
    cudaGetSymbolAddress((void**)&K, g_K);
    cudaGetSymbolAddress((void**)&V, g_V);
    cudaGetSymbolAddress((void**)&attn, g_attn);
    cudaGetSymbolAddress((void**)&xr, g_xr);
    cudaGetSymbolAddress((void**)&Wr, g_Wr);
    float* Wqr = Wr;
    float* Wkr = Wr + (size_t)D_MODEL * D_MODEL;
    float* Wvr = Wr + (size_t)2 * D_MODEL * D_MODEL;
    float* Wor = Wr + (size_t)3 * D_MODEL * D_MODEL;

    cudaFuncSetAttribute(qkv_gemm_kernel,
                         cudaFuncAttributeMaxDynamicSharedMemorySize,
                         GEMM_SMEM_BYTES);
    cudaFuncSetAttribute(out_gemm_kernel,
                         cudaFuncAttributeMaxDynamicSharedMemorySize,
                         GEMM_SMEM_BYTES);
    cudaFuncSetAttribute(attn_mma_kernel,
                         cudaFuncAttributeMaxDynamicSharedMemorySize,
                         ATTN_SMEM_BYTES);

    // ---- pre-round operands to tf32 ----
    const int wn4 = D_MODEL * D_MODEL / 4;     // 262144
    const int xn4 = M_ROWS * D_MODEL / 4;      // 1048576
    round_tf32_kernel<<<592, 256>>>(x,  xr,  xn4);
    round_tf32_kernel<<<592, 256>>>(Wq, Wqr, wn4);
    round_tf32_kernel<<<592, 256>>>(Wk, Wkr, wn4);
    round_tf32_kernel<<<592, 256>>>(Wv, Wvr, wn4);
    round_tf32_kernel<<<592, 256>>>(Wo, Wor, wn4);

    // ---- fused QKV projection ----
    qkv_gemm_kernel<<<dim3(24, 32), 256, GEMM_SMEM_BYTES>>>(
        xr, Wqr, Wkr, Wvr, bq, bk, bv, Q, K, V);

    // ---- attention ----
    attn_mma_kernel<<<dim3(T_SEQ / 128, B_SIZE * N_HEADS), 512,
                      ATTN_SMEM_BYTES>>>(Q, K, V, attn);

    // ---- output projection ----
    out_gemm_kernel<<<dim3(8, 32), 256, GEMM_SMEM_BYTES>>>(attn, Wor, bo, out);
}

// round 7
// speedup vs baseline: 1.0100x; 1.0100x over previous
#include <cuda_runtime.h>
#include <cstdint>

#define D_MODEL 1024
#define N_HEADS 16
#define D_HEAD  64
#define B_SIZE  2
#define T_SEQ   2048
#define M_ROWS  (B_SIZE * T_SEQ)   // 4096

__device__ float g_Q[M_ROWS * D_MODEL];      // [B,H,T,64] natural, tf32, scaled
__device__ float g_K[M_ROWS * D_MODEL];
__device__ float g_V[M_ROWS * D_MODEL];
__device__ float g_attn[M_ROWS * D_MODEL];   // [B,T,1024] perm32 cols, tf32
__device__ float g_xr[M_ROWS * D_MODEL];     // x, perm32 cols, tf32
__device__ float g_Wt[4][D_MODEL * D_MODEL]; // W^T: [n][perm32(k)], tf32

// ===========================================================================
__device__ __forceinline__ uint32_t f2tf32(float x) {
    uint32_t r;
    asm("cvt.rna.tf32.f32 %0, %1;" : "=r"(r) : "f"(x));
    return r;
}
__device__ __forceinline__ float rtf(float x) { return __uint_as_float(f2tf32(x)); }

__device__ __forceinline__ void mma_tf32(float c[4], const uint32_t a[4],
                                         const uint32_t b[2]) {
    asm volatile(
        "mma.sync.aligned.m16n8k8.row.col.f32.tf32.tf32.f32 "
        "{%0,%1,%2,%3}, {%4,%5,%6,%7}, {%8,%9}, {%0,%1,%2,%3};"
        : "+f"(c[0]), "+f"(c[1]), "+f"(c[2]), "+f"(c[3])
        : "r"(a[0]), "r"(a[1]), "r"(a[2]), "r"(a[3]), "r"(b[0]), "r"(b[1]));
}
__device__ __forceinline__ void cp_async16(void* dst_smem, const void* src) {
    uint32_t d = (uint32_t)__cvta_generic_to_shared(dst_smem);
    asm volatile("cp.async.cg.shared.global [%0], [%1], 16;" :: "r"(d), "l"(src));
}
__device__ __forceinline__ void cp_commit() { asm volatile("cp.async.commit_group;"); }
template <int N>
__device__ __forceinline__ void cp_wait() {
    asm volatile("cp.async.wait_group %0;" :: "n"(N));
}

// ===========================================================================
// Prepass 1: x -> xr rounded + per-32-block column permutation
// p(k) = (k%4)*8 + k/4  (within each 32-block). Writes stay in one 128B line.
// ===========================================================================
__global__ void permute_x_kernel(const float* __restrict__ src,
                                 float* __restrict__ dst, int n4)
{
    int i = blockIdx.x * blockDim.x + threadIdx.x;
    const int stride = gridDim.x * blockDim.x;
    for (; i < n4; i += stride) {
        float4 v = reinterpret_cast<const float4*>(src)[i];
        const int m = i >> 8;            // 256 float4 per row of 1024
        const int c = i & 255;
        const int base = m * 1024 + ((4 * c) & ~31);
        const int uu = c & 7;            // k/4 within block
        dst[base + 0 * 8 + uu] = rtf(v.x);
        dst[base + 1 * 8 + uu] = rtf(v.y);
        dst[base + 2 * 8 + uu] = rtf(v.z);
        dst[base + 3 * 8 + uu] = rtf(v.w);
    }
}

// ===========================================================================
// Prepass 2: W[k][n] -> Wt[n][p(k)] rounded. 32x32 tile transpose.
// grid (32 n-tiles, 32 k-tiles, 4 matrices), 256 threads.
// ===========================================================================
__global__ void transpose_w_kernel(const float* __restrict__ Wq,
                                   const float* __restrict__ Wk,
                                   const float* __restrict__ Wv,
                                   const float* __restrict__ Wo,
                                   float* __restrict__ dst)
{
    __shared__ float sm[32][33];
    const int z = blockIdx.z;
    const float* W = (z == 0) ? Wq : (z == 1) ? Wk : (z == 2) ? Wv : Wo;
    float* out = dst + (size_t)z * D_MODEL * D_MODEL;

    const int n0 = blockIdx.x * 32;
    const int k0 = blockIdx.y * 32;
    const int t  = threadIdx.x;
    {
        const int kl = t >> 3;
        const int nc = t & 7;
        float4 v = *reinterpret_cast<const float4*>(
            &W[(size_t)(k0 + kl) * D_MODEL + n0 + nc * 4]);
        sm[kl][nc * 4 + 0] = rtf(v.x);
        sm[kl][nc * 4 + 1] = rtf(v.y);
        sm[kl][nc * 4 + 2] = rtf(v.z);
        sm[kl][nc * 4 + 3] = rtf(v.w);
    }
    __syncthreads();
    {
        const int nl = t >> 3;
        const int kc = t & 7;
        // permuted positions 4kc..4kc+3 pull original k = kb, kb+4, kb+8, kb+12
        const int kb = (kc >> 1) + 16 * (kc & 1);
        float4 o;
        o.x = sm[kb + 0][nl];
        o.y = sm[kb + 4][nl];
        o.z = sm[kb + 8][nl];
        o.w = sm[kb + 12][nl];
        *reinterpret_cast<float4*>(
            &out[(size_t)(n0 + nl) * D_MODEL + k0 + kc * 4]) = o;
    }
}

// ===========================================================================
// TF32 GEMM with permuted layouts. All fragment loads are LDS.128.
// BM=BN=128, BK=32, 256 threads = 8 warps (2 M x 4 N), warp tile 64x32.
// Smem: As[128][36] (m-row of 32 perm k + pad), Bs[128][36] (n-row), 2 stages.
// ===========================================================================
#define GST 36
#define GT_FLOATS (128 * GST)
#define GEMM_SMEM_BYTES (4 * GT_FLOATS * 4)    // 2 stages x (A + B)

__device__ __forceinline__ void gemm_mainloop_perm(
    const float* __restrict__ A, const float* __restrict__ Wt,
    float* As, float* Bs, int brow, int bcol, float acc[4][4][4])
{
    const int tid  = threadIdx.x;
    const int lane = tid & 31;
    const int g    = lane >> 2;
    const int t4   = lane & 3;
    const int wid  = tid >> 5;
    const int warp_m = (wid & 1) * 64;
    const int warp_n = (wid >> 1) * 32;

    const int lr = tid >> 3;          // rows lr, lr+32, lr+64, lr+96
    const int lc = tid & 7;           // float4 column

    auto load_stage = [&](int k0, int buf) {
        float* as = As + buf * GT_FLOATS;
        float* bs = Bs + buf * GT_FLOATS;
        #pragma unroll
        for (int it = 0; it < 4; it++) {
            const int m = lr + it * 32;
            cp_async16(&as[m * GST + lc * 4],
                       &A[(size_t)(brow + m) * D_MODEL + k0 + lc * 4]);
        }
        #pragma unroll
        for (int it = 0; it < 4; it++) {
            const int n = lr + it * 32;
            cp_async16(&bs[n * GST + lc * 4],
                       &Wt[(size_t)(bcol + n) * D_MODEL + k0 + lc * 4]);
        }
        cp_commit();
    };

    load_stage(0, 0);

    for (int it = 0; it < 32; it++) {
        if (it + 1 < 32) {
            load_stage((it + 1) * 32, (it + 1) & 1);
            cp_wait<1>();
        } else {
            cp_wait<0>();
        }
        __syncthreads();

        const float* as = As + (it & 1) * GT_FLOATS;
        const float* bs = Bs + (it & 1) * GT_FLOATS;

        #pragma unroll
        for (int hh = 0; hh < 2; hh++) {       // k-subblocks 2h, 2h+1
            float4 a0[4], a1[4], bv[4];
            #pragma unroll
            for (int mf = 0; mf < 4; mf++) {
                const int m = warp_m + mf * 16 + g;
                a0[mf] = *reinterpret_cast<const float4*>(
                    &as[(m    ) * GST + t4 * 8 + hh * 4]);
                a1[mf] = *reinterpret_cast<const float4*>(
                    &as[(m + 8) * GST + t4 * 8 + hh * 4]);
            }
            #pragma unroll
            for (int nf = 0; nf < 4; nf++) {
                const int n = warp_n + nf * 8 + g;
                bv[nf] = *reinterpret_cast<const float4*>(
                    &bs[n * GST + t4 * 8 + hh * 4]);
            }
            #pragma unroll
            for (int ks = 0; ks < 2; ks++) {
                #pragma unroll
                for (int mf = 0; mf < 4; mf++) {
                    uint32_t a[4];
                    a[0] = __float_as_uint(ks ? a0[mf].z : a0[mf].x);
                    a[1] = __float_as_uint(ks ? a1[mf].z : a1[mf].x);
                    a[2] = __float_as_uint(ks ? a0[mf].w : a0[mf].y);
                    a[3] = __float_as_uint(ks ? a1[mf].w : a1[mf].y);
                    #pragma unroll
                    for (int nf = 0; nf < 4; nf++) {
                        uint32_t b[2];
                        b[0] = __float_as_uint(ks ? bv[nf].z : bv[nf].x);
                        b[1] = __float_as_uint(ks ? bv[nf].w : bv[nf].y);
                        mma_tf32(acc[mf][nf], a, b);
                    }
                }
            }
        }
        __syncthreads();
    }
}

// ---- Fused QKV projection ----
__global__ __launch_bounds__(256)
void qkv_gemm_kernel(const float* __restrict__ A,  const float* __restrict__ Wt,
                     const float* __restrict__ bq, const float* __restrict__ bk,
                     const float* __restrict__ bv,
                     float* __restrict__ Qo, float* __restrict__ Ko,
                     float* __restrict__ Vo)
{
    extern __shared__ float sm[];
    float* As = sm;
    float* Bs = sm + 2 * GT_FLOATS;

    const int wsel = blockIdx.x >> 3;
    const int bcol = (blockIdx.x & 7) * 128;
    const int brow = blockIdx.y * 128;
    const float* W    = Wt + (size_t)wsel * D_MODEL * D_MODEL;
    const float* bias = (wsel == 0) ? bq : (wsel == 1) ? bk : bv;
    float* C          = (wsel == 0) ? Qo : (wsel == 1) ? Ko : Vo;
    const float scale = (wsel == 0) ? 0.125f : 1.0f;

    float acc[4][4][4];
    #pragma unroll
    for (int mf = 0; mf < 4; mf++)
        #pragma unroll
        for (int nf = 0; nf < 4; nf++)
            #pragma unroll
            for (int c = 0; c < 4; c++) acc[mf][nf][c] = 0.0f;

    gemm_mainloop_perm(A, W, As, Bs, brow, bcol, acc);

    const int lane = threadIdx.x & 31;
    const int g  = lane >> 2, t4 = lane & 3;
    const int wid = threadIdx.x >> 5;
    const int warp_m = (wid & 1) * 64, warp_n = (wid >> 1) * 32;

    #pragma unroll
    for (int mf = 0; mf < 4; mf++) {
        #pragma unroll
        for (int nf = 0; nf < 4; nf++) {
            const int col = bcol + warp_n + nf * 8 + 2 * t4;
            const float b0 = bias[col], b1 = bias[col + 1];
            #pragma unroll
            for (int rr = 0; rr < 2; rr++) {
                const int row = brow + warp_m + mf * 16 + g + rr * 8;
                const float v0 = (acc[mf][nf][rr * 2 + 0] + b0) * scale;
                const float v1 = (acc[mf][nf][rr * 2 + 1] + b1) * scale;
                const int bb = row >> 11, tt = row & (T_SEQ - 1);
                const int hh = col >> 6,  dd = col & 63;
                float* p = &C[(((size_t)(bb * N_HEADS + hh) * T_SEQ) + tt)
                              * D_HEAD + dd];
                p[0] = rtf(v0);
                p[1] = rtf(v1);
            }
        }
    }
}

// ---- Output projection (A = permuted attn, epilogue natural fp32) ----
__global__ __launch_bounds__(256)
void out_gemm_kernel(const float* __restrict__ A, const float* __restrict__ Wt,
                     const float* __restrict__ bias, float* __restrict__ C)
{
    extern __shared__ float sm[];
    float* As = sm;
    float* Bs = sm + 2 * GT_FLOATS;

    const int bcol = blockIdx.x * 128;
    const int brow = blockIdx.y * 128;

    float acc[4][4][4];
    #pragma unroll
    for (int mf = 0; mf < 4; mf++)
        #pragma unroll
        for (int nf = 0; nf < 4; nf++)
            #pragma unroll
            for (int c = 0; c < 4; c++) acc[mf][nf][c] = 0.0f;

    gemm_mainloop_perm(A, Wt, As, Bs, brow, bcol, acc);

    const int lane = threadIdx.x & 31;
    const int g  = lane >> 2, t4 = lane & 3;
    const int wid = threadIdx.x >> 5;
    const int warp_m = (wid & 1) * 64, warp_n = (wid >> 1) * 32;

    #pragma unroll
    for (int mf = 0; mf < 4; mf++) {
        #pragma unroll
        for (int nf = 0; nf < 4; nf++) {
            const int col = bcol + warp_n + nf * 8 + 2 * t4;
            const float b0 = bias[col], b1 = bias[col + 1];
            #pragma unroll
            for (int rr = 0; rr < 2; rr++) {
                const int row = brow + warp_m + mf * 16 + g + rr * 8;
                float* p = &C[(size_t)row * D_MODEL + col];
                p[0] = acc[mf][nf][rr * 2 + 0] + b0;
                p[1] = acc[mf][nf][rr * 2 + 1] + b1;
            }
        }
    }
}

// ===========================================================================
// Tensor-core flash attention (causal) — unchanged mainloop from R5 (passing).
// Epilogue writes g_attn at perm32 column positions for the out-GEMM.
// ===========================================================================
#define SQ 68
#define SK 68
#define SV 72
#define SP 132
#define OFF_Q  0
#define OFF_K  (128 * SQ)
#define OFF_V  (OFF_K + 128 * SK)
#define OFF_S  (OFF_V + 128 * SV)
#define OFF_RM (OFF_S + 128 * SP)
#define OFF_RL (OFF_RM + 128)
#define OFF_RS (OFF_RL + 128)
#define OFF_PM (OFF_RS + 128)
#define OFF_PS (OFF_PM + 256)
#define ATTN_SMEM_FLOATS (OFF_PS + 256)
#define ATTN_SMEM_BYTES  (ATTN_SMEM_FLOATS * 4)

__global__ __launch_bounds__(512, 1)
void attn_mma_kernel(const float* __restrict__ Qh,
                     const float* __restrict__ Kh,
                     const float* __restrict__ Vh,
                     float* __restrict__ out)
{
    extern __shared__ float sm[];
    float* Qs    = sm + OFF_Q;
    float* Ks    = sm + OFF_K;
    float* Vs    = sm + OFF_V;
    float* Ss    = sm + OFF_S;
    float* row_m = sm + OFF_RM;
    float* row_l = sm + OFF_RL;
    float* row_s = sm + OFF_RS;
    float* pmax  = sm + OFF_PM;
    float* psum  = sm + OFF_PS;

    const int tid  = threadIdx.x;
    const int lane = tid & 31;
    const int wid  = tid >> 5;
    const int g    = lane >> 2;
    const int t4   = lane & 3;
    const int wr   = wid >> 1;
    const int wc   = wid & 1;

    const int bx = gridDim.x - 1 - blockIdx.x;
    const int bh = blockIdx.y;
    const int b  = bh >> 4;
    const int h  = bh & 15;
    const int q0 = bx * 128;

    const float* Qb = Qh + (size_t)bh * T_SEQ * D_HEAD;
    const float* Kb = Kh + (size_t)bh * T_SEQ * D_HEAD;
    const float* Vb = Vh + (size_t)bh * T_SEQ * D_HEAD;

    auto load_q = [&]() {
        #pragma unroll
        for (int it = 0; it < 4; it++) {
            const int id = tid + it * 512;
            const int r = id >> 4, c4 = id & 15;
            cp_async16(&Qs[r * SQ + c4 * 4], &Qb[(size_t)(q0 + r) * 64 + c4 * 4]);
        }
    };
    auto load_k = [&](int k0) {
        #pragma unroll
        for (int it = 0; it < 4; it++) {
            const int id = tid + it * 512;
            const int r = id >> 4, c4 = id & 15;
            cp_async16(&Ks[r * SK + c4 * 4], &Kb[(size_t)(k0 + r) * 64 + c4 * 4]);
        }
    };
    auto load_v = [&](int k0) {
        #pragma unroll
        for (int it = 0; it < 4; it++) {
            const int id = tid + it * 512;
            const int r = id >> 4, c4 = id & 15;
            cp_async16(&Vs[r * SV + c4 * 4], &Vb[(size_t)(k0 + r) * 64 + c4 * 4]);
        }
    };

    load_q();
    load_k(0);
    cp_commit();
    load_v(0);
    cp_commit();

    if (tid < 128) { row_m[tid] = -1e30f; row_l[tid] = 0.0f; }

    float o_acc[4][4];
    #pragma unroll
    for (int nf = 0; nf < 4; nf++)
        #pragma unroll
        for (int c = 0; c < 4; c++) o_acc[nf][c] = 0.0f;

    const int r0 = wr * 16 + g;
    const int r1 = r0 + 8;
    const int nkt = bx + 1;

    for (int kt = 0; kt < nkt; kt++) {
        const bool have_next = (kt + 1 < nkt);

        cp_wait<1>();
        __syncthreads();

        float s_acc[8][4];
        #pragma unroll
        for (int nf = 0; nf < 8; nf++)
            #pragma unroll
            for (int c = 0; c < 4; c++) s_acc[nf][c] = 0.0f;

        #pragma unroll
        for (int kb = 0; kb < 8; kb++) {
            uint32_t a[4];
            a[0] = __float_as_uint(Qs[r0 * SQ + kb * 8 + t4]);
            a[1] = __float_as_uint(Qs[r1 * SQ + kb * 8 + t4]);
            a[2] = __float_as_uint(Qs[r0 * SQ + kb * 8 + t4 + 4]);
            a[3] = __float_as_uint(Qs[r1 * SQ + kb * 8 + t4 + 4]);
            #pragma unroll
            for (int nf = 0; nf < 8; nf++) {
                const int n = wc * 64 + nf * 8 + g;
                uint32_t bfr[2];
                bfr[0] = __float_as_uint(Ks[n * SK + kb * 8 + t4]);
                bfr[1] = __float_as_uint(Ks[n * SK + kb * 8 + t4 + 4]);
                mma_tf32(s_acc[nf], a, bfr);
            }
        }

        if (kt == bx) {
            #pragma unroll
            for (int nf = 0; nf < 8; nf++) {
                const int c0 = wc * 64 + nf * 8 + t4 * 2;
                if (c0     > r0) s_acc[nf][0] = -1e30f;
                if (c0 + 1 > r0) s_acc[nf][1] = -1e30f;
                if (c0     > r1) s_acc[nf][2] = -1e30f;
                if (c0 + 1 > r1) s_acc[nf][3] = -1e30f;
            }
        }

        {
            float pm0 = -1e30f, pm1 = -1e30f;
            #pragma unroll
            for (int nf = 0; nf < 8; nf++) {
                pm0 = fmaxf(pm0, fmaxf(s_acc[nf][0], s_acc[nf][1]));
                pm1 = fmaxf(pm1, fmaxf(s_acc[nf][2], s_acc[nf][3]));
            }
            pm0 = fmaxf(pm0, __shfl_xor_sync(0xffffffffu, pm0, 1));
            pm0 = fmaxf(pm0, __shfl_xor_sync(0xffffffffu, pm0, 2));
            pm1 = fmaxf(pm1, __shfl_xor_sync(0xffffffffu, pm1, 1));
            pm1 = fmaxf(pm1, __shfl_xor_sync(0xffffffffu, pm1, 2));
            if (t4 == 0) {
                pmax[r0 * 2 + wc] = pm0;
                pmax[r1 * 2 + wc] = pm1;
            }
        }
        __syncthreads();

        if (have_next) { load_k((kt + 1) * 128); cp_commit(); }

        if (tid < 128) {
            const float m_old = row_m[tid];
            const float mn = fmaxf(m_old, fmaxf(pmax[tid * 2], pmax[tid * 2 + 1]));
            row_m[tid] = mn;
            row_s[tid] = __expf(m_old - mn);
        }
        __syncthreads();

        {
            const float mn0 = row_m[r0], mn1 = row_m[r1];
            float sum0 = 0.0f, sum1 = 0.0f;
            #pragma unroll
            for (int nf = 0; nf < 8; nf++) {
                const int c0 = wc * 64 + nf * 8 + t4 * 2;
                const float p00 = __expf(s_acc[nf][0] - mn0);
                const float p01 = __expf(s_acc[nf][1] - mn0);
                const float p10 = __expf(s_acc[nf][2] - mn1);
                const float p11 = __expf(s_acc[nf][3] - mn1);
                sum0 += p00 + p01;
                sum1 += p10 + p11;
                *reinterpret_cast<uint2*>(&Ss[r0 * SP + c0]) =
                    make_uint2(f2tf32(p00), f2tf32(p01));
                *reinterpret_cast<uint2*>(&Ss[r1 * SP + c0]) =
                    make_uint2(f2tf32(p10), f2tf32(p11));
            }
            sum0 += __shfl_xor_sync(0xffffffffu, sum0, 1);
            sum0 += __shfl_xor_sync(0xffffffffu, sum0, 2);
            sum1 += __shfl_xor_sync(0xffffffffu, sum1, 1);
            sum1 += __shfl_xor_sync(0xffffffffu, sum1, 2);
            if (t4 == 0) {
                psum[r0 * 2 + wc] = sum0;
                psum[r1 * 2 + wc] = sum1;
            }
            const float sc0 = row_s[r0], sc1 = row_s[r1];
            #pragma unroll
            for (int nf = 0; nf < 4; nf++) {
                o_acc[nf][0] *= sc0; o_acc[nf][1] *= sc0;
                o_acc[nf][2] *= sc1; o_acc[nf][3] *= sc1;
            }
        }

        if (have_next) cp_wait<1>(); else cp_wait<0>();
        __syncthreads();

        if (tid < 128)
            row_l[tid] = row_l[tid] * row_s[tid] + psum[tid * 2] + psum[tid * 2 + 1];

        #pragma unroll
        for (int kb = 0; kb < 16; kb++) {
            uint32_t a[4];
            a[0] = __float_as_uint(Ss[r0 * SP + kb * 8 + t4]);
            a[1] = __float_as_uint(Ss[r1 * SP + kb * 8 + t4]);
            a[2] = __float_as_uint(Ss[r0 * SP + kb * 8 + t4 + 4]);
            a[3] = __float_as_uint(Ss[r1 * SP + kb * 8 + t4 + 4]);
            #pragma unroll
            for (int nf = 0; nf < 4; nf++) {
                const int n = wc * 32 + nf * 8 + g;
                uint32_t bfr[2];
                bfr[0] = __float_as_uint(Vs[(kb * 8 + t4) * SV + n]);
                bfr[1] = __float_as_uint(Vs[(kb * 8 + t4 + 4) * SV + n]);
                mma_tf32(o_acc[nf], a, bfr);
            }
        }
        __syncthreads();

        if (have_next) { load_v((kt + 1) * 128); cp_commit(); }
    }

    // ---- normalize + store at perm32 column positions (for out-GEMM) ----
    const float il0 = 1.0f / row_l[r0];
    const float il1 = 1.0f / row_l[r1];
    #pragma unroll
    for (int nf = 0; nf < 4; nf++) {
        #pragma unroll
        for (int e = 0; e < 2; e++) {
            const int inner = nf * 8 + t4 * 2 + e;             // 0..31
            const int pcol  = h * 64 + wc * 32
                              + (inner & 3) * 8 + (inner >> 2); // permuted
            out[((size_t)(b * T_SEQ + q0 + r0)) * D_MODEL + pcol] =
                rtf(o_acc[nf][e] * il0);
            out[((size_t)(b * T_SEQ + q0 + r1)) * D_MODEL + pcol] =
                rtf(o_acc[nf][2 + e] * il1);
        }
    }
}

// ---------------------------------------------------------------------------
extern "C" void kernel_launch(void* const* d_in, const int* in_sizes, int n_in,
                              void* d_out, int out_size)
{
    const float* x  = (const float*)d_in[0];
    const float* Wq = (const float*)d_in[1];
    const float* bq = (const float*)d_in[2];
    const float* Wk = (const float*)d_in[3];
    const float* bk = (const float*)d_in[4];
    const float* Wv = (const float*)d_in[5];
    const float* bv = (const float*)d_in[6];
    const float* Wo = (const float*)d_in[7];
    const float* bo = (const float*)d_in[8];
    float* out = (float*)d_out;

    float *Q, *K, *V, *attn, *xr, *Wt;
    cudaGetSymbolAddress((void**)&Q, g_Q);
    cudaGetSymbolAddress((void**)&K, g_K);
    cudaGetSymbolAddress((void**)&V, g_V);
    cudaGetSymbolAddress((void**)&attn, g_attn);
    cudaGetSymbolAddress((void**)&xr, g_xr);
    cudaGetSymbolAddress((void**)&Wt, g_Wt);
    float* Wot = Wt + (size_t)3 * D_MODEL * D_MODEL;

    cudaFuncSetAttribute(qkv_gemm_kernel,
                         cudaFuncAttributeMaxDynamicSharedMemorySize,
                         GEMM_SMEM_BYTES);
    cudaFuncSetAttribute(out_gemm_kernel,
                         cudaFuncAttributeMaxDynamicSharedMemorySize,
                         GEMM_SMEM_BYTES);
    cudaFuncSetAttribute(attn_mma_kernel,
                         cudaFuncAttributeMaxDynamicSharedMemorySize,
                         ATTN_SMEM_BYTES);

    permute_x_kernel<<<592, 256>>>(x, xr, M_ROWS * D_MODEL / 4);
    transpose_w_kernel<<<dim3(32, 32, 4), 256>>>(Wq, Wk, Wv, Wo, Wt);

    qkv_gemm_kernel<<<dim3(24, 32), 256, GEMM_SMEM_BYTES>>>(
        xr, Wt, bq, bk, bv, Q, K, V);

    attn_mma_kernel<<<dim3(T_SEQ / 128, B_SIZE * N_HEADS), 512,
                      ATTN_SMEM_BYTES>>>(Q, K, V, attn);

    out_gemm_kernel<<<dim3(8, 32), 256, GEMM_SMEM_BYTES>>>(attn, Wot, bo, out);
}

// round 9
// speedup vs baseline: 1.0216x; 1.0115x over previous
#include <cuda_runtime.h>
#include <cstdint>

#define D_MODEL 1024
#define N_HEADS 16
#define D_HEAD  64
#define B_SIZE  2
#define T_SEQ   2048
#define M_ROWS  (B_SIZE * T_SEQ)   // 4096

__device__ float g_Q[M_ROWS * D_MODEL];      // [B,H,T,64perm], tf32, scaled
__device__ float g_K[M_ROWS * D_MODEL];      // [B,H,T,64perm], tf32
__device__ float g_V[M_ROWS * D_MODEL];      // [B,H,T,64] natural, tf32
__device__ float g_Vt[M_ROWS * D_MODEL];     // [B,H,64,Tperm64], tf32
__device__ float g_attn[M_ROWS * D_MODEL];   // [B,T,1024] perm32 cols, tf32
__device__ float g_xr[M_ROWS * D_MODEL];     // x, perm32 cols, tf32
__device__ float g_Wt[4][D_MODEL * D_MODEL]; // W^T: [n][perm32(k)], tf32

// ===========================================================================
__device__ __forceinline__ uint32_t f2tf32(float x) {
    uint32_t r;
    asm("cvt.rna.tf32.f32 %0, %1;" : "=r"(r) : "f"(x));
    return r;
}
__device__ __forceinline__ float rtf(float x) { return __uint_as_float(f2tf32(x)); }
__device__ __forceinline__ uint32_t u32(float x) { return __float_as_uint(x); }

__device__ __forceinline__ void mma_tf32(float c[4], const uint32_t a[4],
                                         const uint32_t b[2]) {
    asm volatile(
        "mma.sync.aligned.m16n8k8.row.col.f32.tf32.tf32.f32 "
        "{%0,%1,%2,%3}, {%4,%5,%6,%7}, {%8,%9}, {%0,%1,%2,%3};"
        : "+f"(c[0]), "+f"(c[1]), "+f"(c[2]), "+f"(c[3])
        : "r"(a[0]), "r"(a[1]), "r"(a[2]), "r"(a[3]), "r"(b[0]), "r"(b[1]));
}
__device__ __forceinline__ void cp_async16(void* dst_smem, const void* src) {
    uint32_t d = (uint32_t)__cvta_generic_to_shared(dst_smem);
    asm volatile("cp.async.cg.shared.global [%0], [%1], 16;" :: "r"(d), "l"(src));
}
__device__ __forceinline__ void cp_commit() { asm volatile("cp.async.commit_group;"); }
template <int N>
__device__ __forceinline__ void cp_wait() {
    asm volatile("cp.async.wait_group %0;" :: "n"(N));
}

// ===========================================================================
// Prepass 1: x -> xr rounded + per-32-block column permutation
// ===========================================================================
__global__ void permute_x_kernel(const float* __restrict__ src,
                                 float* __restrict__ dst, int n4)
{
    int i = blockIdx.x * blockDim.x + threadIdx.x;
    const int stride = gridDim.x * blockDim.x;
    for (; i < n4; i += stride) {
        float4 v = reinterpret_cast<const float4*>(src)[i];
        const int m = i >> 8;
        const int c = i & 255;
        const int base = m * 1024 + ((4 * c) & ~31);
        const int uu = c & 7;
        dst[base + 0 * 8 + uu] = rtf(v.x);
        dst[base + 1 * 8 + uu] = rtf(v.y);
        dst[base + 2 * 8 + uu] = rtf(v.z);
        dst[base + 3 * 8 + uu] = rtf(v.w);
    }
}

// ===========================================================================
// Prepass 2: W[k][n] -> Wt[n][p(k)] rounded. 32x32 tile transpose.
// ===========================================================================
__global__ void transpose_w_kernel(const float* __restrict__ Wq,
                                   const float* __restrict__ Wk,
                                   const float* __restrict__ Wv,
                                   const float* __restrict__ Wo,
                                   float* __restrict__ dst)
{
    __shared__ float sm[32][33];
    const int z = blockIdx.z;
    const float* W = (z == 0) ? Wq : (z == 1) ? Wk : (z == 2) ? Wv : Wo;
    float* out = dst + (size_t)z * D_MODEL * D_MODEL;

    const int n0 = blockIdx.x * 32;
    const int k0 = blockIdx.y * 32;
    const int t  = threadIdx.x;
    {
        const int kl = t >> 3;
        const int nc = t & 7;
        float4 v = *reinterpret_cast<const float4*>(
            &W[(size_t)(k0 + kl) * D_MODEL + n0 + nc * 4]);
        sm[kl][nc * 4 + 0] = rtf(v.x);
        sm[kl][nc * 4 + 1] = rtf(v.y);
        sm[kl][nc * 4 + 2] = rtf(v.z);
        sm[kl][nc * 4 + 3] = rtf(v.w);
    }
    __syncthreads();
    {
        const int nl = t >> 3;
        const int kc = t & 7;
        const int kb = (kc >> 1) + 16 * (kc & 1);
        float4 o;
        o.x = sm[kb + 0][nl];
        o.y = sm[kb + 4][nl];
        o.z = sm[kb + 8][nl];
        o.w = sm[kb + 12][nl];
        *reinterpret_cast<float4*>(
            &out[(size_t)(n0 + nl) * D_MODEL + k0 + kc * 4]) = o;
    }
}

// ===========================================================================
// Prepass 3 (post-QKV): V[bh][t][d] -> Vt[bh][d][tile*64 + p64(j)]
// grid (32 j-tiles, 32 bh), 256 threads.
// ===========================================================================
__global__ void transpose_v_kernel(const float* __restrict__ V,
                                   float* __restrict__ Vt)
{
    __shared__ float sm[64 * 68];
    const int jt = blockIdx.x;
    const int bh = blockIdx.y;
    const int t  = threadIdx.x;
    const float* src = V + ((size_t)bh * T_SEQ + jt * 64) * 64;

    #pragma unroll
    for (int it = 0; it < 4; it++) {
        const int id = t + it * 256;
        const int r = id >> 4, c4 = id & 15;
        float4 v = *reinterpret_cast<const float4*>(&src[r * 64 + c4 * 4]);
        *reinterpret_cast<float4*>(&sm[r * 68 + c4 * 4]) = v;
    }
    __syncthreads();
    #pragma unroll
    for (int it = 0; it < 4; it++) {
        const int id = t + it * 256;
        const int d = id >> 4, q4 = id & 15;
        float tmp[4];
        #pragma unroll
        for (int e = 0; e < 4; e++) {
            const int q   = q4 * 4 + e;
            const int blk = q & 32;
            const int qi  = q & 31;
            const int j   = blk + (qi & 7) * 4 + (qi >> 3);
            tmp[e] = sm[j * 68 + d];
        }
        float4 o = make_float4(tmp[0], tmp[1], tmp[2], tmp[3]);
        *reinterpret_cast<float4*>(
            &Vt[((size_t)bh * 64 + d) * T_SEQ + jt * 64 + q4 * 4]) = o;
    }
}

// ===========================================================================
// TF32 GEMM with permuted layouts (unchanged from R7, passing).
// ===========================================================================
#define GST 36
#define GT_FLOATS (128 * GST)
#define GEMM_SMEM_BYTES (4 * GT_FLOATS * 4)

__device__ __forceinline__ void gemm_mainloop_perm(
    const float* __restrict__ A, const float* __restrict__ Wt,
    float* As, float* Bs, int brow, int bcol, float acc[4][4][4])
{
    const int tid  = threadIdx.x;
    const int lane = tid & 31;
    const int g    = lane >> 2;
    const int t4   = lane & 3;
    const int wid  = tid >> 5;
    const int warp_m = (wid & 1) * 64;
    const int warp_n = (wid >> 1) * 32;

    const int lr = tid >> 3;
    const int lc = tid & 7;

    auto load_stage = [&](int k0, int buf) {
        float* as = As + buf * GT_FLOATS;
        float* bs = Bs + buf * GT_FLOATS;
        #pragma unroll
        for (int it = 0; it < 4; it++) {
            const int m = lr + it * 32;
            cp_async16(&as[m * GST + lc * 4],
                       &A[(size_t)(brow + m) * D_MODEL + k0 + lc * 4]);
        }
        #pragma unroll
        for (int it = 0; it < 4; it++) {
            const int n = lr + it * 32;
            cp_async16(&bs[n * GST + lc * 4],
                       &Wt[(size_t)(bcol + n) * D_MODEL + k0 + lc * 4]);
        }
        cp_commit();
    };

    load_stage(0, 0);

    for (int it = 0; it < 32; it++) {
        if (it + 1 < 32) {
            load_stage((it + 1) * 32, (it + 1) & 1);
            cp_wait<1>();
        } else {
            cp_wait<0>();
        }
        __syncthreads();

        const float* as = As + (it & 1) * GT_FLOATS;
        const float* bs = Bs + (it & 1) * GT_FLOATS;

        #pragma unroll
        for (int hh = 0; hh < 2; hh++) {
            float4 a0[4], a1[4], bv[4];
            #pragma unroll
            for (int mf = 0; mf < 4; mf++) {
                const int m = warp_m + mf * 16 + g;
                a0[mf] = *reinterpret_cast<const float4*>(
                    &as[(m    ) * GST + t4 * 8 + hh * 4]);
                a1[mf] = *reinterpret_cast<const float4*>(
                    &as[(m + 8) * GST + t4 * 8 + hh * 4]);
            }
            #pragma unroll
            for (int nf = 0; nf < 4; nf++) {
                const int n = warp_n + nf * 8 + g;
                bv[nf] = *reinterpret_cast<const float4*>(
                    &bs[n * GST + t4 * 8 + hh * 4]);
            }
            #pragma unroll
            for (int ks = 0; ks < 2; ks++) {
                #pragma unroll
                for (int mf = 0; mf < 4; mf++) {
                    uint32_t a[4];
                    a[0] = u32(ks ? a0[mf].z : a0[mf].x);
                    a[1] = u32(ks ? a1[mf].z : a1[mf].x);
                    a[2] = u32(ks ? a0[mf].w : a0[mf].y);
                    a[3] = u32(ks ? a1[mf].w : a1[mf].y);
                    #pragma unroll
                    for (int nf = 0; nf < 4; nf++) {
                        uint32_t b[2];
                        b[0] = u32(ks ? bv[nf].z : bv[nf].x);
                        b[1] = u32(ks ? bv[nf].w : bv[nf].y);
                        mma_tf32(acc[mf][nf], a, b);
                    }
                }
            }
        }
        __syncthreads();
    }
}

// ---- Fused QKV projection; Q/K written d-permuted, V natural ----
__global__ __launch_bounds__(256)
void qkv_gemm_kernel(const float* __restrict__ A,  const float* __restrict__ Wt,
                     const float* __restrict__ bq, const float* __restrict__ bk,
                     const float* __restrict__ bv,
                     float* __restrict__ Qo, float* __restrict__ Ko,
                     float* __restrict__ Vo)
{
    extern __shared__ float sm[];
    float* As = sm;
    float* Bs = sm + 2 * GT_FLOATS;

    const int wsel = blockIdx.x >> 3;
    const int bcol = (blockIdx.x & 7) * 128;
    const int brow = blockIdx.y * 128;
    const float* W    = Wt + (size_t)wsel * D_MODEL * D_MODEL;
    const float* bias = (wsel == 0) ? bq : (wsel == 1) ? bk : bv;
    float* C          = (wsel == 0) ? Qo : (wsel == 1) ? Ko : Vo;
    const float scale = (wsel == 0) ? 0.125f : 1.0f;

    float acc[4][4][4];
    #pragma unroll
    for (int mf = 0; mf < 4; mf++)
        #pragma unroll
        for (int nf = 0; nf < 4; nf++)
            #pragma unroll
            for (int c = 0; c < 4; c++) acc[mf][nf][c] = 0.0f;

    gemm_mainloop_perm(A, W, As, Bs, brow, bcol, acc);

    const int lane = threadIdx.x & 31;
    const int g  = lane >> 2, t4 = lane & 3;
    const int wid = threadIdx.x >> 5;
    const int warp_m = (wid & 1) * 64, warp_n = (wid >> 1) * 32;

    #pragma unroll
    for (int mf = 0; mf < 4; mf++) {
        #pragma unroll
        for (int nf = 0; nf < 4; nf++) {
            const int col = bcol + warp_n + nf * 8 + 2 * t4;
            const float b0 = bias[col], b1 = bias[col + 1];
            #pragma unroll
            for (int rr = 0; rr < 2; rr++) {
                const int row = brow + warp_m + mf * 16 + g + rr * 8;
                const float v0 = (acc[mf][nf][rr * 2 + 0] + b0) * scale;
                const float v1 = (acc[mf][nf][rr * 2 + 1] + b1) * scale;
                const int bb = row >> 11, tt = row & (T_SEQ - 1);
                const int hh = col >> 6,  dd = col & 63;
                float* p = &C[(((size_t)(bb * N_HEADS + hh) * T_SEQ) + tt)
                              * D_HEAD];
                if (wsel < 2) {
                    const int d1 = dd + 1;
                    const int pd0 = (dd & 32) + (dd & 3) * 8 + ((dd & 31) >> 2);
                    const int pd1 = (d1 & 32) + (d1 & 3) * 8 + ((d1 & 31) >> 2);
                    p[pd0] = rtf(v0);
                    p[pd1] = rtf(v1);
                } else {
                    p[dd]     = rtf(v0);
                    p[dd + 1] = rtf(v1);
                }
            }
        }
    }
}

// ---- Output projection ----
__global__ __launch_bounds__(256)
void out_gemm_kernel(const float* __restrict__ A, const float* __restrict__ Wt,
                     const float* __restrict__ bias, float* __restrict__ C)
{
    extern __shared__ float sm[];
    float* As = sm;
    float* Bs = sm + 2 * GT_FLOATS;

    const int bcol = blockIdx.x * 128;
    const int brow = blockIdx.y * 128;

    float acc[4][4][4];
    #pragma unroll
    for (int mf = 0; mf < 4; mf++)
        #pragma unroll
        for (int nf = 0; nf < 4; nf++)
            #pragma unroll
            for (int c = 0; c < 4; c++) acc[mf][nf][c] = 0.0f;

    gemm_mainloop_perm(A, Wt, As, Bs, brow, bcol, acc);

    const int lane = threadIdx.x & 31;
    const int g  = lane >> 2, t4 = lane & 3;
    const int wid = threadIdx.x >> 5;
    const int warp_m = (wid & 1) * 64, warp_n = (wid >> 1) * 32;

    #pragma unroll
    for (int mf = 0; mf < 4; mf++) {
        #pragma unroll
        for (int nf = 0; nf < 4; nf++) {
            const int col = bcol + warp_n + nf * 8 + 2 * t4;
            const float b0 = bias[col], b1 = bias[col + 1];
            #pragma unroll
            for (int rr = 0; rr < 2; rr++) {
                const int row = brow + warp_m + mf * 16 + g + rr * 8;
                float* p = &C[(size_t)row * D_MODEL + col];
                p[0] = acc[mf][nf][rr * 2 + 0] + b0;
                p[1] = acc[mf][nf][rr * 2 + 1] + b1;
            }
        }
    }
}

// ===========================================================================
// Tensor-core flash attention (causal). BQ = BKV = 64, 256 threads, 2 CTA/SM.
// All operands permuted -> every fragment load is LDS.128.
// ===========================================================================
#define AST 68
#define A_OFF_K  (64 * AST)
#define A_OFF_V  (2 * 64 * AST)
#define A_OFF_S  (3 * 64 * AST)
#define A_OFF_RM (4 * 64 * AST)
#define A_OFF_RL (A_OFF_RM + 64)
#define A_OFF_RS (A_OFF_RL + 64)
#define A_OFF_PM (A_OFF_RS + 64)
#define A_OFF_PS (A_OFF_PM + 128)
#define ATTN_SMEM_FLOATS (A_OFF_PS + 128)     // 17856
#define ATTN_SMEM_BYTES  (ATTN_SMEM_FLOATS * 4)

__global__ __launch_bounds__(256, 2)
void attn_mma_kernel(const float* __restrict__ Qh,
                     const float* __restrict__ Kh,
                     const float* __restrict__ Vth,
                     float* __restrict__ out)
{
    extern __shared__ float sm[];
    float* Qs    = sm;
    float* Ks    = sm + A_OFF_K;
    float* Vs    = sm + A_OFF_V;
    float* Ss    = sm + A_OFF_S;
    float* row_m = sm + A_OFF_RM;
    float* row_l = sm + A_OFF_RL;
    float* row_s = sm + A_OFF_RS;
    float* pmax  = sm + A_OFF_PM;
    float* psum  = sm + A_OFF_PS;

    const int tid  = threadIdx.x;
    const int lane = tid & 31;
    const int wid  = tid >> 5;
    const int g    = lane >> 2;
    const int t4   = lane & 3;
    const int wr   = wid >> 1;
    const int wc   = wid & 1;

    const int bx = gridDim.x - 1 - blockIdx.x;   // heavy blocks first
    const int bh = blockIdx.y;
    const int b  = bh >> 4;
    const int h  = bh & 15;
    const int q0 = bx * 64;

    const float* Qb = Qh  + (size_t)bh * T_SEQ * D_HEAD;
    const float* Kb = Kh  + (size_t)bh * T_SEQ * D_HEAD;
    const float* Vb = Vth + (size_t)bh * D_HEAD * T_SEQ;   // [d][t]

    auto load_q = [&]() {
        #pragma unroll
        for (int it = 0; it < 4; it++) {
            const int id = tid + it * 256;
            const int r = id >> 4, c4 = id & 15;
            cp_async16(&Qs[r * AST + c4 * 4], &Qb[(size_t)(q0 + r) * 64 + c4 * 4]);
        }
    };
    auto load_k = [&](int k0) {
        #pragma unroll
        for (int it = 0; it < 4; it++) {
            const int id = tid + it * 256;
            const int r = id >> 4, c4 = id & 15;
            cp_async16(&Ks[r * AST + c4 * 4], &Kb[(size_t)(k0 + r) * 64 + c4 * 4]);
        }
    };
    auto load_v = [&](int k0) {
        #pragma unroll
        for (int it = 0; it < 4; it++) {
            const int id = tid + it * 256;
            const int r = id >> 4, c4 = id & 15;
            cp_async16(&Vs[r * AST + c4 * 4],
                       &Vb[(size_t)r * T_SEQ + k0 + c4 * 4]);
        }
    };

    load_q();
    load_k(0);
    cp_commit();
    load_v(0);
    cp_commit();

    if (tid < 64) { row_m[tid] = -1e30f; row_l[tid] = 0.0f; }

    float o_acc[4][4];
    #pragma unroll
    for (int nf = 0; nf < 4; nf++)
        #pragma unroll
        for (int c = 0; c < 4; c++) o_acc[nf][c] = 0.0f;

    const int r0 = wr * 16 + g;
    const int r1 = r0 + 8;
    const int nkt = bx + 1;

    for (int kt = 0; kt < nkt; kt++) {
        const bool have_next = (kt + 1 < nkt);

        cp_wait<1>();
        __syncthreads();

        // ---- S = Q K^T : 4 kb-pairs x 4 n-frags, all LDS.128 ----
        float s_acc[4][4];
        #pragma unroll
        for (int nf = 0; nf < 4; nf++)
            #pragma unroll
            for (int c = 0; c < 4; c++) s_acc[nf][c] = 0.0f;

        #pragma unroll
        for (int bp = 0; bp < 4; bp++) {
            const int off = (bp >> 1) * 32 + t4 * 8 + (bp & 1) * 4;
            float4 qa = *reinterpret_cast<const float4*>(&Qs[r0 * AST + off]);
            float4 qb = *reinterpret_cast<const float4*>(&Qs[r1 * AST + off]);
            uint32_t ae[4] = {u32(qa.x), u32(qb.x), u32(qa.y), u32(qb.y)};
            uint32_t ao[4] = {u32(qa.z), u32(qb.z), u32(qa.w), u32(qb.w)};
            #pragma unroll
            for (int nf = 0; nf < 4; nf++) {
                const int n = wc * 32 + nf * 8 + g;
                float4 kv = *reinterpret_cast<const float4*>(&Ks[n * AST + off]);
                uint32_t be[2] = {u32(kv.x), u32(kv.y)};
                uint32_t bo[2] = {u32(kv.z), u32(kv.w)};
                mma_tf32(s_acc[nf], ae, be);
                mma_tf32(s_acc[nf], ao, bo);
            }
        }

        // ---- causal mask (diagonal tile only) ----
        if (kt == bx) {
            #pragma unroll
            for (int nf = 0; nf < 4; nf++) {
                const int c0 = wc * 32 + nf * 8 + t4 * 2;
                if (c0     > r0) s_acc[nf][0] = -1e30f;
                if (c0 + 1 > r0) s_acc[nf][1] = -1e30f;
                if (c0     > r1) s_acc[nf][2] = -1e30f;
                if (c0 + 1 > r1) s_acc[nf][3] = -1e30f;
            }
        }

        // ---- partial row max over this warp's 32 cols ----
        {
            float pm0 = -1e30f, pm1 = -1e30f;
            #pragma unroll
            for (int nf = 0; nf < 4; nf++) {
                pm0 = fmaxf(pm0, fmaxf(s_acc[nf][0], s_acc[nf][1]));
                pm1 = fmaxf(pm1, fmaxf(s_acc[nf][2], s_acc[nf][3]));
            }
            pm0 = fmaxf(pm0, __shfl_xor_sync(0xffffffffu, pm0, 1));
            pm0 = fmaxf(pm0, __shfl_xor_sync(0xffffffffu, pm0, 2));
            pm1 = fmaxf(pm1, __shfl_xor_sync(0xffffffffu, pm1, 1));
            pm1 = fmaxf(pm1, __shfl_xor_sync(0xffffffffu, pm1, 2));
            if (t4 == 0) {
                pmax[r0 * 2 + wc] = pm0;
                pmax[r1 * 2 + wc] = pm1;
            }
        }
        __syncthreads();          // pmax ready; Ks free

        if (have_next) { load_k((kt + 1) * 64); cp_commit(); }

        if (tid < 64) {
            const float m_old = row_m[tid];
            const float mn = fmaxf(m_old, fmaxf(pmax[tid * 2], pmax[tid * 2 + 1]));
            row_m[tid] = mn;
            row_s[tid] = __expf(m_old - mn);
        }
        __syncthreads();          // row_m / row_s ready

        // ---- exp, P -> smem at permuted positions, partial sums, O rescale
        {
            const float mn0 = row_m[r0], mn1 = row_m[r1];
            float sum0 = 0.0f, sum1 = 0.0f;
            #pragma unroll
            for (int nf = 0; nf < 4; nf++) {
                #pragma unroll
                for (int e = 0; e < 2; e++) {
                    const int inner = nf * 8 + t4 * 2 + e;
                    const int pos   = wc * 32 + (inner & 3) * 8 + (inner >> 2);
                    const float p0 = __expf(s_acc[nf][e]     - mn0);
                    const float p1 = __expf(s_acc[nf][2 + e] - mn1);
                    sum0 += p0;
                    sum1 += p1;
                    Ss[r0 * AST + pos] = __uint_as_float(f2tf32(p0));
                    Ss[r1 * AST + pos] = __uint_as_float(f2tf32(p1));
                }
            }
            sum0 += __shfl_xor_sync(0xffffffffu, sum0, 1);
            sum0 += __shfl_xor_sync(0xffffffffu, sum0, 2);
            sum1 += __shfl_xor_sync(0xffffffffu, sum1, 1);
            sum1 += __shfl_xor_sync(0xffffffffu, sum1, 2);
            if (t4 == 0) {
                psum[r0 * 2 + wc] = sum0;
                psum[r1 * 2 + wc] = sum1;
            }
            const float sc0 = row_s[r0], sc1 = row_s[r1];
            #pragma unroll
            for (int nf = 0; nf < 4; nf++) {
                o_acc[nf][0] *= sc0; o_acc[nf][1] *= sc0;
                o_acc[nf][2] *= sc1; o_acc[nf][3] *= sc1;
            }
        }

        if (have_next) cp_wait<1>(); else cp_wait<0>();   // V(kt) landed
        __syncthreads();          // Ss + psum ready, Vs visible

        if (tid < 64)
            row_l[tid] = row_l[tid] * row_s[tid] + psum[tid * 2] + psum[tid * 2 + 1];

        // ---- O += P V : 4 kb-pairs x 4 n-frags, all LDS.128 ----
        #pragma unroll
        for (int bp = 0; bp < 4; bp++) {
            const int off = (bp >> 1) * 32 + t4 * 8 + (bp & 1) * 4;
            float4 pa = *reinterpret_cast<const float4*>(&Ss[r0 * AST + off]);
            float4 pb = *reinterpret_cast<const float4*>(&Ss[r1 * AST + off]);
            uint32_t ae[4] = {u32(pa.x), u32(pb.x), u32(pa.y), u32(pb.y)};
            uint32_t ao[4] = {u32(pa.z), u32(pb.z), u32(pa.w), u32(pb.w)};
            #pragma unroll
            for (int nf = 0; nf < 4; nf++) {
                const int n = wc * 32 + nf * 8 + g;
                float4 vv = *reinterpret_cast<const float4*>(&Vs[n * AST + off]);
                uint32_t be[2] = {u32(vv.x), u32(vv.y)};
                uint32_t bo[2] = {u32(vv.z), u32(vv.w)};
                mma_tf32(o_acc[nf], ae, be);
                mma_tf32(o_acc[nf], ao, bo);
            }
        }
        __syncthreads();          // Vs free

        if (have_next) { load_v((kt + 1) * 64); cp_commit(); }
    }

    // ---- normalize + store at perm32 column positions (for out-GEMM) ----
    const float il0 = 1.0f / row_l[r0];
    const float il1 = 1.0f / row_l[r1];
    #pragma unroll
    for (int nf = 0; nf < 4; nf++) {
        #pragma unroll
        for (int e = 0; e < 2; e++) {
            const int d     = wc * 32 + nf * 8 + t4 * 2 + e;
            const int inner = d & 31;
            const int pcol  = h * 64 + (d & 32)
                              + (inner & 3) * 8 + (inner >> 2);
            out[((size_t)(b * T_SEQ + q0 + r0)) * D_MODEL + pcol] =
                rtf(o_acc[nf][e] * il0);
            out[((size_t)(b * T_SEQ + q0 + r1)) * D_MODEL + pcol] =
                rtf(o_acc[nf][2 + e] * il1);
        }
    }
}

// ---------------------------------------------------------------------------
extern "C" void kernel_launch(void* const* d_in, const int* in_sizes, int n_in,
                              void* d_out, int out_size)
{
    const float* x  = (const float*)d_in[0];
    const float* Wq = (const float*)d_in[1];
    const float* bq = (const float*)d_in[2];
    const float* Wk = (const float*)d_in[3];
    const float* bk = (const float*)d_in[4];
    const float* Wv = (const float*)d_in[5];
    const float* bv = (const float*)d_in[6];
    const float* Wo = (const float*)d_in[7];
    const float* bo = (const float*)d_in[8];
    float* out = (float*)d_out;

    float *Q, *K, *V, *Vt, *attn, *xr, *Wt;
    cudaGetSymbolAddress((void**)&Q, g_Q);
    cudaGetSymbolAddress((void**)&K, g_K);
    cudaGetSymbolAddress((void**)&V, g_V);
    cudaGetSymbolAddress((void**)&Vt, g_Vt);
    cudaGetSymbolAddress((void**)&attn, g_attn);
    cudaGetSymbolAddress((void**)&xr, g_xr);
    cudaGetSymbolAddress((void**)&Wt, g_Wt);
    float* Wot = Wt + (size_t)3 * D_MODEL * D_MODEL;

    cudaFuncSetAttribute(qkv_gemm_kernel,
                         cudaFuncAttributeMaxDynamicSharedMemorySize,
                         GEMM_SMEM_BYTES);
    cudaFuncSetAttribute(out_gemm_kernel,
                         cudaFuncAttributeMaxDynamicSharedMemorySize,
                         GEMM_SMEM_BYTES);
    cudaFuncSetAttribute(attn_mma_kernel,
                         cudaFuncAttributeMaxDynamicSharedMemorySize,
                         ATTN_SMEM_BYTES);

    permute_x_kernel<<<592, 256>>>(x, xr, M_ROWS * D_MODEL / 4);
    transpose_w_kernel<<<dim3(32, 32, 4), 256>>>(Wq, Wk, Wv, Wo, Wt);

    qkv_gemm_kernel<<<dim3(24, 32), 256, GEMM_SMEM_BYTES>>>(
        xr, Wt, bq, bk, bv, Q, K, V);

    transpose_v_kernel<<<dim3(T_SEQ / 64, B_SIZE * N_HEADS), 256>>>(V, Vt);

    attn_mma_kernel<<<dim3(T_SEQ / 64, B_SIZE * N_HEADS), 256,
                      ATTN_SMEM_BYTES>>>(Q, K, Vt, attn);

    out_gemm_kernel<<<dim3(8, 32), 256, GEMM_SMEM_BYTES>>>(attn, Wot, bo, out);
}

// round 10
// speedup vs baseline: 2.0290x; 1.9861x over previous
#include <cuda_runtime.h>
#include <cuda_fp16.h>
#include <cstdint>

#define D_MODEL 1024
#define N_HEADS 16
#define D_HEAD  64
#define B_SIZE  2
#define T_SEQ   2048
#define M_ROWS  (B_SIZE * T_SEQ)   // 4096

__device__ __half g_Q[M_ROWS * D_MODEL];      // [B,H,T,64], scaled 0.125
__device__ __half g_K[M_ROWS * D_MODEL];      // [B,H,T,64]
__device__ __half g_V[M_ROWS * D_MODEL];      // [B,H,T,64]
__device__ __half g_Vt[M_ROWS * D_MODEL];     // [B,H,64,T]
__device__ __half g_attn[M_ROWS * D_MODEL];   // [B,T,1024]
__device__ __half g_xh[M_ROWS * D_MODEL];     // x as fp16
__device__ __half g_Wt[4][D_MODEL * D_MODEL]; // W^T: [n][k], fp16

// ===========================================================================
__device__ __forceinline__ uint32_t sptr(const void* p) {
    return (uint32_t)__cvta_generic_to_shared(p);
}
__device__ __forceinline__ void ldsm_x4(uint32_t& r0, uint32_t& r1,
                                        uint32_t& r2, uint32_t& r3,
                                        uint32_t addr) {
    asm volatile("ldmatrix.sync.aligned.m8n8.x4.shared.b16 {%0,%1,%2,%3},[%4];"
                 : "=r"(r0), "=r"(r1), "=r"(r2), "=r"(r3) : "r"(addr));
}
__device__ __forceinline__ void mma_f16(float c[4], const uint32_t a[4],
                                        const uint32_t b[2]) {
    asm volatile(
        "mma.sync.aligned.m16n8k16.row.col.f32.f16.f16.f32 "
        "{%0,%1,%2,%3}, {%4,%5,%6,%7}, {%8,%9}, {%0,%1,%2,%3};"
        : "+f"(c[0]), "+f"(c[1]), "+f"(c[2]), "+f"(c[3])
        : "r"(a[0]), "r"(a[1]), "r"(a[2]), "r"(a[3]), "r"(b[0]), "r"(b[1]));
}
__device__ __forceinline__ void cp_async16(void* dst_smem, const void* src) {
    uint32_t d = (uint32_t)__cvta_generic_to_shared(dst_smem);
    asm volatile("cp.async.cg.shared.global [%0], [%1], 16;" :: "r"(d), "l"(src));
}
__device__ __forceinline__ void cp_commit() { asm volatile("cp.async.commit_group;"); }
template <int N>
__device__ __forceinline__ void cp_wait() {
    asm volatile("cp.async.wait_group %0;" :: "n"(N));
}

// ===========================================================================
// Prepass 1: x (fp32) -> fp16
// ===========================================================================
__global__ void convert_x_kernel(const float* __restrict__ src,
                                 __half* __restrict__ dst, int n4)
{
    int i = blockIdx.x * blockDim.x + threadIdx.x;
    const int stride = gridDim.x * blockDim.x;
    for (; i < n4; i += stride) {
        float4 v = reinterpret_cast<const float4*>(src)[i];
        __half2 h0 = __floats2half2_rn(v.x, v.y);
        __half2 h1 = __floats2half2_rn(v.z, v.w);
        uint2 o = make_uint2(*(uint32_t*)&h0, *(uint32_t*)&h1);
        reinterpret_cast<uint2*>(dst)[i] = o;
    }
}

// ===========================================================================
// Prepass 2: W[k][n] fp32 -> Wt[n][k] fp16. 32x32 tile transpose.
// ===========================================================================
__global__ void transpose_w_kernel(const float* __restrict__ Wq,
                                   const float* __restrict__ Wk,
                                   const float* __restrict__ Wv,
                                   const float* __restrict__ Wo,
                                   __half* __restrict__ dst)
{
    __shared__ float sm[32][33];
    const int z = blockIdx.z;
    const float* W = (z == 0) ? Wq : (z == 1) ? Wk : (z == 2) ? Wv : Wo;
    __half* out = dst + (size_t)z * D_MODEL * D_MODEL;

    const int n0 = blockIdx.x * 32;
    const int k0 = blockIdx.y * 32;
    const int t  = threadIdx.x;
    {
        const int kl = t >> 3;
        const int nc = t & 7;
        float4 v = *reinterpret_cast<const float4*>(
            &W[(size_t)(k0 + kl) * D_MODEL + n0 + nc * 4]);
        sm[kl][nc * 4 + 0] = v.x;
        sm[kl][nc * 4 + 1] = v.y;
        sm[kl][nc * 4 + 2] = v.z;
        sm[kl][nc * 4 + 3] = v.w;
    }
    __syncthreads();
    {
        const int nl = t >> 3;
        const int kc = t & 7;
        __half2 h0 = __floats2half2_rn(sm[kc * 4 + 0][nl], sm[kc * 4 + 1][nl]);
        __half2 h1 = __floats2half2_rn(sm[kc * 4 + 2][nl], sm[kc * 4 + 3][nl]);
        uint2 o = make_uint2(*(uint32_t*)&h0, *(uint32_t*)&h1);
        *reinterpret_cast<uint2*>(
            &out[(size_t)(n0 + nl) * D_MODEL + k0 + kc * 4]) = o;
    }
}

// ===========================================================================
// Prepass 3 (post-QKV): V[bh][t][64] -> Vt[bh][d][t]  (fp16)
// grid (32 j-tiles, 32 bh), 256 threads.
// ===========================================================================
__global__ void transpose_v_kernel(const __half* __restrict__ V,
                                   __half* __restrict__ Vt)
{
    __shared__ __half sm[64 * 72];
    const int jt = blockIdx.x;
    const int bh = blockIdx.y;
    const int t  = threadIdx.x;
    const __half* src = V + ((size_t)bh * T_SEQ + jt * 64) * 64;

    #pragma unroll
    for (int it = 0; it < 2; it++) {
        const int id = t + it * 256;
        const int r = id >> 3, c8 = id & 7;     // 64 rows x 8 chunks(8 halves)
        uint4 v = *reinterpret_cast<const uint4*>(&src[r * 64 + c8 * 8]);
        *reinterpret_cast<uint4*>(&sm[r * 72 + c8 * 8]) = v;
    }
    __syncthreads();
    #pragma unroll
    for (int it = 0; it < 2; it++) {
        const int id = t + it * 256;
        const int d = id >> 3, c8 = id & 7;
        __half tmp[8];
        #pragma unroll
        for (int e = 0; e < 8; e++)
            tmp[e] = sm[(c8 * 8 + e) * 72 + d];
        *reinterpret_cast<uint4*>(
            &Vt[((size_t)bh * 64 + d) * T_SEQ + jt * 64 + c8 * 8]) =
            *reinterpret_cast<uint4*>(tmp);
    }
}

// ===========================================================================
// FP16 tensor-core GEMM. BM=BN=128, BK=32, 256 threads = 8 warps (2Mx4N).
// Smem: As[128][40] halves, Bs[128][40] halves ([n][k]), 2 stages.
// Fragments via ldmatrix (conflict-free: row-bank = 20r mod 32).
// ===========================================================================
#define GSH 40
#define GT_HALVES (128 * GSH)
#define GEMM_SMEM_BYTES (4 * GT_HALVES * 2)   // 2 stages x (A + B), fp16

__device__ __forceinline__ void gemm_mainloop_f16(
    const __half* __restrict__ A, const __half* __restrict__ Wt,
    __half* As, __half* Bs, int brow, int bcol, float acc[4][4][4])
{
    const int tid  = threadIdx.x;
    const int lane = tid & 31;
    const int wid  = tid >> 5;
    const int warp_m = (wid & 1) * 64;
    const int warp_n = (wid >> 1) * 32;

    auto load_stage = [&](int k0, int buf) {
        __half* as = As + buf * GT_HALVES;
        __half* bs = Bs + buf * GT_HALVES;
        #pragma unroll
        for (int it = 0; it < 2; it++) {
            const int id = tid + it * 256;
            const int r = id >> 2, c8 = id & 3;   // 128 rows x 4 chunks
            cp_async16(&as[r * GSH + c8 * 8],
                       &A[(size_t)(brow + r) * D_MODEL + k0 + c8 * 8]);
        }
        #pragma unroll
        for (int it = 0; it < 2; it++) {
            const int id = tid + it * 256;
            const int r = id >> 2, c8 = id & 3;
            cp_async16(&bs[r * GSH + c8 * 8],
                       &Wt[(size_t)(bcol + r) * D_MODEL + k0 + c8 * 8]);
        }
        cp_commit();
    };

    load_stage(0, 0);

    for (int it = 0; it < 32; it++) {
        if (it + 1 < 32) {
            load_stage((it + 1) * 32, (it + 1) & 1);
            cp_wait<1>();
        } else {
            cp_wait<0>();
        }
        __syncthreads();

        const __half* as = As + (it & 1) * GT_HALVES;
        const __half* bs = Bs + (it & 1) * GT_HALVES;

        // B fragments: one x4 per nf covers all 32 k
        uint32_t bf[4][4];
        #pragma unroll
        for (int nf = 0; nf < 4; nf++) {
            const int row = warp_n + nf * 8 + (lane & 7);
            const int kc  = (lane >> 3) * 8;
            ldsm_x4(bf[nf][0], bf[nf][1], bf[nf][2], bf[nf][3],
                    sptr(&bs[row * GSH + kc]));
        }
        // A fragments: one x4 per (mf, ks)
        #pragma unroll
        for (int ks = 0; ks < 2; ks++) {
            uint32_t af[4][4];
            #pragma unroll
            for (int mf = 0; mf < 4; mf++) {
                const int row = warp_m + mf * 16 + (lane & 15);
                const int kc  = ks * 16 + (lane >> 4) * 8;
                ldsm_x4(af[mf][0], af[mf][1], af[mf][2], af[mf][3],
                        sptr(&as[row * GSH + kc]));
            }
            #pragma unroll
            for (int mf = 0; mf < 4; mf++)
                #pragma unroll
                for (int nf = 0; nf < 4; nf++)
                    mma_f16(acc[mf][nf], af[mf], &bf[nf][ks * 2]);
        }
        __syncthreads();
    }
}

// ---- Fused QKV projection (fp16 out, head layout) ----
__global__ __launch_bounds__(256)
void qkv_gemm_kernel(const __half* __restrict__ A,  const __half* __restrict__ Wt,
                     const float* __restrict__ bq, const float* __restrict__ bk,
                     const float* __restrict__ bv,
                     __half* __restrict__ Qo, __half* __restrict__ Ko,
                     __half* __restrict__ Vo)
{
    extern __shared__ __half smh[];
    __half* As = smh;
    __half* Bs = smh + 2 * GT_HALVES;

    const int wsel = blockIdx.x >> 3;
    const int bcol = (blockIdx.x & 7) * 128;
    const int brow = blockIdx.y * 128;
    const __half* W   = Wt + (size_t)wsel * D_MODEL * D_MODEL;
    const float* bias = (wsel == 0) ? bq : (wsel == 1) ? bk : bv;
    __half* C         = (wsel == 0) ? Qo : (wsel == 1) ? Ko : Vo;
    const float scale = (wsel == 0) ? 0.125f : 1.0f;

    float acc[4][4][4];
    #pragma unroll
    for (int mf = 0; mf < 4; mf++)
        #pragma unroll
        for (int nf = 0; nf < 4; nf++)
            #pragma unroll
            for (int c = 0; c < 4; c++) acc[mf][nf][c] = 0.0f;

    gemm_mainloop_f16(A, W, As, Bs, brow, bcol, acc);

    const int lane = threadIdx.x & 31;
    const int g  = lane >> 2, t4 = lane & 3;
    const int wid = threadIdx.x >> 5;
    const int warp_m = (wid & 1) * 64, warp_n = (wid >> 1) * 32;

    #pragma unroll
    for (int mf = 0; mf < 4; mf++) {
        #pragma unroll
        for (int nf = 0; nf < 4; nf++) {
            const int col = bcol + warp_n + nf * 8 + 2 * t4;
            const float b0 = bias[col], b1 = bias[col + 1];
            #pragma unroll
            for (int rr = 0; rr < 2; rr++) {
                const int row = brow + warp_m + mf * 16 + g + rr * 8;
                const float v0 = (acc[mf][nf][rr * 2 + 0] + b0) * scale;
                const float v1 = (acc[mf][nf][rr * 2 + 1] + b1) * scale;
                const int bb = row >> 11, tt = row & (T_SEQ - 1);
                const int hh = col >> 6,  dd = col & 63;
                __half2 hv = __floats2half2_rn(v0, v1);
                *reinterpret_cast<__half2*>(
                    &C[(((size_t)(bb * N_HEADS + hh) * T_SEQ) + tt) * D_HEAD + dd])
                    = hv;
            }
        }
    }
}

// ---- Output projection (A fp16, output fp32) ----
__global__ __launch_bounds__(256)
void out_gemm_kernel(const __half* __restrict__ A, const __half* __restrict__ Wt,
                     const float* __restrict__ bias, float* __restrict__ C)
{
    extern __shared__ __half smh[];
    __half* As = smh;
    __half* Bs = smh + 2 * GT_HALVES;

    const int bcol = blockIdx.x * 128;
    const int brow = blockIdx.y * 128;

    float acc[4][4][4];
    #pragma unroll
    for (int mf = 0; mf < 4; mf++)
        #pragma unroll
        for (int nf = 0; nf < 4; nf++)
            #pragma unroll
            for (int c = 0; c < 4; c++) acc[mf][nf][c] = 0.0f;

    gemm_mainloop_f16(A, Wt, As, Bs, brow, bcol, acc);

    const int lane = threadIdx.x & 31;
    const int g  = lane >> 2, t4 = lane & 3;
    const int wid = threadIdx.x >> 5;
    const int warp_m = (wid & 1) * 64, warp_n = (wid >> 1) * 32;

    #pragma unroll
    for (int mf = 0; mf < 4; mf++) {
        #pragma unroll
        for (int nf = 0; nf < 4; nf++) {
            const int col = bcol + warp_n + nf * 8 + 2 * t4;
            const float b0 = bias[col], b1 = bias[col + 1];
            #pragma unroll
            for (int rr = 0; rr < 2; rr++) {
                const int row = brow + warp_m + mf * 16 + g + rr * 8;
                float* p = &C[(size_t)row * D_MODEL + col];
                p[0] = acc[mf][nf][rr * 2 + 0] + b0;
                p[1] = acc[mf][nf][rr * 2 + 1] + b1;
            }
        }
    }
}

// ===========================================================================
// FP16 tensor-core flash attention (causal). BQ=BKV=64, 256 thr, 2 CTA/SM.
// Smem tiles [64][72] halves; stats fp32. Fragments via ldmatrix.
// ===========================================================================
#define ASH 72
#define TILE_H (64 * ASH)
#define A_OFF_K  TILE_H
#define A_OFF_V  (2 * TILE_H)
#define A_OFF_S  (3 * TILE_H)
#define A_STAT_F (4 * TILE_H / 2)             // float offset after 4 half-tiles
#define ATTN_SMEM_BYTES (4 * TILE_H * 2 + 448 * 4)

__global__ __launch_bounds__(256, 2)
void attn_mma_kernel(const __half* __restrict__ Qh,
                     const __half* __restrict__ Kh,
                     const __half* __restrict__ Vth,
                     __half* __restrict__ out)
{
    extern __shared__ __half smh[];
    __half* Qs = smh;
    __half* Ks = smh + A_OFF_K;
    __half* Vs = smh + A_OFF_V;               // [d][j]
    __half* Ss = smh + A_OFF_S;               // P [q][j]
    float* stat  = reinterpret_cast<float*>(smh) + A_STAT_F;
    float* row_m = stat;                      // 64
    float* row_l = stat + 64;
    float* row_s = stat + 128;
    float* pmax  = stat + 192;                // [64][2]
    float* psum  = stat + 320;                // [64][2]

    const int tid  = threadIdx.x;
    const int lane = tid & 31;
    const int wid  = tid >> 5;
    const int g    = lane >> 2;
    const int t4   = lane & 3;
    const int wr   = wid >> 1;
    const int wc   = wid & 1;

    const int bx = gridDim.x - 1 - blockIdx.x;   // heavy blocks first
    const int bh = blockIdx.y;
    const int b  = bh >> 4;
    const int h  = bh & 15;
    const int q0 = bx * 64;

    const __half* Qb = Qh  + (size_t)bh * T_SEQ * D_HEAD;
    const __half* Kb = Kh  + (size_t)bh * T_SEQ * D_HEAD;
    const __half* Vb = Vth + (size_t)bh * D_HEAD * T_SEQ;   // [d][t]

    auto load_q = [&]() {
        #pragma unroll
        for (int it = 0; it < 2; it++) {
            const int id = tid + it * 256;
            const int r = id >> 3, c8 = id & 7;
            cp_async16(&Qs[r * ASH + c8 * 8], &Qb[(size_t)(q0 + r) * 64 + c8 * 8]);
        }
    };
    auto load_k = [&](int k0) {
        #pragma unroll
        for (int it = 0; it < 2; it++) {
            const int id = tid + it * 256;
            const int r = id >> 3, c8 = id & 7;
            cp_async16(&Ks[r * ASH + c8 * 8], &Kb[(size_t)(k0 + r) * 64 + c8 * 8]);
        }
    };
    auto load_v = [&](int k0) {
        #pragma unroll
        for (int it = 0; it < 2; it++) {
            const int id = tid + it * 256;
            const int r = id >> 3, c8 = id & 7;   // r = d
            cp_async16(&Vs[r * ASH + c8 * 8],
                       &Vb[(size_t)r * T_SEQ + k0 + c8 * 8]);
        }
    };

    load_q();
    load_k(0);
    cp_commit();
    load_v(0);
    cp_commit();

    if (tid < 64) { row_m[tid] = -1e30f; row_l[tid] = 0.0f; }

    float o_acc[4][4];
    #pragma unroll
    for (int nf = 0; nf < 4; nf++)
        #pragma unroll
        for (int c = 0; c < 4; c++) o_acc[nf][c] = 0.0f;

    const int r0 = wr * 16 + g;
    const int r1 = r0 + 8;
    const int nkt = bx + 1;

    for (int kt = 0; kt < nkt; kt++) {
        const bool have_next = (kt + 1 < nkt);

        cp_wait<1>();
        __syncthreads();

        // ---- S = Q K^T : 4 k-steps of 16 ----
        float s_acc[4][4];
        #pragma unroll
        for (int nf = 0; nf < 4; nf++)
            #pragma unroll
            for (int c = 0; c < 4; c++) s_acc[nf][c] = 0.0f;

        // K fragments: 2 x4 per nf (each covers 32 k)
        uint32_t kf[4][8];
        #pragma unroll
        for (int nf = 0; nf < 4; nf++) {
            const int row = wc * 32 + nf * 8 + (lane & 7);
            const int kc  = (lane >> 3) * 8;
            ldsm_x4(kf[nf][0], kf[nf][1], kf[nf][2], kf[nf][3],
                    sptr(&Ks[row * ASH + kc]));
            ldsm_x4(kf[nf][4], kf[nf][5], kf[nf][6], kf[nf][7],
                    sptr(&Ks[row * ASH + 32 + kc]));
        }
        #pragma unroll
        for (int ks = 0; ks < 4; ks++) {
            uint32_t af[4];
            {
                const int row = wr * 16 + (lane & 15);
                const int kc  = ks * 16 + (lane >> 4) * 8;
                ldsm_x4(af[0], af[1], af[2], af[3], sptr(&Qs[row * ASH + kc]));
            }
            #pragma unroll
            for (int nf = 0; nf < 4; nf++)
                mma_f16(s_acc[nf], af, &kf[nf][ks * 2]);
        }

        // ---- causal mask (diagonal tile only) ----
        if (kt == bx) {
            #pragma unroll
            for (int nf = 0; nf < 4; nf++) {
                const int c0 = wc * 32 + nf * 8 + t4 * 2;
                if (c0     > r0) s_acc[nf][0] = -1e30f;
                if (c0 + 1 > r0) s_acc[nf][1] = -1e30f;
                if (c0     > r1) s_acc[nf][2] = -1e30f;
                if (c0 + 1 > r1) s_acc[nf][3] = -1e30f;
            }
        }

        // ---- partial row max ----
        {
            float pm0 = -1e30f, pm1 = -1e30f;
            #pragma unroll
            for (int nf = 0; nf < 4; nf++) {
                pm0 = fmaxf(pm0, fmaxf(s_acc[nf][0], s_acc[nf][1]));
                pm1 = fmaxf(pm1, fmaxf(s_acc[nf][2], s_acc[nf][3]));
            }
            pm0 = fmaxf(pm0, __shfl_xor_sync(0xffffffffu, pm0, 1));
            pm0 = fmaxf(pm0, __shfl_xor_sync(0xffffffffu, pm0, 2));
            pm1 = fmaxf(pm1, __shfl_xor_sync(0xffffffffu, pm1, 1));
            pm1 = fmaxf(pm1, __shfl_xor_sync(0xffffffffu, pm1, 2));
            if (t4 == 0) {
                pmax[r0 * 2 + wc] = pm0;
                pmax[r1 * 2 + wc] = pm1;
            }
        }
        __syncthreads();          // pmax ready; Ks free

        if (have_next) { load_k((kt + 1) * 64); cp_commit(); }

        if (tid < 64) {
            const float m_old = row_m[tid];
            const float mn = fmaxf(m_old, fmaxf(pmax[tid * 2], pmax[tid * 2 + 1]));
            row_m[tid] = mn;
            row_s[tid] = __expf(m_old - mn);
        }
        __syncthreads();          // row_m / row_s ready

        // ---- exp, P -> smem (fp16), partial sums, O rescale ----
        {
            const float mn0 = row_m[r0], mn1 = row_m[r1];
            float sum0 = 0.0f, sum1 = 0.0f;
            #pragma unroll
            for (int nf = 0; nf < 4; nf++) {
                const int col = wc * 32 + nf * 8 + 2 * t4;
                const float p00 = __expf(s_acc[nf][0] - mn0);
                const float p01 = __expf(s_acc[nf][1] - mn0);
                const float p10 = __expf(s_acc[nf][2] - mn1);
                const float p11 = __expf(s_acc[nf][3] - mn1);
                sum0 += p00 + p01;
                sum1 += p10 + p11;
                *reinterpret_cast<__half2*>(&Ss[r0 * ASH + col]) =
                    __floats2half2_rn(p00, p01);
                *reinterpret_cast<__half2*>(&Ss[r1 * ASH + col]) =
                    __floats2half2_rn(p10, p11);
            }
            sum0 += __shfl_xor_sync(0xffffffffu, sum0, 1);
            sum0 += __shfl_xor_sync(0xffffffffu, sum0, 2);
            sum1 += __shfl_xor_sync(0xffffffffu, sum1, 1);
            sum1 += __shfl_xor_sync(0xffffffffu, sum1, 2);
            if (t4 == 0) {
                psum[r0 * 2 + wc] = sum0;
                psum[r1 * 2 + wc] = sum1;
            }
            const float sc0 = row_s[r0], sc1 = row_s[r1];
            #pragma unroll
            for (int nf = 0; nf < 4; nf++) {
                o_acc[nf][0] *= sc0; o_acc[nf][1] *= sc0;
                o_acc[nf][2] *= sc1; o_acc[nf][3] *= sc1;
            }
        }

        if (have_next) cp_wait<1>(); else cp_wait<0>();   // V(kt) landed
        __syncthreads();          // Ss + psum ready, Vs visible

        if (tid < 64)
            row_l[tid] = row_l[tid] * row_s[tid] + psum[tid * 2] + psum[tid * 2 + 1];

        // ---- O += P V ----
        uint32_t vf[4][8];
        #pragma unroll
        for (int nf = 0; nf < 4; nf++) {
            const int row = wc * 32 + nf * 8 + (lane & 7);   // row = d
            const int kc  = (lane >> 3) * 8;
            ldsm_x4(vf[nf][0], vf[nf][1], vf[nf][2], vf[nf][3],
                    sptr(&Vs[row * ASH + kc]));
            ldsm_x4(vf[nf][4], vf[nf][5], vf[nf][6], vf[nf][7],
                    sptr(&Vs[row * ASH + 32 + kc]));
        }
        #pragma unroll
        for (int ks = 0; ks < 4; ks++) {
            uint32_t af[4];
            {
                const int row = wr * 16 + (lane & 15);
                const int kc  = ks * 16 + (lane >> 4) * 8;
                ldsm_x4(af[0], af[1], af[2], af[3], sptr(&Ss[row * ASH + kc]));
            }
            #pragma unroll
            for (int nf = 0; nf < 4; nf++)
                mma_f16(o_acc[nf], af, &vf[nf][ks * 2]);
        }
        __syncthreads();          // Vs free

        if (have_next) { load_v((kt + 1) * 64); cp_commit(); }
    }

    // ---- normalize + store fp16 [B, T, D_MODEL] ----
    const float il0 = 1.0f / row_l[r0];
    const float il1 = 1.0f / row_l[r1];
    #pragma unroll
    for (int nf = 0; nf < 4; nf++) {
        const int d = wc * 32 + nf * 8 + 2 * t4;
        __half2* p0 = reinterpret_cast<__half2*>(
            &out[((size_t)(b * T_SEQ + q0 + r0)) * D_MODEL + h * 64 + d]);
        __half2* p1 = reinterpret_cast<__half2*>(
            &out[((size_t)(b * T_SEQ + q0 + r1)) * D_MODEL + h * 64 + d]);
        *p0 = __floats2half2_rn(o_acc[nf][0] * il0, o_acc[nf][1] * il0);
        *p1 = __floats2half2_rn(o_acc[nf][2] * il1, o_acc[nf][3] * il1);
    }
}

// ---------------------------------------------------------------------------
extern "C" void kernel_launch(void* const* d_in, const int* in_sizes, int n_in,
                              void* d_out, int out_size)
{
    const float* x  = (const float*)d_in[0];
    const float* Wq = (const float*)d_in[1];
    const float* bq = (const float*)d_in[2];
    const float* Wk = (const float*)d_in[3];
    const float* bk = (const float*)d_in[4];
    const float* Wv = (const float*)d_in[5];
    const float* bv = (const float*)d_in[6];
    const float* Wo = (const float*)d_in[7];
    const float* bo = (const float*)d_in[8];
    float* out = (float*)d_out;

    __half *Q, *K, *V, *Vt, *attn, *xh, *Wt;
    cudaGetSymbolAddress((void**)&Q, g_Q);
    cudaGetSymbolAddress((void**)&K, g_K);
    cudaGetSymbolAddress((void**)&V, g_V);
    cudaGetSymbolAddress((void**)&Vt, g_Vt);
    cudaGetSymbolAddress((void**)&attn, g_attn);
    cudaGetSymbolAddress((void**)&xh, g_xh);
    cudaGetSymbolAddress((void**)&Wt, g_Wt);
    __half* Wot = Wt + (size_t)3 * D_MODEL * D_MODEL;

    cudaFuncSetAttribute(qkv_gemm_kernel,
                         cudaFuncAttributeMaxDynamicSharedMemorySize,
                         GEMM_SMEM_BYTES);
    cudaFuncSetAttribute(out_gemm_kernel,
                         cudaFuncAttributeMaxDynamicSharedMemorySize,
                         GEMM_SMEM_BYTES);
    cudaFuncSetAttribute(attn_mma_kernel,
                         cudaFuncAttributeMaxDynamicSharedMemorySize,
                         ATTN_SMEM_BYTES);

    convert_x_kernel<<<592, 256>>>(x, xh, M_ROWS * D_MODEL / 4);
    transpose_w_kernel<<<dim3(32, 32, 4), 256>>>(Wq, Wk, Wv, Wo, Wt);

    qkv_gemm_kernel<<<dim3(24, 32), 256, GEMM_SMEM_BYTES>>>(
        xh, Wt, bq, bk, bv, Q, K, V);

    transpose_v_kernel<<<dim3(T_SEQ / 64, B_SIZE * N_HEADS), 256>>>(V, Vt);

    attn_mma_kernel<<<dim3(T_SEQ / 64, B_SIZE * N_HEADS), 256,
                      ATTN_SMEM_BYTES>>>(Q, K, Vt, attn);

    out_gemm_kernel<<<dim3(8, 32), 256, GEMM_SMEM_BYTES>>>(attn, Wot, bo, out);
}

// round 11
// speedup vs baseline: 2.2013x; 1.0849x over previous
#include <cuda_runtime.h>
#include <cuda_fp16.h>
#include <cstdint>

#define D_MODEL 1024
#define N_HEADS 16
#define D_HEAD  64
#define B_SIZE  2
#define T_SEQ   2048
#define M_ROWS  (B_SIZE * T_SEQ)   // 4096

__device__ __half g_Q[M_ROWS * D_MODEL];      // [B,H,T,64], scaled 0.125
__device__ __half g_K[M_ROWS * D_MODEL];      // [B,H,T,64]
__device__ __half g_Vt[M_ROWS * D_MODEL];     // [B,H,64,T]
__device__ __half g_attn[M_ROWS * D_MODEL];   // [B,T,1024]
__device__ __half g_xh[M_ROWS * D_MODEL];     // x as fp16
__device__ __half g_Wt[4][D_MODEL * D_MODEL]; // W^T: [n][k], fp16

// ===========================================================================
__device__ __forceinline__ uint32_t sptr(const void* p) {
    return (uint32_t)__cvta_generic_to_shared(p);
}
__device__ __forceinline__ void ldsm_x4(uint32_t& r0, uint32_t& r1,
                                        uint32_t& r2, uint32_t& r3,
                                        uint32_t addr) {
    asm volatile("ldmatrix.sync.aligned.m8n8.x4.shared.b16 {%0,%1,%2,%3},[%4];"
                 : "=r"(r0), "=r"(r1), "=r"(r2), "=r"(r3) : "r"(addr));
}
__device__ __forceinline__ void mma_f16(float c[4], const uint32_t a[4],
                                        const uint32_t b[2]) {
    asm volatile(
        "mma.sync.aligned.m16n8k16.row.col.f32.f16.f16.f32 "
        "{%0,%1,%2,%3}, {%4,%5,%6,%7}, {%8,%9}, {%0,%1,%2,%3};"
        : "+f"(c[0]), "+f"(c[1]), "+f"(c[2]), "+f"(c[3])
        : "r"(a[0]), "r"(a[1]), "r"(a[2]), "r"(a[3]), "r"(b[0]), "r"(b[1]));
}
__device__ __forceinline__ void cp_async16(void* dst_smem, const void* src) {
    uint32_t d = (uint32_t)__cvta_generic_to_shared(dst_smem);
    asm volatile("cp.async.cg.shared.global [%0], [%1], 16;" :: "r"(d), "l"(src));
}
__device__ __forceinline__ void cp_commit() { asm volatile("cp.async.commit_group;"); }
template <int N>
__device__ __forceinline__ void cp_wait() {
    asm volatile("cp.async.wait_group %0;" :: "n"(N));
}
__device__ __forceinline__ uint32_t packh2(float a, float b) {
    __half2 h = __floats2half2_rn(a, b);
    return *reinterpret_cast<uint32_t*>(&h);
}

// ===========================================================================
// Prepass 1: x (fp32) -> fp16
// ===========================================================================
__global__ void convert_x_kernel(const float* __restrict__ src,
                                 __half* __restrict__ dst, int n4)
{
    int i = blockIdx.x * blockDim.x + threadIdx.x;
    const int stride = gridDim.x * blockDim.x;
    for (; i < n4; i += stride) {
        float4 v = reinterpret_cast<const float4*>(src)[i];
        __half2 h0 = __floats2half2_rn(v.x, v.y);
        __half2 h1 = __floats2half2_rn(v.z, v.w);
        uint2 o = make_uint2(*(uint32_t*)&h0, *(uint32_t*)&h1);
        reinterpret_cast<uint2*>(dst)[i] = o;
    }
}

// ===========================================================================
// Prepass 2: W[k][n] fp32 -> Wt[n][k] fp16. 32x32 tile transpose.
// ===========================================================================
__global__ void transpose_w_kernel(const float* __restrict__ Wq,
                                   const float* __restrict__ Wk,
                                   const float* __restrict__ Wv,
                                   const float* __restrict__ Wo,
                                   __half* __restrict__ dst)
{
    __shared__ float sm[32][33];
    const int z = blockIdx.z;
    const float* W = (z == 0) ? Wq : (z == 1) ? Wk : (z == 2) ? Wv : Wo;
    __half* out = dst + (size_t)z * D_MODEL * D_MODEL;

    const int n0 = blockIdx.x * 32;
    const int k0 = blockIdx.y * 32;
    const int t  = threadIdx.x;
    {
        const int kl = t >> 3;
        const int nc = t & 7;
        float4 v = *reinterpret_cast<const float4*>(
            &W[(size_t)(k0 + kl) * D_MODEL + n0 + nc * 4]);
        sm[kl][nc * 4 + 0] = v.x;
        sm[kl][nc * 4 + 1] = v.y;
        sm[kl][nc * 4 + 2] = v.z;
        sm[kl][nc * 4 + 3] = v.w;
    }
    __syncthreads();
    {
        const int nl = t >> 3;
        const int kc = t & 7;
        __half2 h0 = __floats2half2_rn(sm[kc * 4 + 0][nl], sm[kc * 4 + 1][nl]);
        __half2 h1 = __floats2half2_rn(sm[kc * 4 + 2][nl], sm[kc * 4 + 3][nl]);
        uint2 o = make_uint2(*(uint32_t*)&h0, *(uint32_t*)&h1);
        *reinterpret_cast<uint2*>(
            &out[(size_t)(n0 + nl) * D_MODEL + k0 + kc * 4]) = o;
    }
}

// ===========================================================================
// FP16 GEMM, 3-stage cp.async pipeline (1 sync per K-tile).
// BM=BN=128, BK=32, 256 threads = 8 warps (2Mx4N).
// ===========================================================================
#define GSH 40
#define GT_HALVES (128 * GSH)
#define GEMM_SMEM_BYTES (6 * GT_HALVES * 2)   // 3 stages x (A + B), fp16

__device__ __forceinline__ void gemm_mainloop_f16(
    const __half* __restrict__ A, const __half* __restrict__ Wt,
    __half* As, __half* Bs, int brow, int bcol, float acc[4][4][4])
{
    const int tid  = threadIdx.x;
    const int lane = tid & 31;
    const int wid  = tid >> 5;
    const int warp_m = (wid & 1) * 64;
    const int warp_n = (wid >> 1) * 32;

    auto load_stage = [&](int k0, int buf) {
        __half* as = As + buf * GT_HALVES;
        __half* bs = Bs + buf * GT_HALVES;
        #pragma unroll
        for (int it = 0; it < 2; it++) {
            const int id = tid + it * 256;
            const int r = id >> 2, c8 = id & 3;
            cp_async16(&as[r * GSH + c8 * 8],
                       &A[(size_t)(brow + r) * D_MODEL + k0 + c8 * 8]);
        }
        #pragma unroll
        for (int it = 0; it < 2; it++) {
            const int id = tid + it * 256;
            const int r = id >> 2, c8 = id & 3;
            cp_async16(&bs[r * GSH + c8 * 8],
                       &Wt[(size_t)(bcol + r) * D_MODEL + k0 + c8 * 8]);
        }
        cp_commit();
    };

    load_stage(0, 0);
    load_stage(32, 1);

    for (int it = 0; it < 32; it++) {
        if (it + 1 < 32) cp_wait<1>(); else cp_wait<0>();
        __syncthreads();
        if (it + 2 < 32) load_stage((it + 2) * 32, (it + 2) % 3);

        const __half* as = As + (it % 3) * GT_HALVES;
        const __half* bs = Bs + (it % 3) * GT_HALVES;

        uint32_t bf[4][4];
        #pragma unroll
        for (int nf = 0; nf < 4; nf++) {
            const int row = warp_n + nf * 8 + (lane & 7);
            const int kc  = (lane >> 3) * 8;
            ldsm_x4(bf[nf][0], bf[nf][1], bf[nf][2], bf[nf][3],
                    sptr(&bs[row * GSH + kc]));
        }
        #pragma unroll
        for (int ks = 0; ks < 2; ks++) {
            uint32_t af[4][4];
            #pragma unroll
            for (int mf = 0; mf < 4; mf++) {
                const int row = warp_m + mf * 16 + (lane & 15);
                const int kc  = ks * 16 + (lane >> 4) * 8;
                ldsm_x4(af[mf][0], af[mf][1], af[mf][2], af[mf][3],
                        sptr(&as[row * GSH + kc]));
            }
            #pragma unroll
            for (int mf = 0; mf < 4; mf++)
                #pragma unroll
                for (int nf = 0; nf < 4; nf++)
                    mma_f16(acc[mf][nf], af[mf], &bf[nf][ks * 2]);
        }
    }
    __syncthreads();
}

// ---- Fused QKV projection: Q/K head layout; V written transposed [d][t] ----
__global__ __launch_bounds__(256)
void qkv_gemm_kernel(const __half* __restrict__ A,  const __half* __restrict__ Wt,
                     const float* __restrict__ bq, const float* __restrict__ bk,
                     const float* __restrict__ bv,
                     __half* __restrict__ Qo, __half* __restrict__ Ko,
                     __half* __restrict__ Vto)
{
    extern __shared__ __half smh[];
    __half* As = smh;
    __half* Bs = smh + 3 * GT_HALVES;

    const int wsel = blockIdx.x >> 3;
    const int bcol = (blockIdx.x & 7) * 128;
    const int brow = blockIdx.y * 128;
    const __half* W   = Wt + (size_t)wsel * D_MODEL * D_MODEL;
    const float* bias = (wsel == 0) ? bq : (wsel == 1) ? bk : bv;
    const float scale = (wsel == 0) ? 0.125f : 1.0f;

    float acc[4][4][4];
    #pragma unroll
    for (int mf = 0; mf < 4; mf++)
        #pragma unroll
        for (int nf = 0; nf < 4; nf++)
            #pragma unroll
            for (int c = 0; c < 4; c++) acc[mf][nf][c] = 0.0f;

    gemm_mainloop_f16(A, W, As, Bs, brow, bcol, acc);

    const int lane = threadIdx.x & 31;
    const int g  = lane >> 2, t4 = lane & 3;
    const int wid = threadIdx.x >> 5;
    const int warp_m = (wid & 1) * 64, warp_n = (wid >> 1) * 32;

    #pragma unroll
    for (int mf = 0; mf < 4; mf++) {
        #pragma unroll
        for (int nf = 0; nf < 4; nf++) {
            const int col = bcol + warp_n + nf * 8 + 2 * t4;
            const float b0 = bias[col], b1 = bias[col + 1];
            #pragma unroll
            for (int rr = 0; rr < 2; rr++) {
                const int row = brow + warp_m + mf * 16 + g + rr * 8;
                const float v0 = (acc[mf][nf][rr * 2 + 0] + b0) * scale;
                const float v1 = (acc[mf][nf][rr * 2 + 1] + b1) * scale;
                const int bb = row >> 11, tt = row & (T_SEQ - 1);
                const int hh = col >> 6,  dd = col & 63;
                const int bh = bb * N_HEADS + hh;
                if (wsel == 2) {
                    Vto[((size_t)bh * 64 + dd)     * T_SEQ + tt] = __float2half_rn(v0);
                    Vto[((size_t)bh * 64 + dd + 1) * T_SEQ + tt] = __float2half_rn(v1);
                } else {
                    __half* C = (wsel == 0) ? Qo : Ko;
                    *reinterpret_cast<__half2*>(
                        &C[((size_t)bh * T_SEQ + tt) * D_HEAD + dd]) =
                        __floats2half2_rn(v0, v1);
                }
            }
        }
    }
}

// ---- Output projection (A fp16, output fp32) ----
__global__ __launch_bounds__(256)
void out_gemm_kernel(const __half* __restrict__ A, const __half* __restrict__ Wt,
                     const float* __restrict__ bias, float* __restrict__ C)
{
    extern __shared__ __half smh[];
    __half* As = smh;
    __half* Bs = smh + 3 * GT_HALVES;

    const int bcol = blockIdx.x * 128;
    const int brow = blockIdx.y * 128;

    float acc[4][4][4];
    #pragma unroll
    for (int mf = 0; mf < 4; mf++)
        #pragma unroll
        for (int nf = 0; nf < 4; nf++)
            #pragma unroll
            for (int c = 0; c < 4; c++) acc[mf][nf][c] = 0.0f;

    gemm_mainloop_f16(A, Wt, As, Bs, brow, bcol, acc);

    const int lane = threadIdx.x & 31;
    const int g  = lane >> 2, t4 = lane & 3;
    const int wid = threadIdx.x >> 5;
    const int warp_m = (wid & 1) * 64, warp_n = (wid >> 1) * 32;

    #pragma unroll
    for (int mf = 0; mf < 4; mf++) {
        #pragma unroll
        for (int nf = 0; nf < 4; nf++) {
            const int col = bcol + warp_n + nf * 8 + 2 * t4;
            const float b0 = bias[col], b1 = bias[col + 1];
            #pragma unroll
            for (int rr = 0; rr < 2; rr++) {
                const int row = brow + warp_m + mf * 16 + g + rr * 8;
                float* p = &C[(size_t)row * D_MODEL + col];
                p[0] = acc[mf][nf][rr * 2 + 0] + b0;
                p[1] = acc[mf][nf][rr * 2 + 1] + b1;
            }
        }
    }
}

// ===========================================================================
// FP16 flash attention (causal). BQ=128, BKV=64, 256 thr, 2 CTA/SM.
// Each warp owns 16 full rows x 64 cols -> softmax stats in registers,
// P converted register-direct to PV A-fragments (no smem staging).
// One __syncthreads per KV tile. 3-buffer K/V ring (one cp group per tile).
// ===========================================================================
#define ASH 72
#define QT_H (128 * ASH)                       // 9216 halves
#define KT_H (64 * ASH)                        // 4608 halves
#define ATTN_SMEM_BYTES ((QT_H + 6 * KT_H) * 2)  // 73728 B

__global__ __launch_bounds__(256, 2)
void attn_mma_kernel(const __half* __restrict__ Qh,
                     const __half* __restrict__ Kh,
                     const __half* __restrict__ Vth,
                     __half* __restrict__ out)
{
    extern __shared__ __half smh[];
    __half* Qs  = smh;
    __half* Kb0 = smh + QT_H;
    __half* Vb0 = smh + QT_H + 3 * KT_H;

    const int tid  = threadIdx.x;
    const int lane = tid & 31;
    const int wr   = tid >> 5;                 // warp = 16-row group (0..7)
    const int g    = lane >> 2;
    const int t4   = lane & 3;

    const int bx = gridDim.x - 1 - blockIdx.x; // heavy blocks first
    const int bh = blockIdx.y;
    const int b  = bh >> 4;
    const int h  = bh & 15;
    const int q0 = bx * 128;

    const __half* Qb = Qh  + (size_t)bh * T_SEQ * D_HEAD;
    const __half* Kb = Kh  + (size_t)bh * T_SEQ * D_HEAD;
    const __half* Vb = Vth + (size_t)bh * D_HEAD * T_SEQ;   // [d][t]

    auto load_q = [&]() {
        #pragma unroll
        for (int it = 0; it < 4; it++) {
            const int id = tid + it * 256;
            const int r = id >> 3, c8 = id & 7;
            cp_async16(&Qs[r * ASH + c8 * 8], &Qb[(size_t)(q0 + r) * 64 + c8 * 8]);
        }
    };
    auto load_k = [&](int k0, int buf) {
        __half* d = Kb0 + buf * KT_H;
        #pragma unroll
        for (int it = 0; it < 2; it++) {
            const int id = tid + it * 256;
            const int r = id >> 3, c8 = id & 7;
            cp_async16(&d[r * ASH + c8 * 8], &Kb[(size_t)(k0 + r) * 64 + c8 * 8]);
        }
    };
    auto load_v = [&](int k0, int buf) {
        __half* dv = Vb0 + buf * KT_H;
        #pragma unroll
        for (int it = 0; it < 2; it++) {
            const int id = tid + it * 256;
            const int r = id >> 3, c8 = id & 7;   // r = d
            cp_async16(&dv[r * ASH + c8 * 8], &Vb[(size_t)r * T_SEQ + k0 + c8 * 8]);
        }
    };

    const int nkt = 2 * bx + 2;
    load_q(); load_k(0, 0); load_v(0, 0); cp_commit();
    if (nkt > 1) { load_k(64, 1); load_v(64, 1); cp_commit(); }

    float m0 = -1e30f, m1 = -1e30f, l0 = 0.0f, l1 = 0.0f;
    float o_acc[8][4];
    #pragma unroll
    for (int nf = 0; nf < 8; nf++)
        #pragma unroll
        for (int c = 0; c < 4; c++) o_acc[nf][c] = 0.0f;

    const int r0 = wr * 16 + g;
    const int r1 = r0 + 8;

    for (int kt = 0; kt < nkt; kt++) {
        if (kt + 1 < nkt) cp_wait<1>(); else cp_wait<0>();
        __syncthreads();
        if (kt + 2 < nkt) {
            load_k((kt + 2) * 64, (kt + 2) % 3);
            load_v((kt + 2) * 64, (kt + 2) % 3);
            cp_commit();
        }
        const __half* Ks = Kb0 + (kt % 3) * KT_H;
        const __half* Vs = Vb0 + (kt % 3) * KT_H;

        // ---- S = Q K^T : warp tile 16x64 ----
        float s[8][4];
        #pragma unroll
        for (int nf = 0; nf < 8; nf++)
            #pragma unroll
            for (int c = 0; c < 4; c++) s[nf][c] = 0.0f;

        #pragma unroll
        for (int ks = 0; ks < 4; ks++) {
            uint32_t qf[4];
            ldsm_x4(qf[0], qf[1], qf[2], qf[3],
                    sptr(&Qs[(wr * 16 + (lane & 15)) * ASH
                             + ks * 16 + (lane >> 4) * 8]));
            #pragma unroll
            for (int nh = 0; nh < 2; nh++) {
                const int rr = nh * 32 + (lane >> 3) * 8 + (lane & 7);
                uint32_t blo[4], bhi[4];
                ldsm_x4(blo[0], blo[1], blo[2], blo[3],
                        sptr(&Ks[rr * ASH + ks * 16]));
                ldsm_x4(bhi[0], bhi[1], bhi[2], bhi[3],
                        sptr(&Ks[rr * ASH + ks * 16 + 8]));
                #pragma unroll
                for (int m = 0; m < 4; m++) {
                    uint32_t bfr[2] = {blo[m], bhi[m]};
                    mma_f16(s[nh * 4 + m], qf, bfr);
                }
            }
        }

        // ---- causal mask (last two tiles) ----
        if (kt >= nkt - 2) {
            const int k0 = kt * 64;
            #pragma unroll
            for (int nf = 0; nf < 8; nf++) {
                const int c0 = k0 + nf * 8 + 2 * t4;
                if (c0     > q0 + r0) s[nf][0] = -1e30f;
                if (c0 + 1 > q0 + r0) s[nf][1] = -1e30f;
                if (c0     > q0 + r1) s[nf][2] = -1e30f;
                if (c0 + 1 > q0 + r1) s[nf][3] = -1e30f;
            }
        }

        // ---- register softmax: quad shfl covers full 64-col rows ----
        float pm0 = -1e30f, pm1 = -1e30f;
        #pragma unroll
        for (int nf = 0; nf < 8; nf++) {
            pm0 = fmaxf(pm0, fmaxf(s[nf][0], s[nf][1]));
            pm1 = fmaxf(pm1, fmaxf(s[nf][2], s[nf][3]));
        }
        pm0 = fmaxf(pm0, __shfl_xor_sync(0xffffffffu, pm0, 1));
        pm0 = fmaxf(pm0, __shfl_xor_sync(0xffffffffu, pm0, 2));
        pm1 = fmaxf(pm1, __shfl_xor_sync(0xffffffffu, pm1, 1));
        pm1 = fmaxf(pm1, __shfl_xor_sync(0xffffffffu, pm1, 2));

        const float mn0 = fmaxf(m0, pm0);
        const float mn1 = fmaxf(m1, pm1);
        const float sc0 = __expf(m0 - mn0);
        const float sc1 = __expf(m1 - mn1);
        m0 = mn0; m1 = mn1;

        float sum0 = 0.0f, sum1 = 0.0f;
        uint32_t pa[4][4];                       // PV A-frags, register-direct
        #pragma unroll
        for (int m = 0; m < 4; m++) {
            #pragma unroll
            for (int j = 0; j < 2; j++) {
                const int nf = 2 * m + j;
                const float e0 = __expf(s[nf][0] - mn0);
                const float e1 = __expf(s[nf][1] - mn0);
                const float e2 = __expf(s[nf][2] - mn1);
                const float e3 = __expf(s[nf][3] - mn1);
                sum0 += e0 + e1;
                sum1 += e2 + e3;
                pa[m][j * 2 + 0] = packh2(e0, e1);   // row g,   k-lo/hi
                pa[m][j * 2 + 1] = packh2(e2, e3);   // row g+8
            }
        }
        sum0 += __shfl_xor_sync(0xffffffffu, sum0, 1);
        sum0 += __shfl_xor_sync(0xffffffffu, sum0, 2);
        sum1 += __shfl_xor_sync(0xffffffffu, sum1, 1);
        sum1 += __shfl_xor_sync(0xffffffffu, sum1, 2);
        l0 = l0 * sc0 + sum0;
        l1 = l1 * sc1 + sum1;

        #pragma unroll
        for (int nf = 0; nf < 8; nf++) {
            o_acc[nf][0] *= sc0; o_acc[nf][1] *= sc0;
            o_acc[nf][2] *= sc1; o_acc[nf][3] *= sc1;
        }

        // ---- O += P V : k = j (4 blocks of 16), n = d (8 frags) ----
        #pragma unroll
        for (int m = 0; m < 4; m++) {
            #pragma unroll
            for (int nh = 0; nh < 2; nh++) {
                const int rr = nh * 32 + (lane >> 3) * 8 + (lane & 7);  // d rows
                uint32_t blo[4], bhi[4];
                ldsm_x4(blo[0], blo[1], blo[2], blo[3],
                        sptr(&Vs[rr * ASH + m * 16]));
                ldsm_x4(bhi[0], bhi[1], bhi[2], bhi[3],
                        sptr(&Vs[rr * ASH + m * 16 + 8]));
                #pragma unroll
                for (int mm = 0; mm < 4; mm++) {
                    uint32_t bfr[2] = {blo[mm], bhi[mm]};
                    mma_f16(o_acc[nh * 4 + mm], pa[m], bfr);
                }
            }
        }
    }

    // ---- normalize + store fp16 [B, T, D_MODEL] ----
    const float il0 = 1.0f / l0;
    const float il1 = 1.0f / l1;
    #pragma unroll
    for (int nf = 0; nf < 8; nf++) {
        const int d = nf * 8 + 2 * t4;
        *reinterpret_cast<__half2*>(
            &out[((size_t)(b * T_SEQ + q0 + r0)) * D_MODEL + h * 64 + d]) =
            __floats2half2_rn(o_acc[nf][0] * il0, o_acc[nf][1] * il0);
        *reinterpret_cast<__half2*>(
            &out[((size_t)(b * T_SEQ + q0 + r1)) * D_MODEL + h * 64 + d]) =
            __floats2half2_rn(o_acc[nf][2] * il1, o_acc[nf][3] * il1);
    }
}

// ---------------------------------------------------------------------------
extern "C" void kernel_launch(void* const* d_in, const int* in_sizes, int n_in,
                              void* d_out, int out_size)
{
    const float* x  = (const float*)d_in[0];
    const float* Wq = (const float*)d_in[1];
    const float* bq = (const float*)d_in[2];
    const float* Wk = (const float*)d_in[3];
    const float* bk = (const float*)d_in[4];
    const float* Wv = (const float*)d_in[5];
    const float* bv = (const float*)d_in[6];
    const float* Wo = (const float*)d_in[7];
    const float* bo = (const float*)d_in[8];
    float* out = (float*)d_out;

    __half *Q, *K, *Vt, *attn, *xh, *Wt;
    cudaGetSymbolAddress((void**)&Q, g_Q);
    cudaGetSymbolAddress((void**)&K, g_K);
    cudaGetSymbolAddress((void**)&Vt, g_Vt);
    cudaGetSymbolAddress((void**)&attn, g_attn);
    cudaGetSymbolAddress((void**)&xh, g_xh);
    cudaGetSymbolAddress((void**)&Wt, g_Wt);
    __half* Wot = Wt + (size_t)3 * D_MODEL * D_MODEL;

    cudaFuncSetAttribute(qkv_gemm_kernel,
                         cudaFuncAttributeMaxDynamicSharedMemorySize,
                         GEMM_SMEM_BYTES);
    cudaFuncSetAttribute(out_gemm_kernel,
                         cudaFuncAttributeMaxDynamicSharedMemorySize,
                         GEMM_SMEM_BYTES);
    cudaFuncSetAttribute(attn_mma_kernel,
                         cudaFuncAttributeMaxDynamicSharedMemorySize,
                         ATTN_SMEM_BYTES);

    convert_x_kernel<<<592, 256>>>(x, xh, M_ROWS * D_MODEL / 4);
    transpose_w_kernel<<<dim3(32, 32, 4), 256>>>(Wq, Wk, Wv, Wo, Wt);

    qkv_gemm_kernel<<<dim3(24, 32), 256, GEMM_SMEM_BYTES>>>(
        xh, Wt, bq, bk, bv, Q, K, Vt);

    attn_mma_kernel<<<dim3(T_SEQ / 128, B_SIZE * N_HEADS), 256,
                      ATTN_SMEM_BYTES>>>(Q, K, Vt, attn);

    out_gemm_kernel<<<dim3(8, 32), 256, GEMM_SMEM_BYTES>>>(attn, Wot, bo, out);
}

// round 14
// speedup vs baseline: 2.3563x; 1.0704x over previous
#include <cuda_runtime.h>
#include <cuda_fp16.h>
#include <cstdint>

#define D_MODEL 1024
#define N_HEADS 16
#define D_HEAD  64
#define B_SIZE  2
#define T_SEQ   2048
#define M_ROWS  (B_SIZE * T_SEQ)   // 4096

#define QSCALE 0.1803368801111204f   // 0.125 * log2(e)

__device__ __half g_Q[M_ROWS * D_MODEL];      // [B,H,T,64], scaled 0.125*log2e
__device__ __half g_K[M_ROWS * D_MODEL];      // [B,H,T,64]
__device__ __half g_Vt[M_ROWS * D_MODEL];     // [B,H,64,T]
__device__ __half g_attn[M_ROWS * D_MODEL];   // [B,T,1024]
__device__ __half g_xh[M_ROWS * D_MODEL];     // x as fp16
__device__ __half g_Wt[4][D_MODEL * D_MODEL]; // W^T: [n][k], fp16

// ===========================================================================
__device__ __forceinline__ uint32_t sptr(const void* p) {
    return (uint32_t)__cvta_generic_to_shared(p);
}
__device__ __forceinline__ void ldsm_x4(uint32_t& r0, uint32_t& r1,
                                        uint32_t& r2, uint32_t& r3,
                                        uint32_t addr) {
    asm volatile("ldmatrix.sync.aligned.m8n8.x4.shared.b16 {%0,%1,%2,%3},[%4];"
                 : "=r"(r0), "=r"(r1), "=r"(r2), "=r"(r3) : "r"(addr));
}
__device__ __forceinline__ void mma_f16(float c[4], const uint32_t a[4],
                                        const uint32_t b[2]) {
    asm volatile(
        "mma.sync.aligned.m16n8k16.row.col.f32.f16.f16.f32 "
        "{%0,%1,%2,%3}, {%4,%5,%6,%7}, {%8,%9}, {%0,%1,%2,%3};"
        : "+f"(c[0]), "+f"(c[1]), "+f"(c[2]), "+f"(c[3])
        : "r"(a[0]), "r"(a[1]), "r"(a[2]), "r"(a[3]), "r"(b[0]), "r"(b[1]));
}
__device__ __forceinline__ void cp_async16(void* dst_smem, const void* src) {
    uint32_t d = (uint32_t)__cvta_generic_to_shared(dst_smem);
    asm volatile("cp.async.cg.shared.global [%0], [%1], 16;" :: "r"(d), "l"(src));
}
__device__ __forceinline__ void cp_commit() { asm volatile("cp.async.commit_group;"); }
template <int N>
__device__ __forceinline__ void cp_wait() {
    asm volatile("cp.async.wait_group %0;" :: "n"(N));
}
__device__ __forceinline__ uint32_t packh2(float a, float b) {
    __half2 h = __floats2half2_rn(a, b);
    return *reinterpret_cast<uint32_t*>(&h);
}

// ===========================================================================
// Prepass 1: x (fp32) -> fp16
// ===========================================================================
__global__ void convert_x_kernel(const float* __restrict__ src,
                                 __half* __restrict__ dst, int n4)
{
    int i = blockIdx.x * blockDim.x + threadIdx.x;
    const int stride = gridDim.x * blockDim.x;
    for (; i < n4; i += stride) {
        float4 v = reinterpret_cast<const float4*>(src)[i];
        __half2 h0 = __floats2half2_rn(v.x, v.y);
        __half2 h1 = __floats2half2_rn(v.z, v.w);
        uint2 o = make_uint2(*(uint32_t*)&h0, *(uint32_t*)&h1);
        reinterpret_cast<uint2*>(dst)[i] = o;
    }
}

// ===========================================================================
// Prepass 2: W[k][n] fp32 -> Wt[n][k] fp16. 32x32 tile transpose.
// ===========================================================================
__global__ void transpose_w_kernel(const float* __restrict__ Wq,
                                   const float* __restrict__ Wk,
                                   const float* __restrict__ Wv,
                                   const float* __restrict__ Wo,
                                   __half* __restrict__ dst)
{
    __shared__ float sm[32][33];
    const int z = blockIdx.z;
    const float* W = (z == 0) ? Wq : (z == 1) ? Wk : (z == 2) ? Wv : Wo;
    __half* out = dst + (size_t)z * D_MODEL * D_MODEL;

    const int n0 = blockIdx.x * 32;
    const int k0 = blockIdx.y * 32;
    const int t  = threadIdx.x;
    {
        const int kl = t >> 3, nc = t & 7;
        float4 v = *reinterpret_cast<const float4*>(
            &W[(size_t)(k0 + kl) * D_MODEL + n0 + nc * 4]);
        sm[kl][nc * 4 + 0] = v.x; sm[kl][nc * 4 + 1] = v.y;
        sm[kl][nc * 4 + 2] = v.z; sm[kl][nc * 4 + 3] = v.w;
    }
    __syncthreads();
    {
        const int nl = t >> 3, kc = t & 7;
        __half2 h0 = __floats2half2_rn(sm[kc * 4 + 0][nl], sm[kc * 4 + 1][nl]);
        __half2 h1 = __floats2half2_rn(sm[kc * 4 + 2][nl], sm[kc * 4 + 3][nl]);
        uint2 o = make_uint2(*(uint32_t*)&h0, *(uint32_t*)&h1);
        *reinterpret_cast<uint2*>(
            &out[(size_t)(n0 + nl) * D_MODEL + k0 + kc * 4]) = o;
    }
}

// ===========================================================================
// FP16 GEMM: BK=64, 3-stage cp.async ring (distance-2 prefetch, hazard-free),
// ONE __syncthreads per K-tile, 16 iterations.
// BM=BN=128, 256 threads = 8 warps (2Mx4N).
// Smem rows stride 72 halves -> ldmatrix bank = 4r mod 32, conflict-free.
// ===========================================================================
#define GSH 72
#define GT_HALVES (128 * GSH)
#define GEMM_SMEM_BYTES (6 * GT_HALVES * 2)   // 3 stages x (A + B), fp16

__device__ __forceinline__ void gemm_mainloop_f16(
    const __half* __restrict__ A, const __half* __restrict__ Wt,
    __half* As, __half* Bs, int brow, int bcol, float acc[4][4][4])
{
    const int tid  = threadIdx.x;
    const int lane = tid & 31;
    const int wid  = tid >> 5;
    const int warp_m = (wid & 1) * 64;
    const int warp_n = (wid >> 1) * 32;

    auto load_stage = [&](int k0, int buf) {
        __half* as = As + buf * GT_HALVES;
        __half* bs = Bs + buf * GT_HALVES;
        #pragma unroll
        for (int it = 0; it < 4; it++) {
            const int id = tid + it * 256;
            const int r = id >> 3, c8 = id & 7;
            cp_async16(&as[r * GSH + c8 * 8],
                       &A[(size_t)(brow + r) * D_MODEL + k0 + c8 * 8]);
        }
        #pragma unroll
        for (int it = 0; it < 4; it++) {
            const int id = tid + it * 256;
            const int r = id >> 3, c8 = id & 7;
            cp_async16(&bs[r * GSH + c8 * 8],
                       &Wt[(size_t)(bcol + r) * D_MODEL + k0 + c8 * 8]);
        }
        cp_commit();
    };

    // 3-stage ring, distance-2 prefetch (R11 pattern): writes to (it+2)%3
    // happen AFTER the sync at iteration it; that buffer was consumed at
    // iteration it-1, so no overlap with readers.
    load_stage(0, 0);
    load_stage(64, 1);

    for (int it = 0; it < 16; it++) {
        if (it + 1 < 16) cp_wait<1>(); else cp_wait<0>();
        __syncthreads();
        if (it + 2 < 16) load_stage((it + 2) * 64, (it + 2) % 3);

        const __half* as = As + (it % 3) * GT_HALVES;
        const __half* bs = Bs + (it % 3) * GT_HALVES;

        // B fragments: 2 x4 per nf cover all 64 k
        uint32_t bf[4][8];
        #pragma unroll
        for (int nf = 0; nf < 4; nf++) {
            const int row = warp_n + nf * 8 + (lane & 7);
            const int kc  = (lane >> 3) * 8;
            ldsm_x4(bf[nf][0], bf[nf][1], bf[nf][2], bf[nf][3],
                    sptr(&bs[row * GSH + kc]));
            ldsm_x4(bf[nf][4], bf[nf][5], bf[nf][6], bf[nf][7],
                    sptr(&bs[row * GSH + 32 + kc]));
        }
        #pragma unroll
        for (int ks = 0; ks < 4; ks++) {
            uint32_t af[4][4];
            #pragma unroll
            for (int mf = 0; mf < 4; mf++) {
                const int row = warp_m + mf * 16 + (lane & 15);
                const int kc  = ks * 16 + (lane >> 4) * 8;
                ldsm_x4(af[mf][0], af[mf][1], af[mf][2], af[mf][3],
                        sptr(&as[row * GSH + kc]));
            }
            #pragma unroll
            for (int mf = 0; mf < 4; mf++)
                #pragma unroll
                for (int nf = 0; nf < 4; nf++)
                    mma_f16(acc[mf][nf], af[mf], &bf[nf][ks * 2]);
        }
    }
    __syncthreads();
}

// ---- Fused QKV projection: Q/K head layout; V written transposed [d][t] ----
__global__ __launch_bounds__(256)
void qkv_gemm_kernel(const __half* __restrict__ A,  const __half* __restrict__ Wt,
                     const float* __restrict__ bq, const float* __restrict__ bk,
                     const float* __restrict__ bv,
                     __half* __restrict__ Qo, __half* __restrict__ Ko,
                     __half* __restrict__ Vto)
{
    extern __shared__ __half smh[];
    __half* As = smh;
    __half* Bs = smh + 3 * GT_HALVES;

    const int wsel = blockIdx.x >> 3;
    const int bcol = (blockIdx.x & 7) * 128;
    const int brow = blockIdx.y * 128;
    const __half* W   = Wt + (size_t)wsel * D_MODEL * D_MODEL;
    const float* bias = (wsel == 0) ? bq : (wsel == 1) ? bk : bv;
    const float scale = (wsel == 0) ? QSCALE : 1.0f;

    float acc[4][4][4];
    #pragma unroll
    for (int mf = 0; mf < 4; mf++)
        #pragma unroll
        for (int nf = 0; nf < 4; nf++)
            #pragma unroll
            for (int c = 0; c < 4; c++) acc[mf][nf][c] = 0.0f;

    gemm_mainloop_f16(A, W, As, Bs, brow, bcol, acc);

    const int lane = threadIdx.x & 31;
    const int g  = lane >> 2, t4 = lane & 3;
    const int wid = threadIdx.x >> 5;
    const int warp_m = (wid & 1) * 64, warp_n = (wid >> 1) * 32;

    #pragma unroll
    for (int mf = 0; mf < 4; mf++) {
        #pragma unroll
        for (int nf = 0; nf < 4; nf++) {
            const int col = bcol + warp_n + nf * 8 + 2 * t4;
            const float b0 = bias[col], b1 = bias[col + 1];
            #pragma unroll
            for (int rr = 0; rr < 2; rr++) {
                const int row = brow + warp_m + mf * 16 + g + rr * 8;
                const float v0 = (acc[mf][nf][rr * 2 + 0] + b0) * scale;
                const float v1 = (acc[mf][nf][rr * 2 + 1] + b1) * scale;
                const int bb = row >> 11, tt = row & (T_SEQ - 1);
                const int hh = col >> 6,  dd = col & 63;
                const int bh = bb * N_HEADS + hh;
                if (wsel == 2) {
                    Vto[((size_t)bh * 64 + dd)     * T_SEQ + tt] = __float2half_rn(v0);
                    Vto[((size_t)bh * 64 + dd + 1) * T_SEQ + tt] = __float2half_rn(v1);
                } else {
                    __half* C = (wsel == 0) ? Qo : Ko;
                    *reinterpret_cast<__half2*>(
                        &C[((size_t)bh * T_SEQ + tt) * D_HEAD + dd]) =
                        __floats2half2_rn(v0, v1);
                }
            }
        }
    }
}

// ---- Output projection (A fp16, output fp32) ----
__global__ __launch_bounds__(256)
void out_gemm_kernel(const __half* __restrict__ A, const __half* __restrict__ Wt,
                     const float* __restrict__ bias, float* __restrict__ C)
{
    extern __shared__ __half smh[];
    __half* As = smh;
    __half* Bs = smh + 3 * GT_HALVES;

    const int bcol = blockIdx.x * 128;
    const int brow = blockIdx.y * 128;

    float acc[4][4][4];
    #pragma unroll
    for (int mf = 0; mf < 4; mf++)
        #pragma unroll
        for (int nf = 0; nf < 4; nf++)
            #pragma unroll
            for (int c = 0; c < 4; c++) acc[mf][nf][c] = 0.0f;

    gemm_mainloop_f16(A, Wt, As, Bs, brow, bcol, acc);

    const int lane = threadIdx.x & 31;
    const int g  = lane >> 2, t4 = lane & 3;
    const int wid = threadIdx.x >> 5;
    const int warp_m = (wid & 1) * 64, warp_n = (wid >> 1) * 32;

    #pragma unroll
    for (int mf = 0; mf < 4; mf++) {
        #pragma unroll
        for (int nf = 0; nf < 4; nf++) {
            const int col = bcol + warp_n + nf * 8 + 2 * t4;
            const float b0 = bias[col], b1 = bias[col + 1];
            #pragma unroll
            for (int rr = 0; rr < 2; rr++) {
                const int row = brow + warp_m + mf * 16 + g + rr * 8;
                float* p = &C[(size_t)row * D_MODEL + col];
                p[0] = acc[mf][nf][rr * 2 + 0] + b0;
                p[1] = acc[mf][nf][rr * 2 + 1] + b1;
            }
        }
    }
}

// ===========================================================================
// FP16 flash attention (causal), exp2-domain softmax. BQ=128, BKV=64,
// 256 thr, 2 CTA/SM. Stats in registers, P register-direct to A-frags.
// Structure identical to passing R11 (3-buffer ring, distance-2, 1 sync).
// ===========================================================================
#define ASH 72
#define QT_H (128 * ASH)
#define KT_H (64 * ASH)
#define ATTN_SMEM_BYTES ((QT_H + 6 * KT_H) * 2)

__global__ __launch_bounds__(256, 2)
void attn_mma_kernel(const __half* __restrict__ Qh,
                     const __half* __restrict__ Kh,
                     const __half* __restrict__ Vth,
                     __half* __restrict__ out)
{
    extern __shared__ __half smh[];
    __half* Qs  = smh;
    __half* Kb0 = smh + QT_H;
    __half* Vb0 = smh + QT_H + 3 * KT_H;

    const int tid  = threadIdx.x;
    const int lane = tid & 31;
    const int wr   = tid >> 5;
    const int g    = lane >> 2;
    const int t4   = lane & 3;

    const int bx = gridDim.x - 1 - blockIdx.x;
    const int bh = blockIdx.y;
    const int b  = bh >> 4;
    const int h  = bh & 15;
    const int q0 = bx * 128;

    const __half* Qb = Qh  + (size_t)bh * T_SEQ * D_HEAD;
    const __half* Kb = Kh  + (size_t)bh * T_SEQ * D_HEAD;
    const __half* Vb = Vth + (size_t)bh * D_HEAD * T_SEQ;

    auto load_q = [&]() {
        #pragma unroll
        for (int it = 0; it < 4; it++) {
            const int id = tid + it * 256;
            const int r = id >> 3, c8 = id & 7;
            cp_async16(&Qs[r * ASH + c8 * 8], &Qb[(size_t)(q0 + r) * 64 + c8 * 8]);
        }
    };
    auto load_k = [&](int k0, int buf) {
        __half* d = Kb0 + buf * KT_H;
        #pragma unroll
        for (int it = 0; it < 2; it++) {
            const int id = tid + it * 256;
            const int r = id >> 3, c8 = id & 7;
            cp_async16(&d[r * ASH + c8 * 8], &Kb[(size_t)(k0 + r) * 64 + c8 * 8]);
        }
    };
    auto load_v = [&](int k0, int buf) {
        __half* dv = Vb0 + buf * KT_H;
        #pragma unroll
        for (int it = 0; it < 2; it++) {
            const int id = tid + it * 256;
            const int r = id >> 3, c8 = id & 7;
            cp_async16(&dv[r * ASH + c8 * 8], &Vb[(size_t)r * T_SEQ + k0 + c8 * 8]);
        }
    };

    const int nkt = 2 * bx + 2;
    load_q(); load_k(0, 0); load_v(0, 0); cp_commit();
    if (nkt > 1) { load_k(64, 1); load_v(64, 1); cp_commit(); }

    float m0 = -1e30f, m1 = -1e30f, l0 = 0.0f, l1 = 0.0f;
    float o_acc[8][4];
    #pragma unroll
    for (int nf = 0; nf < 8; nf++)
        #pragma unroll
        for (int c = 0; c < 4; c++) o_acc[nf][c] = 0.0f;

    const int r0 = wr * 16 + g;
    const int r1 = r0 + 8;

    for (int kt = 0; kt < nkt; kt++) {
        if (kt + 1 < nkt) cp_wait<1>(); else cp_wait<0>();
        __syncthreads();
        if (kt + 2 < nkt) {
            load_k((kt + 2) * 64, (kt + 2) % 3);
            load_v((kt + 2) * 64, (kt + 2) % 3);
            cp_commit();
        }
        const __half* Ks = Kb0 + (kt % 3) * KT_H;
        const __half* Vs = Vb0 + (kt % 3) * KT_H;

        float s[8][4];
        #pragma unroll
        for (int nf = 0; nf < 8; nf++)
            #pragma unroll
            for (int c = 0; c < 4; c++) s[nf][c] = 0.0f;

        #pragma unroll
        for (int ks = 0; ks < 4; ks++) {
            uint32_t qf[4];
            ldsm_x4(qf[0], qf[1], qf[2], qf[3],
                    sptr(&Qs[(wr * 16 + (lane & 15)) * ASH
                             + ks * 16 + (lane >> 4) * 8]));
            #pragma unroll
            for (int nh = 0; nh < 2; nh++) {
                const int rr = nh * 32 + (lane >> 3) * 8 + (lane & 7);
                uint32_t blo[4], bhi[4];
                ldsm_x4(blo[0], blo[1], blo[2], blo[3],
                        sptr(&Ks[rr * ASH + ks * 16]));
                ldsm_x4(bhi[0], bhi[1], bhi[2], bhi[3],
                        sptr(&Ks[rr * ASH + ks * 16 + 8]));
                #pragma unroll
                for (int m = 0; m < 4; m++) {
                    uint32_t bfr[2] = {blo[m], bhi[m]};
                    mma_f16(s[nh * 4 + m], qf, bfr);
                }
            }
        }

        if (kt >= nkt - 2) {
            const int k0 = kt * 64;
            #pragma unroll
            for (int nf = 0; nf < 8; nf++) {
                const int c0 = k0 + nf * 8 + 2 * t4;
                if (c0     > q0 + r0) s[nf][0] = -1e30f;
                if (c0 + 1 > q0 + r0) s[nf][1] = -1e30f;
                if (c0     > q0 + r1) s[nf][2] = -1e30f;
                if (c0 + 1 > q0 + r1) s[nf][3] = -1e30f;
            }
        }

        float pm0 = -1e30f, pm1 = -1e30f;
        #pragma unroll
        for (int nf = 0; nf < 8; nf++) {
            pm0 = fmaxf(pm0, fmaxf(s[nf][0], s[nf][1]));
            pm1 = fmaxf(pm1, fmaxf(s[nf][2], s[nf][3]));
        }
        pm0 = fmaxf(pm0, __shfl_xor_sync(0xffffffffu, pm0, 1));
        pm0 = fmaxf(pm0, __shfl_xor_sync(0xffffffffu, pm0, 2));
        pm1 = fmaxf(pm1, __shfl_xor_sync(0xffffffffu, pm1, 1));
        pm1 = fmaxf(pm1, __shfl_xor_sync(0xffffffffu, pm1, 2));

        const float mn0 = fmaxf(m0, pm0);
        const float mn1 = fmaxf(m1, pm1);
        const float sc0 = exp2f(m0 - mn0);
        const float sc1 = exp2f(m1 - mn1);
        m0 = mn0; m1 = mn1;

        float sum0 = 0.0f, sum1 = 0.0f;
        uint32_t pa[4][4];
        #pragma unroll
        for (int m = 0; m < 4; m++) {
            #pragma unroll
            for (int j = 0; j < 2; j++) {
                const int nf = 2 * m + j;
                const float e0 = exp2f(s[nf][0] - mn0);
                const float e1 = exp2f(s[nf][1] - mn0);
                const float e2 = exp2f(s[nf][2] - mn1);
                const float e3 = exp2f(s[nf][3] - mn1);
                sum0 += e0 + e1;
                sum1 += e2 + e3;
                pa[m][j * 2 + 0] = packh2(e0, e1);
                pa[m][j * 2 + 1] = packh2(e2, e3);
            }
        }
        sum0 += __shfl_xor_sync(0xffffffffu, sum0, 1);
        sum0 += __shfl_xor_sync(0xffffffffu, sum0, 2);
        sum1 += __shfl_xor_sync(0xffffffffu, sum1, 1);
        sum1 += __shfl_xor_sync(0xffffffffu, sum1, 2);
        l0 = l0 * sc0 + sum0;
        l1 = l1 * sc1 + sum1;

        #pragma unroll
        for (int nf = 0; nf < 8; nf++) {
            o_acc[nf][0] *= sc0; o_acc[nf][1] *= sc0;
            o_acc[nf][2] *= sc1; o_acc[nf][3] *= sc1;
        }

        #pragma unroll
        for (int m = 0; m < 4; m++) {
            #pragma unroll
            for (int nh = 0; nh < 2; nh++) {
                const int rr = nh * 32 + (lane >> 3) * 8 + (lane & 7);
                uint32_t blo[4], bhi[4];
                ldsm_x4(blo[0], blo[1], blo[2], blo[3],
                        sptr(&Vs[rr * ASH + m * 16]));
                ldsm_x4(bhi[0], bhi[1], bhi[2], bhi[3],
                        sptr(&Vs[rr * ASH + m * 16 + 8]));
                #pragma unroll
                for (int mm = 0; mm < 4; mm++) {
                    uint32_t bfr[2] = {blo[mm], bhi[mm]};
                    mma_f16(o_acc[nh * 4 + mm], pa[m], bfr);
                }
            }
        }
    }

    const float il0 = 1.0f / l0;
    const float il1 = 1.0f / l1;
    #pragma unroll
    for (int nf = 0; nf < 8; nf++) {
        const int d = nf * 8 + 2 * t4;
        *reinterpret_cast<__half2*>(
            &out[((size_t)(b * T_SEQ + q0 + r0)) * D_MODEL + h * 64 + d]) =
            __floats2half2_rn(o_acc[nf][0] * il0, o_acc[nf][1] * il0);
        *reinterpret_cast<__half2*>(
            &out[((size_t)(b * T_SEQ + q0 + r1)) * D_MODEL + h * 64 + d]) =
            __floats2half2_rn(o_acc[nf][2] * il1, o_acc[nf][3] * il1);
    }
}

// ---------------------------------------------------------------------------
extern "C" void kernel_launch(void* const* d_in, const int* in_sizes, int n_in,
                              void* d_out, int out_size)
{
    const float* x  = (const float*)d_in[0];
    const float* Wq = (const float*)d_in[1];
    const float* bq = (const float*)d_in[2];
    const float* Wk = (const float*)d_in[3];
    const float* bk = (const float*)d_in[4];
    const float* Wv = (const float*)d_in[5];
    const float* bv = (const float*)d_in[6];
    const float* Wo = (const float*)d_in[7];
    const float* bo = (const float*)d_in[8];
    float* out = (float*)d_out;

    __half *Q, *K, *Vt, *attn, *xh, *Wt;
    cudaGetSymbolAddress((void**)&Q, g_Q);
    cudaGetSymbolAddress((void**)&K, g_K);
    cudaGetSymbolAddress((void**)&Vt, g_Vt);
    cudaGetSymbolAddress((void**)&attn, g_attn);
    cudaGetSymbolAddress((void**)&xh, g_xh);
    cudaGetSymbolAddress((void**)&Wt, g_Wt);
    __half* Wot = Wt + (size_t)3 * D_MODEL * D_MODEL;

    cudaFuncSetAttribute(qkv_gemm_kernel,
                         cudaFuncAttributeMaxDynamicSharedMemorySize,
                         GEMM_SMEM_BYTES);
    cudaFuncSetAttribute(out_gemm_kernel,
                         cudaFuncAttributeMaxDynamicSharedMemorySize,
                         GEMM_SMEM_BYTES);
    cudaFuncSetAttribute(attn_mma_kernel,
                         cudaFuncAttributeMaxDynamicSharedMemorySize,
                         ATTN_SMEM_BYTES);

    convert_x_kernel<<<592, 256>>>(x, xh, M_ROWS * D_MODEL / 4);
    transpose_w_kernel<<<dim3(32, 32, 4), 256>>>(Wq, Wk, Wv, Wo, Wt);

    qkv_gemm_kernel<<<dim3(24, 32), 256, GEMM_SMEM_BYTES>>>(
        xh, Wt, bq, bk, bv, Q, K, Vt);

    attn_mma_kernel<<<dim3(T_SEQ / 128, B_SIZE * N_HEADS), 256,
                      ATTN_SMEM_BYTES>>>(Q, K, Vt, attn);

    out_gemm_kernel<<<dim3(8, 32), 256, GEMM_SMEM_BYTES>>>(attn, Wot, bo, out);
}

// round 15
// speedup vs baseline: 2.3912x; 1.0148x over previous
#include <cuda_runtime.h>
#include <cuda_fp16.h>
#include <cstdint>

#define D_MODEL 1024
#define N_HEADS 16
#define D_HEAD  64
#define B_SIZE  2
#define T_SEQ   2048
#define M_ROWS  (B_SIZE * T_SEQ)   // 4096

#define QSCALE 0.1803368801111204f   // 0.125 * log2(e)

__device__ __half g_Q[M_ROWS * D_MODEL];      // [B,H,T,64], scaled 0.125*log2e
__device__ __half g_K[M_ROWS * D_MODEL];      // [B,H,T,64]
__device__ __half g_Vt[M_ROWS * D_MODEL];     // [B,H,64,T]
__device__ __half g_attn[M_ROWS * D_MODEL];   // [B,T,1024]
__device__ __half g_xh[M_ROWS * D_MODEL];     // x as fp16
__device__ __half g_Wt[4][D_MODEL * D_MODEL]; // W^T: [n][k], fp16

// ===========================================================================
__device__ __forceinline__ uint32_t sptr(const void* p) {
    return (uint32_t)__cvta_generic_to_shared(p);
}
__device__ __forceinline__ void ldsm_x4(uint32_t& r0, uint32_t& r1,
                                        uint32_t& r2, uint32_t& r3,
                                        uint32_t addr) {
    asm volatile("ldmatrix.sync.aligned.m8n8.x4.shared.b16 {%0,%1,%2,%3},[%4];"
                 : "=r"(r0), "=r"(r1), "=r"(r2), "=r"(r3) : "r"(addr));
}
__device__ __forceinline__ void mma_f16(float c[4], const uint32_t a[4],
                                        const uint32_t b[2]) {
    asm volatile(
        "mma.sync.aligned.m16n8k16.row.col.f32.f16.f16.f32 "
        "{%0,%1,%2,%3}, {%4,%5,%6,%7}, {%8,%9}, {%0,%1,%2,%3};"
        : "+f"(c[0]), "+f"(c[1]), "+f"(c[2]), "+f"(c[3])
        : "r"(a[0]), "r"(a[1]), "r"(a[2]), "r"(a[3]), "r"(b[0]), "r"(b[1]));
}
__device__ __forceinline__ void cp_async16(void* dst_smem, const void* src) {
    uint32_t d = (uint32_t)__cvta_generic_to_shared(dst_smem);
    asm volatile("cp.async.cg.shared.global [%0], [%1], 16;" :: "r"(d), "l"(src));
}
__device__ __forceinline__ void cp_commit() { asm volatile("cp.async.commit_group;"); }
template <int N>
__device__ __forceinline__ void cp_wait() {
    asm volatile("cp.async.wait_group %0;" :: "n"(N));
}
__device__ __forceinline__ uint32_t packh2(float a, float b) {
    __half2 h = __floats2half2_rn(a, b);
    return *reinterpret_cast<uint32_t*>(&h);
}

// ===========================================================================
// Merged prepass: blocks [0,592) convert x -> fp16; blocks [592, 592+4096)
// transpose one 32x32 W tile (z = tile/1024 selects the matrix).
// ===========================================================================
#define PREP_XBLOCKS 592
__global__ void prep_kernel(const float* __restrict__ x,
                            __half* __restrict__ xh,
                            const float* __restrict__ Wq,
                            const float* __restrict__ Wk,
                            const float* __restrict__ Wv,
                            const float* __restrict__ Wo,
                            __half* __restrict__ Wt)
{
    __shared__ float sm[32][33];
    const int t = threadIdx.x;

    if (blockIdx.x < PREP_XBLOCKS) {
        const int n4 = M_ROWS * D_MODEL / 4;
        int i = blockIdx.x * 256 + t;
        const int stride = PREP_XBLOCKS * 256;
        for (; i < n4; i += stride) {
            float4 v = reinterpret_cast<const float4*>(x)[i];
            __half2 h0 = __floats2half2_rn(v.x, v.y);
            __half2 h1 = __floats2half2_rn(v.z, v.w);
            uint2 o = make_uint2(*(uint32_t*)&h0, *(uint32_t*)&h1);
            reinterpret_cast<uint2*>(xh)[i] = o;
        }
        return;
    }

    const int tl = blockIdx.x - PREP_XBLOCKS;   // 0..4095
    const int z    = tl >> 10;                  // matrix id
    const int tile = tl & 1023;
    const int n0 = (tile & 31) * 32;
    const int k0 = (tile >> 5) * 32;
    const float* W = (z == 0) ? Wq : (z == 1) ? Wk : (z == 2) ? Wv : Wo;
    __half* out = Wt + (size_t)z * D_MODEL * D_MODEL;

    {
        const int kl = t >> 3, nc = t & 7;
        float4 v = *reinterpret_cast<const float4*>(
            &W[(size_t)(k0 + kl) * D_MODEL + n0 + nc * 4]);
        sm[kl][nc * 4 + 0] = v.x; sm[kl][nc * 4 + 1] = v.y;
        sm[kl][nc * 4 + 2] = v.z; sm[kl][nc * 4 + 3] = v.w;
    }
    __syncthreads();
    {
        const int nl = t >> 3, kc = t & 7;
        __half2 h0 = __floats2half2_rn(sm[kc * 4 + 0][nl], sm[kc * 4 + 1][nl]);
        __half2 h1 = __floats2half2_rn(sm[kc * 4 + 2][nl], sm[kc * 4 + 3][nl]);
        uint2 o = make_uint2(*(uint32_t*)&h0, *(uint32_t*)&h1);
        *reinterpret_cast<uint2*>(
            &out[(size_t)(n0 + nl) * D_MODEL + k0 + kc * 4]) = o;
    }
}

// ===========================================================================
// FP16 GEMM: BK=64, 3-stage cp.async ring, 1 sync per K-tile, 16 iterations.
// BM=BN=128, 256 threads = 8 warps (2Mx4N). Target 2 CTAs/SM (221KB smem).
// ===========================================================================
#define GSH 72
#define GT_HALVES (128 * GSH)
#define GEMM_SMEM_BYTES (6 * GT_HALVES * 2)   // 3 stages x (A + B), fp16

__device__ __forceinline__ void gemm_mainloop_f16(
    const __half* __restrict__ A, const __half* __restrict__ Wt,
    __half* As, __half* Bs, int brow, int bcol, float acc[4][4][4])
{
    const int tid  = threadIdx.x;
    const int lane = tid & 31;
    const int wid  = tid >> 5;
    const int warp_m = (wid & 1) * 64;
    const int warp_n = (wid >> 1) * 32;

    auto load_stage = [&](int k0, int buf) {
        __half* as = As + buf * GT_HALVES;
        __half* bs = Bs + buf * GT_HALVES;
        #pragma unroll
        for (int it = 0; it < 4; it++) {
            const int id = tid + it * 256;
            const int r = id >> 3, c8 = id & 7;
            cp_async16(&as[r * GSH + c8 * 8],
                       &A[(size_t)(brow + r) * D_MODEL + k0 + c8 * 8]);
        }
        #pragma unroll
        for (int it = 0; it < 4; it++) {
            const int id = tid + it * 256;
            const int r = id >> 3, c8 = id & 7;
            cp_async16(&bs[r * GSH + c8 * 8],
                       &Wt[(size_t)(bcol + r) * D_MODEL + k0 + c8 * 8]);
        }
        cp_commit();
    };

    load_stage(0, 0);
    load_stage(64, 1);

    for (int it = 0; it < 16; it++) {
        if (it + 1 < 16) cp_wait<1>(); else cp_wait<0>();
        __syncthreads();
        if (it + 2 < 16) load_stage((it + 2) * 64, (it + 2) % 3);

        const __half* as = As + (it % 3) * GT_HALVES;
        const __half* bs = Bs + (it % 3) * GT_HALVES;

        uint32_t bf[4][8];
        #pragma unroll
        for (int nf = 0; nf < 4; nf++) {
            const int row = warp_n + nf * 8 + (lane & 7);
            const int kc  = (lane >> 3) * 8;
            ldsm_x4(bf[nf][0], bf[nf][1], bf[nf][2], bf[nf][3],
                    sptr(&bs[row * GSH + kc]));
            ldsm_x4(bf[nf][4], bf[nf][5], bf[nf][6], bf[nf][7],
                    sptr(&bs[row * GSH + 32 + kc]));
        }
        #pragma unroll
        for (int ks = 0; ks < 4; ks++) {
            uint32_t af[4][4];
            #pragma unroll
            for (int mf = 0; mf < 4; mf++) {
                const int row = warp_m + mf * 16 + (lane & 15);
                const int kc  = ks * 16 + (lane >> 4) * 8;
                ldsm_x4(af[mf][0], af[mf][1], af[mf][2], af[mf][3],
                        sptr(&as[row * GSH + kc]));
            }
            #pragma unroll
            for (int mf = 0; mf < 4; mf++)
                #pragma unroll
                for (int nf = 0; nf < 4; nf++)
                    mma_f16(acc[mf][nf], af[mf], &bf[nf][ks * 2]);
        }
    }
    __syncthreads();
}

// ---- Fused QKV projection: Q/K head layout; V written transposed [d][t] ----
__global__ __launch_bounds__(256, 2)
void qkv_gemm_kernel(const __half* __restrict__ A,  const __half* __restrict__ Wt,
                     const float* __restrict__ bq, const float* __restrict__ bk,
                     const float* __restrict__ bv,
                     __half* __restrict__ Qo, __half* __restrict__ Ko,
                     __half* __restrict__ Vto)
{
    extern __shared__ __half smh[];
    __half* As = smh;
    __half* Bs = smh + 3 * GT_HALVES;

    const int wsel = blockIdx.x >> 3;
    const int bcol = (blockIdx.x & 7) * 128;
    const int brow = blockIdx.y * 128;
    const __half* W   = Wt + (size_t)wsel * D_MODEL * D_MODEL;
    const float* bias = (wsel == 0) ? bq : (wsel == 1) ? bk : bv;
    const float scale = (wsel == 0) ? QSCALE : 1.0f;

    float acc[4][4][4];
    #pragma unroll
    for (int mf = 0; mf < 4; mf++)
        #pragma unroll
        for (int nf = 0; nf < 4; nf++)
            #pragma unroll
            for (int c = 0; c < 4; c++) acc[mf][nf][c] = 0.0f;

    gemm_mainloop_f16(A, W, As, Bs, brow, bcol, acc);

    const int lane = threadIdx.x & 31;
    const int g  = lane >> 2, t4 = lane & 3;
    const int wid = threadIdx.x >> 5;
    const int warp_m = (wid & 1) * 64, warp_n = (wid >> 1) * 32;

    #pragma unroll
    for (int mf = 0; mf < 4; mf++) {
        #pragma unroll
        for (int nf = 0; nf < 4; nf++) {
            const int col = bcol + warp_n + nf * 8 + 2 * t4;
            const float b0 = bias[col], b1 = bias[col + 1];
            #pragma unroll
            for (int rr = 0; rr < 2; rr++) {
                const int row = brow + warp_m + mf * 16 + g + rr * 8;
                const float v0 = (acc[mf][nf][rr * 2 + 0] + b0) * scale;
                const float v1 = (acc[mf][nf][rr * 2 + 1] + b1) * scale;
                const int bb = row >> 11, tt = row & (T_SEQ - 1);
                const int hh = col >> 6,  dd = col & 63;
                const int bh = bb * N_HEADS + hh;
                if (wsel == 2) {
                    Vto[((size_t)bh * 64 + dd)     * T_SEQ + tt] = __float2half_rn(v0);
                    Vto[((size_t)bh * 64 + dd + 1) * T_SEQ + tt] = __float2half_rn(v1);
                } else {
                    __half* C = (wsel == 0) ? Qo : Ko;
                    *reinterpret_cast<__half2*>(
                        &C[((size_t)bh * T_SEQ + tt) * D_HEAD + dd]) =
                        __floats2half2_rn(v0, v1);
                }
            }
        }
    }
}

// ---- Output projection (A fp16, output fp32) ----
__global__ __launch_bounds__(256, 2)
void out_gemm_kernel(const __half* __restrict__ A, const __half* __restrict__ Wt,
                     const float* __restrict__ bias, float* __restrict__ C)
{
    extern __shared__ __half smh[];
    __half* As = smh;
    __half* Bs = smh + 3 * GT_HALVES;

    const int bcol = blockIdx.x * 128;
    const int brow = blockIdx.y * 128;

    float acc[4][4][4];
    #pragma unroll
    for (int mf = 0; mf < 4; mf++)
        #pragma unroll
        for (int nf = 0; nf < 4; nf++)
            #pragma unroll
            for (int c = 0; c < 4; c++) acc[mf][nf][c] = 0.0f;

    gemm_mainloop_f16(A, Wt, As, Bs, brow, bcol, acc);

    const int lane = threadIdx.x & 31;
    const int g  = lane >> 2, t4 = lane & 3;
    const int wid = threadIdx.x >> 5;
    const int warp_m = (wid & 1) * 64, warp_n = (wid >> 1) * 32;

    #pragma unroll
    for (int mf = 0; mf < 4; mf++) {
        #pragma unroll
        for (int nf = 0; nf < 4; nf++) {
            const int col = bcol + warp_n + nf * 8 + 2 * t4;
            const float b0 = bias[col], b1 = bias[col + 1];
            #pragma unroll
            for (int rr = 0; rr < 2; rr++) {
                const int row = brow + warp_m + mf * 16 + g + rr * 8;
                float* p = &C[(size_t)row * D_MODEL + col];
                p[0] = acc[mf][nf][rr * 2 + 0] + b0;
                p[1] = acc[mf][nf][rr * 2 + 1] + b1;
            }
        }
    }
}

// ===========================================================================
// FP16 flash attention (causal), exp2 softmax, warp-level masked-tile skip.
// BQ=128, BKV=64, 256 thr, 2 CTA/SM. Stats in registers, P register-direct.
// ===========================================================================
#define ASH 72
#define QT_H (128 * ASH)
#define KT_H (64 * ASH)
#define ATTN_SMEM_BYTES ((QT_H + 6 * KT_H) * 2)

__global__ __launch_bounds__(256, 2)
void attn_mma_kernel(const __half* __restrict__ Qh,
                     const __half* __restrict__ Kh,
                     const __half* __restrict__ Vth,
                     __half* __restrict__ out)
{
    extern __shared__ __half smh[];
    __half* Qs  = smh;
    __half* Kb0 = smh + QT_H;
    __half* Vb0 = smh + QT_H + 3 * KT_H;

    const int tid  = threadIdx.x;
    const int lane = tid & 31;
    const int wr   = tid >> 5;
    const int g    = lane >> 2;
    const int t4   = lane & 3;

    const int bx = gridDim.x - 1 - blockIdx.x;
    const int bh = blockIdx.y;
    const int b  = bh >> 4;
    const int h  = bh & 15;
    const int q0 = bx * 128;

    const __half* Qb = Qh  + (size_t)bh * T_SEQ * D_HEAD;
    const __half* Kb = Kh  + (size_t)bh * T_SEQ * D_HEAD;
    const __half* Vb = Vth + (size_t)bh * D_HEAD * T_SEQ;

    auto load_q = [&]() {
        #pragma unroll
        for (int it = 0; it < 4; it++) {
            const int id = tid + it * 256;
            const int r = id >> 3, c8 = id & 7;
            cp_async16(&Qs[r * ASH + c8 * 8], &Qb[(size_t)(q0 + r) * 64 + c8 * 8]);
        }
    };
    auto load_k = [&](int k0, int buf) {
        __half* d = Kb0 + buf * KT_H;
        #pragma unroll
        for (int it = 0; it < 2; it++) {
            const int id = tid + it * 256;
            const int r = id >> 3, c8 = id & 7;
            cp_async16(&d[r * ASH + c8 * 8], &Kb[(size_t)(k0 + r) * 64 + c8 * 8]);
        }
    };
    auto load_v = [&](int k0, int buf) {
        __half* dv = Vb0 + buf * KT_H;
        #pragma unroll
        for (int it = 0; it < 2; it++) {
            const int id = tid + it * 256;
            const int r = id >> 3, c8 = id & 7;
            cp_async16(&dv[r * ASH + c8 * 8], &Vb[(size_t)r * T_SEQ + k0 + c8 * 8]);
        }
    };

    const int nkt = 2 * bx + 2;
    load_q(); load_k(0, 0); load_v(0, 0); cp_commit();
    if (nkt > 1) { load_k(64, 1); load_v(64, 1); cp_commit(); }

    float m0 = -1e30f, m1 = -1e30f, l0 = 0.0f, l1 = 0.0f;
    float o_acc[8][4];
    #pragma unroll
    for (int nf = 0; nf < 8; nf++)
        #pragma unroll
        for (int c = 0; c < 4; c++) o_acc[nf][c] = 0.0f;

    const int r0 = wr * 16 + g;
    const int r1 = r0 + 8;
    const int row_hi = q0 + wr * 16 + 15;   // warp's last (largest) row

    for (int kt = 0; kt < nkt; kt++) {
        if (kt + 1 < nkt) cp_wait<1>(); else cp_wait<0>();
        __syncthreads();
        if (kt + 2 < nkt) {
            load_k((kt + 2) * 64, (kt + 2) % 3);
            load_v((kt + 2) * 64, (kt + 2) % 3);
            cp_commit();
        }

        const int k0 = kt * 64;
        if (k0 > row_hi) continue;   // whole tile causally masked for this warp

        const __half* Ks = Kb0 + (kt % 3) * KT_H;
        const __half* Vs = Vb0 + (kt % 3) * KT_H;

        float s[8][4];
        #pragma unroll
        for (int nf = 0; nf < 8; nf++)
            #pragma unroll
            for (int c = 0; c < 4; c++) s[nf][c] = 0.0f;

        #pragma unroll
        for (int ks = 0; ks < 4; ks++) {
            uint32_t qf[4];
            ldsm_x4(qf[0], qf[1], qf[2], qf[3],
                    sptr(&Qs[(wr * 16 + (lane & 15)) * ASH
                             + ks * 16 + (lane >> 4) * 8]));
            #pragma unroll
            for (int nh = 0; nh < 2; nh++) {
                const int rr = nh * 32 + (lane >> 3) * 8 + (lane & 7);
                uint32_t blo[4], bhi[4];
                ldsm_x4(blo[0], blo[1], blo[2], blo[3],
                        sptr(&Ks[rr * ASH + ks * 16]));
                ldsm_x4(bhi[0], bhi[1], bhi[2], bhi[3],
                        sptr(&Ks[rr * ASH + ks * 16 + 8]));
                #pragma unroll
                for (int m = 0; m < 4; m++) {
                    uint32_t bfr[2] = {blo[m], bhi[m]};
                    mma_f16(s[nh * 4 + m], qf, bfr);
                }
            }
        }

        if (k0 + 63 > q0 + wr * 16) {     // tile touches this warp's diagonal
            #pragma unroll
            for (int nf = 0; nf < 8; nf++) {
                const int c0 = k0 + nf * 8 + 2 * t4;
                if (c0     > q0 + r0) s[nf][0] = -1e30f;
                if (c0 + 1 > q0 + r0) s[nf][1] = -1e30f;
                if (c0     > q0 + r1) s[nf][2] = -1e30f;
                if (c0 + 1 > q0 + r1) s[nf][3] = -1e30f;
            }
        }

        float pm0 = -1e30f, pm1 = -1e30f;
        #pragma unroll
        for (int nf = 0; nf < 8; nf++) {
            pm0 = fmaxf(pm0, fmaxf(s[nf][0], s[nf][1]));
            pm1 = fmaxf(pm1, fmaxf(s[nf][2], s[nf][3]));
        }
        pm0 = fmaxf(pm0, __shfl_xor_sync(0xffffffffu, pm0, 1));
        pm0 = fmaxf(pm0, __shfl_xor_sync(0xffffffffu, pm0, 2));
        pm1 = fmaxf(pm1, __shfl_xor_sync(0xffffffffu, pm1, 1));
        pm1 = fmaxf(pm1, __shfl_xor_sync(0xffffffffu, pm1, 2));

        const float mn0 = fmaxf(m0, pm0);
        const float mn1 = fmaxf(m1, pm1);
        const float sc0 = exp2f(m0 - mn0);
        const float sc1 = exp2f(m1 - mn1);
        m0 = mn0; m1 = mn1;

        float sum0 = 0.0f, sum1 = 0.0f;
        uint32_t pa[4][4];
        #pragma unroll
        for (int m = 0; m < 4; m++) {
            #pragma unroll
            for (int j = 0; j < 2; j++) {
                const int nf = 2 * m + j;
                const float e0 = exp2f(s[nf][0] - mn0);
                const float e1 = exp2f(s[nf][1] - mn0);
                const float e2 = exp2f(s[nf][2] - mn1);
                const float e3 = exp2f(s[nf][3] - mn1);
                sum0 += e0 + e1;
                sum1 += e2 + e3;
                pa[m][j * 2 + 0] = packh2(e0, e1);
                pa[m][j * 2 + 1] = packh2(e2, e3);
            }
        }
        sum0 += __shfl_xor_sync(0xffffffffu, sum0, 1);
        sum0 += __shfl_xor_sync(0xffffffffu, sum0, 2);
        sum1 += __shfl_xor_sync(0xffffffffu, sum1, 1);
        sum1 += __shfl_xor_sync(0xffffffffu, sum1, 2);
        l0 = l0 * sc0 + sum0;
        l1 = l1 * sc1 + sum1;

        #pragma unroll
        for (int nf = 0; nf < 8; nf++) {
            o_acc[nf][0] *= sc0; o_acc[nf][1] *= sc0;
            o_acc[nf][2] *= sc1; o_acc[nf][3] *= sc1;
        }

        #pragma unroll
        for (int m = 0; m < 4; m++) {
            #pragma unroll
            for (int nh = 0; nh < 2; nh++) {
                const int rr = nh * 32 + (lane >> 3) * 8 + (lane & 7);
                uint32_t blo[4], bhi[4];
                ldsm_x4(blo[0], blo[1], blo[2], blo[3],
                        sptr(&Vs[rr * ASH + m * 16]));
                ldsm_x4(bhi[0], bhi[1], bhi[2], bhi[3],
                        sptr(&Vs[rr * ASH + m * 16 + 8]));
                #pragma unroll
                for (int mm = 0; mm < 4; mm++) {
                    uint32_t bfr[2] = {blo[mm], bhi[mm]};
                    mma_f16(o_acc[nh * 4 + mm], pa[m], bfr);
                }
            }
        }
    }

    const float il0 = 1.0f / l0;
    const float il1 = 1.0f / l1;
    #pragma unroll
    for (int nf = 0; nf < 8; nf++) {
        const int d = nf * 8 + 2 * t4;
        *reinterpret_cast<__half2*>(
            &out[((size_t)(b * T_SEQ + q0 + r0)) * D_MODEL + h * 64 + d]) =
            __floats2half2_rn(o_acc[nf][0] * il0, o_acc[nf][1] * il0);
        *reinterpret_cast<__half2*>(
            &out[((size_t)(b * T_SEQ + q0 + r1)) * D_MODEL + h * 64 + d]) =
            __floats2half2_rn(o_acc[nf][2] * il1, o_acc[nf][3] * il1);
    }
}

// ---------------------------------------------------------------------------
extern "C" void kernel_launch(void* const* d_in, const int* in_sizes, int n_in,
                              void* d_out, int out_size)
{
    const float* x  = (const float*)d_in[0];
    const float* Wq = (const float*)d_in[1];
    const float* bq = (const float*)d_in[2];
    const float* Wk = (const float*)d_in[3];
    const float* bk = (const float*)d_in[4];
    const float* Wv = (const float*)d_in[5];
    const float* bv = (const float*)d_in[6];
    const float* Wo = (const float*)d_in[7];
    const float* bo = (const float*)d_in[8];
    float* out = (float*)d_out;

    __half *Q, *K, *Vt, *attn, *xh, *Wt;
    cudaGetSymbolAddress((void**)&Q, g_Q);
    cudaGetSymbolAddress((void**)&K, g_K);
    cudaGetSymbolAddress((void**)&Vt, g_Vt);
    cudaGetSymbolAddress((void**)&attn, g_attn);
    cudaGetSymbolAddress((void**)&xh, g_xh);
    cudaGetSymbolAddress((void**)&Wt, g_Wt);
    __half* Wot = Wt + (size_t)3 * D_MODEL * D_MODEL;

    cudaFuncSetAttribute(qkv_gemm_kernel,
                         cudaFuncAttributeMaxDynamicSharedMemorySize,
                         GEMM_SMEM_BYTES);
    cudaFuncSetAttribute(out_gemm_kernel,
                         cudaFuncAttributeMaxDynamicSharedMemorySize,
                         GEMM_SMEM_BYTES);
    cudaFuncSetAttribute(attn_mma_kernel,
                         cudaFuncAttributeMaxDynamicSharedMemorySize,
                         ATTN_SMEM_BYTES);

    prep_kernel<<<PREP_XBLOCKS + 4096, 256>>>(x, xh, Wq, Wk, Wv, Wo, Wt);

    qkv_gemm_kernel<<<dim3(24, 32), 256, GEMM_SMEM_BYTES>>>(
        xh, Wt, bq, bk, bv, Q, K, Vt);

    attn_mma_kernel<<<dim3(T_SEQ / 128, B_SIZE * N_HEADS), 256,
                      ATTN_SMEM_BYTES>>>(Q, K, Vt, attn);

    out_gemm_kernel<<<dim3(8, 32), 256, GEMM_SMEM_BYTES>>>(attn, Wot, bo, out);
}

// round 16
// speedup vs baseline: 2.4481x; 1.0238x over previous
#include <cuda_runtime.h>
#include <cuda_fp16.h>
#include <cstdint>

#define D_MODEL 1024
#define N_HEADS 16
#define D_HEAD  64
#define B_SIZE  2
#define T_SEQ   2048
#define M_ROWS  (B_SIZE * T_SEQ)   // 4096

#define QSCALE 0.1803368801111204f   // 0.125 * log2(e)

__device__ __half g_Q[M_ROWS * D_MODEL];      // [B,H,T,64], scaled 0.125*log2e
__device__ __half g_K[M_ROWS * D_MODEL];      // [B,H,T,64]
__device__ __half g_Vt[M_ROWS * D_MODEL];     // [B,H,64,T]
__device__ __half g_attn[M_ROWS * D_MODEL];   // [B,T,1024]
__device__ __half g_xh[M_ROWS * D_MODEL];     // x as fp16
__device__ __half g_Wt[4][D_MODEL * D_MODEL]; // W^T: [n][k], fp16

// ===========================================================================
__device__ __forceinline__ uint32_t sptr(const void* p) {
    return (uint32_t)__cvta_generic_to_shared(p);
}
__device__ __forceinline__ void ldsm_x4(uint32_t& r0, uint32_t& r1,
                                        uint32_t& r2, uint32_t& r3,
                                        uint32_t addr) {
    asm volatile("ldmatrix.sync.aligned.m8n8.x4.shared.b16 {%0,%1,%2,%3},[%4];"
                 : "=r"(r0), "=r"(r1), "=r"(r2), "=r"(r3) : "r"(addr));
}
__device__ __forceinline__ void mma_f16(float c[4], const uint32_t a[4],
                                        const uint32_t b[2]) {
    asm volatile(
        "mma.sync.aligned.m16n8k16.row.col.f32.f16.f16.f32 "
        "{%0,%1,%2,%3}, {%4,%5,%6,%7}, {%8,%9}, {%0,%1,%2,%3};"
        : "+f"(c[0]), "+f"(c[1]), "+f"(c[2]), "+f"(c[3])
        : "r"(a[0]), "r"(a[1]), "r"(a[2]), "r"(a[3]), "r"(b[0]), "r"(b[1]));
}
__device__ __forceinline__ void cp_async16(void* dst_smem, const void* src) {
    uint32_t d = (uint32_t)__cvta_generic_to_shared(dst_smem);
    asm volatile("cp.async.cg.shared.global [%0], [%1], 16;" :: "r"(d), "l"(src));
}
__device__ __forceinline__ void cp_commit() { asm volatile("cp.async.commit_group;"); }
template <int N>
__device__ __forceinline__ void cp_wait() {
    asm volatile("cp.async.wait_group %0;" :: "n"(N));
}
__device__ __forceinline__ uint32_t packh2(float a, float b) {
    __half2 h = __floats2half2_rn(a, b);
    return *reinterpret_cast<uint32_t*>(&h);
}
__device__ __forceinline__ uint32_t h2exp2(uint32_t x) {
    uint32_t r;
    asm volatile("ex2.approx.f16x2 %0, %1;" : "=r"(r) : "r"(x));
    return r;
}
__device__ __forceinline__ float fex2(float x) {
    float r;
    asm volatile("ex2.approx.ftz.f32 %0, %1;" : "=f"(r) : "f"(x));
    return r;
}
__device__ __forceinline__ uint32_t hadd2(uint32_t a, uint32_t b) {
    uint32_t r;
    asm volatile("add.f16x2 %0, %1, %2;" : "=r"(r) : "r"(a), "r"(b));
    return r;
}
__device__ __forceinline__ float2 h2f2(uint32_t h) {
    __half2 hh = *reinterpret_cast<__half2*>(&h);
    return __half22float2(hh);
}

// ===========================================================================
// Merged prepass: blocks [0,592) convert x -> fp16; blocks [592, 592+4096)
// transpose one 32x32 W tile.
// ===========================================================================
#define PREP_XBLOCKS 592
__global__ void prep_kernel(const float* __restrict__ x,
                            __half* __restrict__ xh,
                            const float* __restrict__ Wq,
                            const float* __restrict__ Wk,
                            const float* __restrict__ Wv,
                            const float* __restrict__ Wo,
                            __half* __restrict__ Wt)
{
    __shared__ float sm[32][33];
    const int t = threadIdx.x;

    if (blockIdx.x < PREP_XBLOCKS) {
        const int n4 = M_ROWS * D_MODEL / 4;
        int i = blockIdx.x * 256 + t;
        const int stride = PREP_XBLOCKS * 256;
        for (; i < n4; i += stride) {
            float4 v = reinterpret_cast<const float4*>(x)[i];
            __half2 h0 = __floats2half2_rn(v.x, v.y);
            __half2 h1 = __floats2half2_rn(v.z, v.w);
            uint2 o = make_uint2(*(uint32_t*)&h0, *(uint32_t*)&h1);
            reinterpret_cast<uint2*>(xh)[i] = o;
        }
        return;
    }

    const int tl = blockIdx.x - PREP_XBLOCKS;
    const int z    = tl >> 10;
    const int tile = tl & 1023;
    const int n0 = (tile & 31) * 32;
    const int k0 = (tile >> 5) * 32;
    const float* W = (z == 0) ? Wq : (z == 1) ? Wk : (z == 2) ? Wv : Wo;
    __half* out = Wt + (size_t)z * D_MODEL * D_MODEL;

    {
        const int kl = t >> 3, nc = t & 7;
        float4 v = *reinterpret_cast<const float4*>(
            &W[(size_t)(k0 + kl) * D_MODEL + n0 + nc * 4]);
        sm[kl][nc * 4 + 0] = v.x; sm[kl][nc * 4 + 1] = v.y;
        sm[kl][nc * 4 + 2] = v.z; sm[kl][nc * 4 + 3] = v.w;
    }
    __syncthreads();
    {
        const int nl = t >> 3, kc = t & 7;
        __half2 h0 = __floats2half2_rn(sm[kc * 4 + 0][nl], sm[kc * 4 + 1][nl]);
        __half2 h1 = __floats2half2_rn(sm[kc * 4 + 2][nl], sm[kc * 4 + 3][nl]);
        uint2 o = make_uint2(*(uint32_t*)&h0, *(uint32_t*)&h1);
        *reinterpret_cast<uint2*>(
            &out[(size_t)(n0 + nl) * D_MODEL + k0 + kc * 4]) = o;
    }
}

// ===========================================================================
// FP16 GEMM: BK=64, 3-stage cp.async ring, 1 sync per K-tile, 16 iterations.
// BM=BN=128, 256 threads = 8 warps (2Mx4N).
// ===========================================================================
#define GSH 72
#define GT_HALVES (128 * GSH)
#define GEMM_SMEM_BYTES (6 * GT_HALVES * 2)   // 3 stages x (A + B), fp16

__device__ __forceinline__ void gemm_mainloop_f16(
    const __half* __restrict__ A, const __half* __restrict__ Wt,
    __half* As, __half* Bs, int brow, int bcol, float acc[4][4][4])
{
    const int tid  = threadIdx.x;
    const int lane = tid & 31;
    const int wid  = tid >> 5;
    const int warp_m = (wid & 1) * 64;
    const int warp_n = (wid >> 1) * 32;

    auto load_stage = [&](int k0, int buf) {
        __half* as = As + buf * GT_HALVES;
        __half* bs = Bs + buf * GT_HALVES;
        #pragma unroll
        for (int it = 0; it < 4; it++) {
            const int id = tid + it * 256;
            const int r = id >> 3, c8 = id & 7;
            cp_async16(&as[r * GSH + c8 * 8],
                       &A[(size_t)(brow + r) * D_MODEL + k0 + c8 * 8]);
        }
        #pragma unroll
        for (int it = 0; it < 4; it++) {
            const int id = tid + it * 256;
            const int r = id >> 3, c8 = id & 7;
            cp_async16(&bs[r * GSH + c8 * 8],
                       &Wt[(size_t)(bcol + r) * D_MODEL + k0 + c8 * 8]);
        }
        cp_commit();
    };

    load_stage(0, 0);
    load_stage(64, 1);

    for (int it = 0; it < 16; it++) {
        if (it + 1 < 16) cp_wait<1>(); else cp_wait<0>();
        __syncthreads();
        if (it + 2 < 16) load_stage((it + 2) * 64, (it + 2) % 3);

        const __half* as = As + (it % 3) * GT_HALVES;
        const __half* bs = Bs + (it % 3) * GT_HALVES;

        uint32_t bf[4][8];
        #pragma unroll
        for (int nf = 0; nf < 4; nf++) {
            const int row = warp_n + nf * 8 + (lane & 7);
            const int kc  = (lane >> 3) * 8;
            ldsm_x4(bf[nf][0], bf[nf][1], bf[nf][2], bf[nf][3],
                    sptr(&bs[row * GSH + kc]));
            ldsm_x4(bf[nf][4], bf[nf][5], bf[nf][6], bf[nf][7],
                    sptr(&bs[row * GSH + 32 + kc]));
        }
        #pragma unroll
        for (int ks = 0; ks < 4; ks++) {
            uint32_t af[4][4];
            #pragma unroll
            for (int mf = 0; mf < 4; mf++) {
                const int row = warp_m + mf * 16 + (lane & 15);
                const int kc  = ks * 16 + (lane >> 4) * 8;
                ldsm_x4(af[mf][0], af[mf][1], af[mf][2], af[mf][3],
                        sptr(&as[row * GSH + kc]));
            }
            #pragma unroll
            for (int mf = 0; mf < 4; mf++)
                #pragma unroll
                for (int nf = 0; nf < 4; nf++)
                    mma_f16(acc[mf][nf], af[mf], &bf[nf][ks * 2]);
        }
    }
    __syncthreads();
}

// ---- Fused QKV projection: Q/K head layout; V written transposed [d][t] ----
__global__ __launch_bounds__(256, 2)
void qkv_gemm_kernel(const __half* __restrict__ A,  const __half* __restrict__ Wt,
                     const float* __restrict__ bq, const float* __restrict__ bk,
                     const float* __restrict__ bv,
                     __half* __restrict__ Qo, __half* __restrict__ Ko,
                     __half* __restrict__ Vto)
{
    extern __shared__ __half smh[];
    __half* As = smh;
    __half* Bs = smh + 3 * GT_HALVES;

    const int wsel = blockIdx.x >> 3;
    const int bcol = (blockIdx.x & 7) * 128;
    const int brow = blockIdx.y * 128;
    const __half* W   = Wt + (size_t)wsel * D_MODEL * D_MODEL;
    const float* bias = (wsel == 0) ? bq : (wsel == 1) ? bk : bv;
    const float scale = (wsel == 0) ? QSCALE : 1.0f;

    float acc[4][4][4];
    #pragma unroll
    for (int mf = 0; mf < 4; mf++)
        #pragma unroll
        for (int nf = 0; nf < 4; nf++)
            #pragma unroll
            for (int c = 0; c < 4; c++) acc[mf][nf][c] = 0.0f;

    gemm_mainloop_f16(A, W, As, Bs, brow, bcol, acc);

    const int lane = threadIdx.x & 31;
    const int g  = lane >> 2, t4 = lane & 3;
    const int wid = threadIdx.x >> 5;
    const int warp_m = (wid & 1) * 64, warp_n = (wid >> 1) * 32;

    #pragma unroll
    for (int mf = 0; mf < 4; mf++) {
        #pragma unroll
        for (int nf = 0; nf < 4; nf++) {
            const int col = bcol + warp_n + nf * 8 + 2 * t4;
            const float b0 = bias[col], b1 = bias[col + 1];
            #pragma unroll
            for (int rr = 0; rr < 2; rr++) {
                const int row = brow + warp_m + mf * 16 + g + rr * 8;
                const float v0 = (acc[mf][nf][rr * 2 + 0] + b0) * scale;
                const float v1 = (acc[mf][nf][rr * 2 + 1] + b1) * scale;
                const int bb = row >> 11, tt = row & (T_SEQ - 1);
                const int hh = col >> 6,  dd = col & 63;
                const int bh = bb * N_HEADS + hh;
                if (wsel == 2) {
                    Vto[((size_t)bh * 64 + dd)     * T_SEQ + tt] = __float2half_rn(v0);
                    Vto[((size_t)bh * 64 + dd + 1) * T_SEQ + tt] = __float2half_rn(v1);
                } else {
                    __half* C = (wsel == 0) ? Qo : Ko;
                    *reinterpret_cast<__half2*>(
                        &C[((size_t)bh * T_SEQ + tt) * D_HEAD + dd]) =
                        __floats2half2_rn(v0, v1);
                }
            }
        }
    }
}

// ---- Output projection (A fp16, output fp32) ----
__global__ __launch_bounds__(256, 2)
void out_gemm_kernel(const __half* __restrict__ A, const __half* __restrict__ Wt,
                     const float* __restrict__ bias, float* __restrict__ C)
{
    extern __shared__ __half smh[];
    __half* As = smh;
    __half* Bs = smh + 3 * GT_HALVES;

    const int bcol = blockIdx.x * 128;
    const int brow = blockIdx.y * 128;

    float acc[4][4][4];
    #pragma unroll
    for (int mf = 0; mf < 4; mf++)
        #pragma unroll
        for (int nf = 0; nf < 4; nf++)
            #pragma unroll
            for (int c = 0; c < 4; c++) acc[mf][nf][c] = 0.0f;

    gemm_mainloop_f16(A, Wt, As, Bs, brow, bcol, acc);

    const int lane = threadIdx.x & 31;
    const int g  = lane >> 2, t4 = lane & 3;
    const int wid = threadIdx.x >> 5;
    const int warp_m = (wid & 1) * 64, warp_n = (wid >> 1) * 32;

    #pragma unroll
    for (int mf = 0; mf < 4; mf++) {
        #pragma unroll
        for (int nf = 0; nf < 4; nf++) {
            const int col = bcol + warp_n + nf * 8 + 2 * t4;
            const float b0 = bias[col], b1 = bias[col + 1];
            #pragma unroll
            for (int rr = 0; rr < 2; rr++) {
                const int row = brow + warp_m + mf * 16 + g + rr * 8;
                float* p = &C[(size_t)row * D_MODEL + col];
                p[0] = acc[mf][nf][rr * 2 + 0] + b0;
                p[1] = acc[mf][nf][rr * 2 + 1] + b1;
            }
        }
    }
}

// ===========================================================================
// FP16 flash attention (causal), hardware-ex2 half2 softmax, warp tile-skip.
// BQ=128, BKV=64, 256 thr, 2 CTA/SM. Stats in registers, P register-direct.
// ===========================================================================
#define ASH 72
#define QT_H (128 * ASH)
#define KT_H (64 * ASH)
#define ATTN_SMEM_BYTES ((QT_H + 6 * KT_H) * 2)

__global__ __launch_bounds__(256, 2)
void attn_mma_kernel(const __half* __restrict__ Qh,
                     const __half* __restrict__ Kh,
                     const __half* __restrict__ Vth,
                     __half* __restrict__ out)
{
    extern __shared__ __half smh[];
    __half* Qs  = smh;
    __half* Kb0 = smh + QT_H;
    __half* Vb0 = smh + QT_H + 3 * KT_H;

    const int tid  = threadIdx.x;
    const int lane = tid & 31;
    const int wr   = tid >> 5;
    const int g    = lane >> 2;
    const int t4   = lane & 3;

    const int bx = gridDim.x - 1 - blockIdx.x;
    const int bh = blockIdx.y;
    const int b  = bh >> 4;
    const int h  = bh & 15;
    const int q0 = bx * 128;

    const __half* Qb = Qh  + (size_t)bh * T_SEQ * D_HEAD;
    const __half* Kb = Kh  + (size_t)bh * T_SEQ * D_HEAD;
    const __half* Vb = Vth + (size_t)bh * D_HEAD * T_SEQ;

    auto load_q = [&]() {
        #pragma unroll
        for (int it = 0; it < 4; it++) {
            const int id = tid + it * 256;
            const int r = id >> 3, c8 = id & 7;
            cp_async16(&Qs[r * ASH + c8 * 8], &Qb[(size_t)(q0 + r) * 64 + c8 * 8]);
        }
    };
    auto load_k = [&](int k0, int buf) {
        __half* d = Kb0 + buf * KT_H;
        #pragma unroll
        for (int it = 0; it < 2; it++) {
            const int id = tid + it * 256;
            const int r = id >> 3, c8 = id & 7;
            cp_async16(&d[r * ASH + c8 * 8], &Kb[(size_t)(k0 + r) * 64 + c8 * 8]);
        }
    };
    auto load_v = [&](int k0, int buf) {
        __half* dv = Vb0 + buf * KT_H;
        #pragma unroll
        for (int it = 0; it < 2; it++) {
            const int id = tid + it * 256;
            const int r = id >> 3, c8 = id & 7;
            cp_async16(&dv[r * ASH + c8 * 8], &Vb[(size_t)r * T_SEQ + k0 + c8 * 8]);
        }
    };

    const int nkt = 2 * bx + 2;
    load_q(); load_k(0, 0); load_v(0, 0); cp_commit();
    if (nkt > 1) { load_k(64, 1); load_v(64, 1); cp_commit(); }

    float m0 = -1e30f, m1 = -1e30f, l0 = 0.0f, l1 = 0.0f;
    float o_acc[8][4];
    #pragma unroll
    for (int nf = 0; nf < 8; nf++)
        #pragma unroll
        for (int c = 0; c < 4; c++) o_acc[nf][c] = 0.0f;

    const int r0 = wr * 16 + g;
    const int r1 = r0 + 8;
    const int row_hi = q0 + wr * 16 + 15;

    for (int kt = 0; kt < nkt; kt++) {
        if (kt + 1 < nkt) cp_wait<1>(); else cp_wait<0>();
        __syncthreads();
        if (kt + 2 < nkt) {
            load_k((kt + 2) * 64, (kt + 2) % 3);
            load_v((kt + 2) * 64, (kt + 2) % 3);
            cp_commit();
        }

        const int k0 = kt * 64;
        if (k0 > row_hi) continue;   // whole tile causally masked for this warp

        const __half* Ks = Kb0 + (kt % 3) * KT_H;
        const __half* Vs = Vb0 + (kt % 3) * KT_H;

        float s[8][4];
        #pragma unroll
        for (int nf = 0; nf < 8; nf++)
            #pragma unroll
            for (int c = 0; c < 4; c++) s[nf][c] = 0.0f;

        #pragma unroll
        for (int ks = 0; ks < 4; ks++) {
            uint32_t qf[4];
            ldsm_x4(qf[0], qf[1], qf[2], qf[3],
                    sptr(&Qs[(wr * 16 + (lane & 15)) * ASH
                             + ks * 16 + (lane >> 4) * 8]));
            #pragma unroll
            for (int nh = 0; nh < 2; nh++) {
                const int rr = nh * 32 + (lane >> 3) * 8 + (lane & 7);
                uint32_t blo[4], bhi[4];
                ldsm_x4(blo[0], blo[1], blo[2], blo[3],
                        sptr(&Ks[rr * ASH + ks * 16]));
                ldsm_x4(bhi[0], bhi[1], bhi[2], bhi[3],
                        sptr(&Ks[rr * ASH + ks * 16 + 8]));
                #pragma unroll
                for (int m = 0; m < 4; m++) {
                    uint32_t bfr[2] = {blo[m], bhi[m]};
                    mma_f16(s[nh * 4 + m], qf, bfr);
                }
            }
        }

        if (k0 + 63 > q0 + wr * 16) {
            #pragma unroll
            for (int nf = 0; nf < 8; nf++) {
                const int c0 = k0 + nf * 8 + 2 * t4;
                if (c0     > q0 + r0) s[nf][0] = -1e30f;
                if (c0 + 1 > q0 + r0) s[nf][1] = -1e30f;
                if (c0     > q0 + r1) s[nf][2] = -1e30f;
                if (c0 + 1 > q0 + r1) s[nf][3] = -1e30f;
            }
        }

        float pm0 = -1e30f, pm1 = -1e30f;
        #pragma unroll
        for (int nf = 0; nf < 8; nf++) {
            pm0 = fmaxf(pm0, fmaxf(s[nf][0], s[nf][1]));
            pm1 = fmaxf(pm1, fmaxf(s[nf][2], s[nf][3]));
        }
        pm0 = fmaxf(pm0, __shfl_xor_sync(0xffffffffu, pm0, 1));
        pm0 = fmaxf(pm0, __shfl_xor_sync(0xffffffffu, pm0, 2));
        pm1 = fmaxf(pm1, __shfl_xor_sync(0xffffffffu, pm1, 1));
        pm1 = fmaxf(pm1, __shfl_xor_sync(0xffffffffu, pm1, 2));

        const float mn0 = fmaxf(m0, pm0);
        const float mn1 = fmaxf(m1, pm1);
        const float sc0 = fex2(m0 - mn0);
        const float sc1 = fex2(m1 - mn1);
        m0 = mn0; m1 = mn1;

        // ---- half2 exp + half2 partial sums (2 interleaved accumulators) ----
        uint32_t pa[4][4];
        uint32_t a0a = 0u, a0b = 0u, a1a = 0u, a1b = 0u;
        #pragma unroll
        for (int m = 0; m < 4; m++) {
            #pragma unroll
            for (int j = 0; j < 2; j++) {
                const int nf = 2 * m + j;
                const uint32_t d0 = packh2(s[nf][0] - mn0, s[nf][1] - mn0);
                const uint32_t d1 = packh2(s[nf][2] - mn1, s[nf][3] - mn1);
                const uint32_t e0 = h2exp2(d0);
                const uint32_t e1 = h2exp2(d1);
                pa[m][j * 2 + 0] = e0;
                pa[m][j * 2 + 1] = e1;
                if (j) { a0b = hadd2(a0b, e0); a1b = hadd2(a1b, e1); }
                else   { a0a = hadd2(a0a, e0); a1a = hadd2(a1a, e1); }
            }
        }
        float2 f0a = h2f2(a0a), f0b = h2f2(a0b);
        float2 f1a = h2f2(a1a), f1b = h2f2(a1b);
        float sum0 = (f0a.x + f0a.y) + (f0b.x + f0b.y);
        float sum1 = (f1a.x + f1a.y) + (f1b.x + f1b.y);

        sum0 += __shfl_xor_sync(0xffffffffu, sum0, 1);
        sum0 += __shfl_xor_sync(0xffffffffu, sum0, 2);
        sum1 += __shfl_xor_sync(0xffffffffu, sum1, 1);
        sum1 += __shfl_xor_sync(0xffffffffu, sum1, 2);
        l0 = l0 * sc0 + sum0;
        l1 = l1 * sc1 + sum1;

        #pragma unroll
        for (int nf = 0; nf < 8; nf++) {
            o_acc[nf][0] *= sc0; o_acc[nf][1] *= sc0;
            o_acc[nf][2] *= sc1; o_acc[nf][3] *= sc1;
        }

        #pragma unroll
        for (int m = 0; m < 4; m++) {
            #pragma unroll
            for (int nh = 0; nh < 2; nh++) {
                const int rr = nh * 32 + (lane >> 3) * 8 + (lane & 7);
                uint32_t blo[4], bhi[4];
                ldsm_x4(blo[0], blo[1], blo[2], blo[3],
                        sptr(&Vs[rr * ASH + m * 16]));
                ldsm_x4(bhi[0], bhi[1], bhi[2], bhi[3],
                        sptr(&Vs[rr * ASH + m * 16 + 8]));
                #pragma unroll
                for (int mm = 0; mm < 4; mm++) {
                    uint32_t bfr[2] = {blo[mm], bhi[mm]};
                    mma_f16(o_acc[nh * 4 + mm], pa[m], bfr);
                }
            }
        }
    }

    const float il0 = 1.0f / l0;
    const float il1 = 1.0f / l1;
    #pragma unroll
    for (int nf = 0; nf < 8; nf++) {
        const int d = nf * 8 + 2 * t4;
        *reinterpret_cast<__half2*>(
            &out[((size_t)(b * T_SEQ + q0 + r0)) * D_MODEL + h * 64 + d]) =
            __floats2half2_rn(o_acc[nf][0] * il0, o_acc[nf][1] * il0);
        *reinterpret_cast<__half2*>(
            &out[((size_t)(b * T_SEQ + q0 + r1)) * D_MODEL + h * 64 + d]) =
            __floats2half2_rn(o_acc[nf][2] * il1, o_acc[nf][3] * il1);
    }
}

// ---------------------------------------------------------------------------
extern "C" void kernel_launch(void* const* d_in, const int* in_sizes, int n_in,
                              void* d_out, int out_size)
{
    const float* x  = (const float*)d_in[0];
    const float* Wq = (const float*)d_in[1];
    const float* bq = (const float*)d_in[2];
    const float* Wk = (const float*)d_in[3];
    const float* bk = (const float*)d_in[4];
    const float* Wv = (const float*)d_in[5];
    const float* bv = (const float*)d_in[6];
    const float* Wo = (const float*)d_in[7];
    const float* bo = (const float*)d_in[8];
    float* out = (float*)d_out;

    __half *Q, *K, *Vt, *attn, *xh, *Wt;
    cudaGetSymbolAddress((void**)&Q, g_Q);
    cudaGetSymbolAddress((void**)&K, g_K);
    cudaGetSymbolAddress((void**)&Vt, g_Vt);
    cudaGetSymbolAddress((void**)&attn, g_attn);
    cudaGetSymbolAddress((void**)&xh, g_xh);
    cudaGetSymbolAddress((void**)&Wt, g_Wt);
    __half* Wot = Wt + (size_t)3 * D_MODEL * D_MODEL;

    cudaFuncSetAttribute(qkv_gemm_kernel,
                         cudaFuncAttributeMaxDynamicSharedMemorySize,
                         GEMM_SMEM_BYTES);
    cudaFuncSetAttribute(out_gemm_kernel,
                         cudaFuncAttributeMaxDynamicSharedMemorySize,
                         GEMM_SMEM_BYTES);
    cudaFuncSetAttribute(attn_mma_kernel,
                         cudaFuncAttributeMaxDynamicSharedMemorySize,
                         ATTN_SMEM_BYTES);

    prep_kernel<<<PREP_XBLOCKS + 4096, 256>>>(x, xh, Wq, Wk, Wv, Wo, Wt);

    qkv_gemm_kernel<<<dim3(24, 32), 256, GEMM_SMEM_BYTES>>>(
        xh, Wt, bq, bk, bv, Q, K, Vt);

    attn_mma_kernel<<<dim3(T_SEQ / 128, B_SIZE * N_HEADS), 256,
                      ATTN_SMEM_BYTES>>>(Q, K, Vt, attn);

    out_gemm_kernel<<<dim3(8, 32), 256, GEMM_SMEM_BYTES>>>(attn, Wot, bo, out);
}

// round 17
// speedup vs baseline: 2.5228x; 1.0305x over previous
#include <cuda_runtime.h>
#include <cuda_fp16.h>
#include <cstdint>

#define D_MODEL 1024
#define N_HEADS 16
#define D_HEAD  64
#define B_SIZE  2
#define T_SEQ   2048
#define M_ROWS  (B_SIZE * T_SEQ)   // 4096

#define QSCALE 0.1803368801111204f   // 0.125 * log2(e)

__device__ __half g_Q[M_ROWS * D_MODEL];      // [B,H,T,64], scaled 0.125*log2e
__device__ __half g_K[M_ROWS * D_MODEL];      // [B,H,T,64]
__device__ __half g_Vt[M_ROWS * D_MODEL];     // [B,H,64,T]
__device__ __half g_attn[M_ROWS * D_MODEL];   // [B,T,1024]
__device__ __half g_xh[M_ROWS * D_MODEL];     // x as fp16
__device__ __half g_Wt[4][D_MODEL * D_MODEL]; // W^T: [n][k], fp16

// ===========================================================================
__device__ __forceinline__ uint32_t sptr(const void* p) {
    return (uint32_t)__cvta_generic_to_shared(p);
}
__device__ __forceinline__ void ldsm_x4(uint32_t& r0, uint32_t& r1,
                                        uint32_t& r2, uint32_t& r3,
                                        uint32_t addr) {
    asm volatile("ldmatrix.sync.aligned.m8n8.x4.shared.b16 {%0,%1,%2,%3},[%4];"
                 : "=r"(r0), "=r"(r1), "=r"(r2), "=r"(r3) : "r"(addr));
}
__device__ __forceinline__ void mma_f16(float c[4], const uint32_t a[4],
                                        const uint32_t b[2]) {
    asm volatile(
        "mma.sync.aligned.m16n8k16.row.col.f32.f16.f16.f32 "
        "{%0,%1,%2,%3}, {%4,%5,%6,%7}, {%8,%9}, {%0,%1,%2,%3};"
        : "+f"(c[0]), "+f"(c[1]), "+f"(c[2]), "+f"(c[3])
        : "r"(a[0]), "r"(a[1]), "r"(a[2]), "r"(a[3]), "r"(b[0]), "r"(b[1]));
}
__device__ __forceinline__ void cp_async16(void* dst_smem, const void* src) {
    uint32_t d = (uint32_t)__cvta_generic_to_shared(dst_smem);
    asm volatile("cp.async.cg.shared.global [%0], [%1], 16;" :: "r"(d), "l"(src));
}
__device__ __forceinline__ void cp_commit() { asm volatile("cp.async.commit_group;"); }
template <int N>
__device__ __forceinline__ void cp_wait() {
    asm volatile("cp.async.wait_group %0;" :: "n"(N));
}
__device__ __forceinline__ uint32_t packh2(float a, float b) {
    __half2 h = __floats2half2_rn(a, b);
    return *reinterpret_cast<uint32_t*>(&h);
}
__device__ __forceinline__ uint32_t h2exp2(uint32_t x) {
    uint32_t r;
    asm volatile("ex2.approx.f16x2 %0, %1;" : "=r"(r) : "r"(x));
    return r;
}
__device__ __forceinline__ float fex2(float x) {
    float r;
    asm volatile("ex2.approx.ftz.f32 %0, %1;" : "=f"(r) : "f"(x));
    return r;
}
__device__ __forceinline__ uint32_t hadd2(uint32_t a, uint32_t b) {
    uint32_t r;
    asm volatile("add.f16x2 %0, %1, %2;" : "=r"(r) : "r"(a), "r"(b));
    return r;
}
__device__ __forceinline__ float2 h2f2(uint32_t h) {
    __half2 hh = *reinterpret_cast<__half2*>(&h);
    return __half22float2(hh);
}

// ===========================================================================
// Merged prepass (unchanged from R16)
// ===========================================================================
#define PREP_XBLOCKS 592
__global__ void prep_kernel(const float* __restrict__ x,
                            __half* __restrict__ xh,
                            const float* __restrict__ Wq,
                            const float* __restrict__ Wk,
                            const float* __restrict__ Wv,
                            const float* __restrict__ Wo,
                            __half* __restrict__ Wt)
{
    __shared__ float sm[32][33];
    const int t = threadIdx.x;

    if (blockIdx.x < PREP_XBLOCKS) {
        const int n4 = M_ROWS * D_MODEL / 4;
        int i = blockIdx.x * 256 + t;
        const int stride = PREP_XBLOCKS * 256;
        for (; i < n4; i += stride) {
            float4 v = reinterpret_cast<const float4*>(x)[i];
            __half2 h0 = __floats2half2_rn(v.x, v.y);
            __half2 h1 = __floats2half2_rn(v.z, v.w);
            uint2 o = make_uint2(*(uint32_t*)&h0, *(uint32_t*)&h1);
            reinterpret_cast<uint2*>(xh)[i] = o;
        }
        return;
    }

    const int tl = blockIdx.x - PREP_XBLOCKS;
    const int z    = tl >> 10;
    const int tile = tl & 1023;
    const int n0 = (tile & 31) * 32;
    const int k0 = (tile >> 5) * 32;
    const float* W = (z == 0) ? Wq : (z == 1) ? Wk : (z == 2) ? Wv : Wo;
    __half* out = Wt + (size_t)z * D_MODEL * D_MODEL;

    {
        const int kl = t >> 3, nc = t & 7;
        float4 v = *reinterpret_cast<const float4*>(
            &W[(size_t)(k0 + kl) * D_MODEL + n0 + nc * 4]);
        sm[kl][nc * 4 + 0] = v.x; sm[kl][nc * 4 + 1] = v.y;
        sm[kl][nc * 4 + 2] = v.z; sm[kl][nc * 4 + 3] = v.w;
    }
    __syncthreads();
    {
        const int nl = t >> 3, kc = t & 7;
        __half2 h0 = __floats2half2_rn(sm[kc * 4 + 0][nl], sm[kc * 4 + 1][nl]);
        __half2 h1 = __floats2half2_rn(sm[kc * 4 + 2][nl], sm[kc * 4 + 3][nl]);
        uint2 o = make_uint2(*(uint32_t*)&h0, *(uint32_t*)&h1);
        *reinterpret_cast<uint2*>(
            &out[(size_t)(n0 + nl) * D_MODEL + k0 + kc * 4]) = o;
    }
}

// ===========================================================================
// FP16 GEMM (unchanged from R16): BK=64, 3-stage ring, 1 sync/K-tile.
// ===========================================================================
#define GSH 72
#define GT_HALVES (128 * GSH)
#define GEMM_SMEM_BYTES (6 * GT_HALVES * 2)

__device__ __forceinline__ void gemm_mainloop_f16(
    const __half* __restrict__ A, const __half* __restrict__ Wt,
    __half* As, __half* Bs, int brow, int bcol, float acc[4][4][4])
{
    const int tid  = threadIdx.x;
    const int lane = tid & 31;
    const int wid  = tid >> 5;
    const int warp_m = (wid & 1) * 64;
    const int warp_n = (wid >> 1) * 32;

    auto load_stage = [&](int k0, int buf) {
        __half* as = As + buf * GT_HALVES;
        __half* bs = Bs + buf * GT_HALVES;
        #pragma unroll
        for (int it = 0; it < 4; it++) {
            const int id = tid + it * 256;
            const int r = id >> 3, c8 = id & 7;
            cp_async16(&as[r * GSH + c8 * 8],
                       &A[(size_t)(brow + r) * D_MODEL + k0 + c8 * 8]);
        }
        #pragma unroll
        for (int it = 0; it < 4; it++) {
            const int id = tid + it * 256;
            const int r = id >> 3, c8 = id & 7;
            cp_async16(&bs[r * GSH + c8 * 8],
                       &Wt[(size_t)(bcol + r) * D_MODEL + k0 + c8 * 8]);
        }
        cp_commit();
    };

    load_stage(0, 0);
    load_stage(64, 1);

    for (int it = 0; it < 16; it++) {
        if (it + 1 < 16) cp_wait<1>(); else cp_wait<0>();
        __syncthreads();
        if (it + 2 < 16) load_stage((it + 2) * 64, (it + 2) % 3);

        const __half* as = As + (it % 3) * GT_HALVES;
        const __half* bs = Bs + (it % 3) * GT_HALVES;

        uint32_t bf[4][8];
        #pragma unroll
        for (int nf = 0; nf < 4; nf++) {
            const int row = warp_n + nf * 8 + (lane & 7);
            const int kc  = (lane >> 3) * 8;
            ldsm_x4(bf[nf][0], bf[nf][1], bf[nf][2], bf[nf][3],
                    sptr(&bs[row * GSH + kc]));
            ldsm_x4(bf[nf][4], bf[nf][5], bf[nf][6], bf[nf][7],
                    sptr(&bs[row * GSH + 32 + kc]));
        }
        #pragma unroll
        for (int ks = 0; ks < 4; ks++) {
            uint32_t af[4][4];
            #pragma unroll
            for (int mf = 0; mf < 4; mf++) {
                const int row = warp_m + mf * 16 + (lane & 15);
                const int kc  = ks * 16 + (lane >> 4) * 8;
                ldsm_x4(af[mf][0], af[mf][1], af[mf][2], af[mf][3],
                        sptr(&as[row * GSH + kc]));
            }
            #pragma unroll
            for (int mf = 0; mf < 4; mf++)
                #pragma unroll
                for (int nf = 0; nf < 4; nf++)
                    mma_f16(acc[mf][nf], af[mf], &bf[nf][ks * 2]);
        }
    }
    __syncthreads();
}

// ---- Fused QKV projection (unchanged) ----
__global__ __launch_bounds__(256, 2)
void qkv_gemm_kernel(const __half* __restrict__ A,  const __half* __restrict__ Wt,
                     const float* __restrict__ bq, const float* __restrict__ bk,
                     const float* __restrict__ bv,
                     __half* __restrict__ Qo, __half* __restrict__ Ko,
                     __half* __restrict__ Vto)
{
    extern __shared__ __half smh[];
    __half* As = smh;
    __half* Bs = smh + 3 * GT_HALVES;

    const int wsel = blockIdx.x >> 3;
    const int bcol = (blockIdx.x & 7) * 128;
    const int brow = blockIdx.y * 128;
    const __half* W   = Wt + (size_t)wsel * D_MODEL * D_MODEL;
    const float* bias = (wsel == 0) ? bq : (wsel == 1) ? bk : bv;
    const float scale = (wsel == 0) ? QSCALE : 1.0f;

    float acc[4][4][4];
    #pragma unroll
    for (int mf = 0; mf < 4; mf++)
        #pragma unroll
        for (int nf = 0; nf < 4; nf++)
            #pragma unroll
            for (int c = 0; c < 4; c++) acc[mf][nf][c] = 0.0f;

    gemm_mainloop_f16(A, W, As, Bs, brow, bcol, acc);

    const int lane = threadIdx.x & 31;
    const int g  = lane >> 2, t4 = lane & 3;
    const int wid = threadIdx.x >> 5;
    const int warp_m = (wid & 1) * 64, warp_n = (wid >> 1) * 32;

    #pragma unroll
    for (int mf = 0; mf < 4; mf++) {
        #pragma unroll
        for (int nf = 0; nf < 4; nf++) {
            const int col = bcol + warp_n + nf * 8 + 2 * t4;
            const float b0 = bias[col], b1 = bias[col + 1];
            #pragma unroll
            for (int rr = 0; rr < 2; rr++) {
                const int row = brow + warp_m + mf * 16 + g + rr * 8;
                const float v0 = (acc[mf][nf][rr * 2 + 0] + b0) * scale;
                const float v1 = (acc[mf][nf][rr * 2 + 1] + b1) * scale;
                const int bb = row >> 11, tt = row & (T_SEQ - 1);
                const int hh = col >> 6,  dd = col & 63;
                const int bh = bb * N_HEADS + hh;
                if (wsel == 2) {
                    Vto[((size_t)bh * 64 + dd)     * T_SEQ + tt] = __float2half_rn(v0);
                    Vto[((size_t)bh * 64 + dd + 1) * T_SEQ + tt] = __float2half_rn(v1);
                } else {
                    __half* C = (wsel == 0) ? Qo : Ko;
                    *reinterpret_cast<__half2*>(
                        &C[((size_t)bh * T_SEQ + tt) * D_HEAD + dd]) =
                        __floats2half2_rn(v0, v1);
                }
            }
        }
    }
}

// ---- Output projection (unchanged) ----
__global__ __launch_bounds__(256, 2)
void out_gemm_kernel(const __half* __restrict__ A, const __half* __restrict__ Wt,
                     const float* __restrict__ bias, float* __restrict__ C)
{
    extern __shared__ __half smh[];
    __half* As = smh;
    __half* Bs = smh + 3 * GT_HALVES;

    const int bcol = blockIdx.x * 128;
    const int brow = blockIdx.y * 128;

    float acc[4][4][4];
    #pragma unroll
    for (int mf = 0; mf < 4; mf++)
        #pragma unroll
        for (int nf = 0; nf < 4; nf++)
            #pragma unroll
            for (int c = 0; c < 4; c++) acc[mf][nf][c] = 0.0f;

    gemm_mainloop_f16(A, Wt, As, Bs, brow, bcol, acc);

    const int lane = threadIdx.x & 31;
    const int g  = lane >> 2, t4 = lane & 3;
    const int wid = threadIdx.x >> 5;
    const int warp_m = (wid & 1) * 64, warp_n = (wid >> 1) * 32;

    #pragma unroll
    for (int mf = 0; mf < 4; mf++) {
        #pragma unroll
        for (int nf = 0; nf < 4; nf++) {
            const int col = bcol + warp_n + nf * 8 + 2 * t4;
            const float b0 = bias[col], b1 = bias[col + 1];
            #pragma unroll
            for (int rr = 0; rr < 2; rr++) {
                const int row = brow + warp_m + mf * 16 + g + rr * 8;
                float* p = &C[(size_t)row * D_MODEL + col];
                p[0] = acc[mf][nf][rr * 2 + 0] + b0;
                p[1] = acc[mf][nf][rr * 2 + 1] + b1;
            }
        }
    }
}

// ===========================================================================
// FP16 flash attention v3 (causal). BQ=64, BKV=64, 128 threads (4 warps),
// 4 CTAs/SM. Q fragments hoisted to registers; 2-buffer K/V rings with
// post-sync distance-1 prefetch; hardware-ex2 half2 softmax; ballot-guarded
// O rescale. Only the final tile needs causal masking.
// ===========================================================================
#define ASH 72
#define AQT_H (64 * ASH)                       // 4608 halves per 64x64 tile
#define ATTN_SMEM_BYTES ((5 * AQT_H) * 2)      // Q + 2K + 2V = 46080 B

__global__ __launch_bounds__(128, 4)
void attn_mma_kernel(const __half* __restrict__ Qh,
                     const __half* __restrict__ Kh,
                     const __half* __restrict__ Vth,
                     __half* __restrict__ out)
{
    extern __shared__ __half smh[];
    __half* Qs  = smh;
    __half* Kb0 = smh + AQT_H;
    __half* Vb0 = smh + 3 * AQT_H;

    const int tid  = threadIdx.x;
    const int lane = tid & 31;
    const int wr   = tid >> 5;                 // 0..3
    const int g    = lane >> 2;
    const int t4   = lane & 3;

    const int bx = gridDim.x - 1 - blockIdx.x; // heavy blocks first
    const int bh = blockIdx.y;
    const int b  = bh >> 4;
    const int h  = bh & 15;
    const int q0 = bx * 64;

    const __half* Qb = Qh  + (size_t)bh * T_SEQ * D_HEAD;
    const __half* Kb = Kh  + (size_t)bh * T_SEQ * D_HEAD;
    const __half* Vb = Vth + (size_t)bh * D_HEAD * T_SEQ;

    auto load_q = [&]() {
        #pragma unroll
        for (int it = 0; it < 4; it++) {
            const int id = tid + it * 128;
            const int r = id >> 3, c8 = id & 7;
            cp_async16(&Qs[r * ASH + c8 * 8], &Qb[(size_t)(q0 + r) * 64 + c8 * 8]);
        }
    };
    auto load_k = [&](int k0, int buf) {
        __half* d = Kb0 + buf * AQT_H;
        #pragma unroll
        for (int it = 0; it < 4; it++) {
            const int id = tid + it * 128;
            const int r = id >> 3, c8 = id & 7;
            cp_async16(&d[r * ASH + c8 * 8], &Kb[(size_t)(k0 + r) * 64 + c8 * 8]);
        }
    };
    auto load_v = [&](int k0, int buf) {
        __half* dv = Vb0 + buf * AQT_H;
        #pragma unroll
        for (int it = 0; it < 4; it++) {
            const int id = tid + it * 128;
            const int r = id >> 3, c8 = id & 7;   // r = d
            cp_async16(&dv[r * ASH + c8 * 8], &Vb[(size_t)r * T_SEQ + k0 + c8 * 8]);
        }
    };

    const int nkt = bx + 1;
    load_q(); load_k(0, 0); load_v(0, 0); cp_commit();
    cp_wait<0>();
    __syncthreads();

    // ---- hoist Q fragments (loop-invariant) ----
    uint32_t qf[4][4];
    #pragma unroll
    for (int ks = 0; ks < 4; ks++)
        ldsm_x4(qf[ks][0], qf[ks][1], qf[ks][2], qf[ks][3],
                sptr(&Qs[(wr * 16 + (lane & 15)) * ASH
                         + ks * 16 + (lane >> 4) * 8]));

    float m0 = -1e30f, m1 = -1e30f, l0 = 0.0f, l1 = 0.0f;
    float o_acc[8][4];
    #pragma unroll
    for (int nf = 0; nf < 8; nf++)
        #pragma unroll
        for (int c = 0; c < 4; c++) o_acc[nf][c] = 0.0f;

    const int r0 = wr * 16 + g;
    const int r1 = r0 + 8;

    for (int kt = 0; kt < nkt; kt++) {
        if (kt > 0) {
            cp_wait<0>();
            __syncthreads();
        }
        // post-sync prefetch into the buffer consumed at kt-1 (hazard-free)
        if (kt + 1 < nkt) {
            load_k((kt + 1) * 64, (kt + 1) & 1);
            load_v((kt + 1) * 64, (kt + 1) & 1);
            cp_commit();
        }
        const __half* Ks = Kb0 + (kt & 1) * AQT_H;
        const __half* Vs = Vb0 + (kt & 1) * AQT_H;

        // ---- S = Q K^T ----
        float s[8][4];
        #pragma unroll
        for (int nf = 0; nf < 8; nf++)
            #pragma unroll
            for (int c = 0; c < 4; c++) s[nf][c] = 0.0f;

        #pragma unroll
        for (int ks = 0; ks < 4; ks++) {
            #pragma unroll
            for (int nh = 0; nh < 2; nh++) {
                const int rr = nh * 32 + (lane >> 3) * 8 + (lane & 7);
                uint32_t blo[4], bhi[4];
                ldsm_x4(blo[0], blo[1], blo[2], blo[3],
                        sptr(&Ks[rr * ASH + ks * 16]));
                ldsm_x4(bhi[0], bhi[1], bhi[2], bhi[3],
                        sptr(&Ks[rr * ASH + ks * 16 + 8]));
                #pragma unroll
                for (int m = 0; m < 4; m++) {
                    uint32_t bfr[2] = {blo[m], bhi[m]};
                    mma_f16(s[nh * 4 + m], qf[ks], bfr);
                }
            }
        }

        // ---- causal mask: only the final tile touches the diagonal ----
        if (kt == nkt - 1) {
            const int k0 = kt * 64;
            #pragma unroll
            for (int nf = 0; nf < 8; nf++) {
                const int c0 = k0 + nf * 8 + 2 * t4;
                if (c0     > q0 + r0) s[nf][0] = -1e30f;
                if (c0 + 1 > q0 + r0) s[nf][1] = -1e30f;
                if (c0     > q0 + r1) s[nf][2] = -1e30f;
                if (c0 + 1 > q0 + r1) s[nf][3] = -1e30f;
            }
        }

        float pm0 = -1e30f, pm1 = -1e30f;
        #pragma unroll
        for (int nf = 0; nf < 8; nf++) {
            pm0 = fmaxf(pm0, fmaxf(s[nf][0], s[nf][1]));
            pm1 = fmaxf(pm1, fmaxf(s[nf][2], s[nf][3]));
        }
        pm0 = fmaxf(pm0, __shfl_xor_sync(0xffffffffu, pm0, 1));
        pm0 = fmaxf(pm0, __shfl_xor_sync(0xffffffffu, pm0, 2));
        pm1 = fmaxf(pm1, __shfl_xor_sync(0xffffffffu, pm1, 1));
        pm1 = fmaxf(pm1, __shfl_xor_sync(0xffffffffu, pm1, 2));

        const float mn0 = fmaxf(m0, pm0);
        const float mn1 = fmaxf(m1, pm1);
        const float sc0 = fex2(m0 - mn0);
        const float sc1 = fex2(m1 - mn1);
        const bool unchanged = (mn0 == m0) && (mn1 == m1);
        m0 = mn0; m1 = mn1;

        // ---- half2 exp + half2 partial sums ----
        uint32_t pa[4][4];
        uint32_t a0a = 0u, a0b = 0u, a1a = 0u, a1b = 0u;
        #pragma unroll
        for (int m = 0; m < 4; m++) {
            #pragma unroll
            for (int j = 0; j < 2; j++) {
                const int nf = 2 * m + j;
                const uint32_t d0 = packh2(s[nf][0] - mn0, s[nf][1] - mn0);
                const uint32_t d1 = packh2(s[nf][2] - mn1, s[nf][3] - mn1);
                const uint32_t e0 = h2exp2(d0);
                const uint32_t e1 = h2exp2(d1);
                pa[m][j * 2 + 0] = e0;
                pa[m][j * 2 + 1] = e1;
                if (j) { a0b = hadd2(a0b, e0); a1b = hadd2(a1b, e1); }
                else   { a0a = hadd2(a0a, e0); a1a = hadd2(a1a, e1); }
            }
        }
        float2 f0a = h2f2(a0a), f0b = h2f2(a0b);
        float2 f1a = h2f2(a1a), f1b = h2f2(a1b);
        float sum0 = (f0a.x + f0a.y) + (f0b.x + f0b.y);
        float sum1 = (f1a.x + f1a.y) + (f1b.x + f1b.y);

        sum0 += __shfl_xor_sync(0xffffffffu, sum0, 1);
        sum0 += __shfl_xor_sync(0xffffffffu, sum0, 2);
        sum1 += __shfl_xor_sync(0xffffffffu, sum1, 1);
        sum1 += __shfl_xor_sync(0xffffffffu, sum1, 2);
        l0 = l0 * sc0 + sum0;
        l1 = l1 * sc1 + sum1;

        // ---- rescale O only if some lane's max moved (warp-uniform test) ----
        if (__ballot_sync(0xffffffffu, unchanged) != 0xffffffffu) {
            #pragma unroll
            for (int nf = 0; nf < 8; nf++) {
                o_acc[nf][0] *= sc0; o_acc[nf][1] *= sc0;
                o_acc[nf][2] *= sc1; o_acc[nf][3] *= sc1;
            }
        }

        // ---- O += P V ----
        #pragma unroll
        for (int m = 0; m < 4; m++) {
            #pragma unroll
            for (int nh = 0; nh < 2; nh++) {
                const int rr = nh * 32 + (lane >> 3) * 8 + (lane & 7);
                uint32_t blo[4], bhi[4];
                ldsm_x4(blo[0], blo[1], blo[2], blo[3],
                        sptr(&Vs[rr * ASH + m * 16]));
                ldsm_x4(bhi[0], bhi[1], bhi[2], bhi[3],
                        sptr(&Vs[rr * ASH + m * 16 + 8]));
                #pragma unroll
                for (int mm = 0; mm < 4; mm++) {
                    uint32_t bfr[2] = {blo[mm], bhi[mm]};
                    mma_f16(o_acc[nh * 4 + mm], pa[m], bfr);
                }
            }
        }
    }

    const float il0 = 1.0f / l0;
    const float il1 = 1.0f / l1;
    #pragma unroll
    for (int nf = 0; nf < 8; nf++) {
        const int d = nf * 8 + 2 * t4;
        *reinterpret_cast<__half2*>(
            &out[((size_t)(b * T_SEQ + q0 + r0)) * D_MODEL + h * 64 + d]) =
            __floats2half2_rn(o_acc[nf][0] * il0, o_acc[nf][1] * il0);
        *reinterpret_cast<__half2*>(
            &out[((size_t)(b * T_SEQ + q0 + r1)) * D_MODEL + h * 64 + d]) =
            __floats2half2_rn(o_acc[nf][2] * il1, o_acc[nf][3] * il1);
    }
}

// ---------------------------------------------------------------------------
extern "C" void kernel_launch(void* const* d_in, const int* in_sizes, int n_in,
                              void* d_out, int out_size)
{
    const float* x  = (const float*)d_in[0];
    const float* Wq = (const float*)d_in[1];
    const float* bq = (const float*)d_in[2];
    const float* Wk = (const float*)d_in[3];
    const float* bk = (const float*)d_in[4];
    const float* Wv = (const float*)d_in[5];
    const float* bv = (const float*)d_in[6];
    const float* Wo = (const float*)d_in[7];
    const float* bo = (const float*)d_in[8];
    float* out = (float*)d_out;

    __half *Q, *K, *Vt, *attn, *xh, *Wt;
    cudaGetSymbolAddress((void**)&Q, g_Q);
    cudaGetSymbolAddress((void**)&K, g_K);
    cudaGetSymbolAddress((void**)&Vt, g_Vt);
    cudaGetSymbolAddress((void**)&attn, g_attn);
    cudaGetSymbolAddress((void**)&xh, g_xh);
    cudaGetSymbolAddress((void**)&Wt, g_Wt);
    __half* Wot = Wt + (size_t)3 * D_MODEL * D_MODEL;

    cudaFuncSetAttribute(qkv_gemm_kernel,
                         cudaFuncAttributeMaxDynamicSharedMemorySize,
                         GEMM_SMEM_BYTES);
    cudaFuncSetAttribute(out_gemm_kernel,
                         cudaFuncAttributeMaxDynamicSharedMemorySize,
                         GEMM_SMEM_BYTES);
    cudaFuncSetAttribute(attn_mma_kernel,
                         cudaFuncAttributeMaxDynamicSharedMemorySize,
                         ATTN_SMEM_BYTES);

    prep_kernel<<<PREP_XBLOCKS + 4096, 256>>>(x, xh, Wq, Wk, Wv, Wo, Wt);

    qkv_gemm_kernel<<<dim3(24, 32), 256, GEMM_SMEM_BYTES>>>(
        xh, Wt, bq, bk, bv, Q, K, Vt);

    attn_mma_kernel<<<dim3(T_SEQ / 64, B_SIZE * N_HEADS), 128,
                      ATTN_SMEM_BYTES>>>(Q, K, Vt, attn);

    out_gemm_kernel<<<dim3(8, 32), 256, GEMM_SMEM_BYTES>>>(attn, Wot, bo, out);
}